// round 1
// baseline (speedup 1.0000x reference)
#include <cuda_runtime.h>
#include <math.h>

#define C_DIM   2048
#define N_HEADS 16
#define HD      128
#define B_SZ    2
#define T_SZ    2048
#define BT      (B_SZ * T_SZ)

// ---------------- scratch (device globals: no allocations allowed) ----------
__device__ __align__(16) float g_q [BT * C_DIM];   // full Q projection [token, C]
__device__ __align__(16) float g_ks[BT * HD];      // selected-head K   [token, HD]
__device__ __align__(16) float g_vs[BT * HD];      // gated selected V  [token, HD]
__device__ float g_gv [BT];                         // top-1 softmax value per token
__device__ int   g_cnt[N_HEADS];                    // bucket counts
__device__ int   g_list[N_HEADS * BT];              // token lists per head

// ---------------- K0: reset bucket counts (graph replays!) ------------------
__global__ void zero_cnt_kernel() {
    if (threadIdx.x < N_HEADS) g_cnt[threadIdx.x] = 0;
}

// ---------------- K1: gating logits -> argmax head + top1 softmax value -----
// one block (128 threads) per token
__global__ __launch_bounds__(128) void gating_kernel(
    const float* __restrict__ x, const float* __restrict__ Wg)
{
    const int t = blockIdx.x;
    const float* xr = x + (size_t)t * C_DIM;

    float acc[N_HEADS];
#pragma unroll
    for (int h = 0; h < N_HEADS; h++) acc[h] = 0.0f;

    for (int k = threadIdx.x; k < C_DIM; k += 128) {
        const float xv = xr[k];
#pragma unroll
        for (int h = 0; h < N_HEADS; h++)
            acc[h] += xv * Wg[h * C_DIM + k];
    }
    // warp reduce
#pragma unroll
    for (int h = 0; h < N_HEADS; h++) {
#pragma unroll
        for (int off = 16; off > 0; off >>= 1)
            acc[h] += __shfl_xor_sync(0xffffffffu, acc[h], off);
    }
    __shared__ float red[4][N_HEADS];
    const int w = threadIdx.x >> 5, lane = threadIdx.x & 31;
    if (lane == 0) {
#pragma unroll
        for (int h = 0; h < N_HEADS; h++) red[w][h] = acc[h];
    }
    __syncthreads();
    if (threadIdx.x == 0) {
        float lg[N_HEADS];
#pragma unroll
        for (int h = 0; h < N_HEADS; h++)
            lg[h] = red[0][h] + red[1][h] + red[2][h] + red[3][h];
        float mx = lg[0]; int bi = 0;
#pragma unroll
        for (int h = 1; h < N_HEADS; h++)
            if (lg[h] > mx) { mx = lg[h]; bi = h; }   // first-max like jnp.argmax
        float s = 0.0f;
#pragma unroll
        for (int h = 0; h < N_HEADS; h++) s += expf(lg[h] - mx);
        g_gv[t] = 1.0f / s;                            // top-1 softmax probability
        const int pos = atomicAdd(&g_cnt[bi], 1);
        g_list[bi * BT + pos] = t;
    }
}

// ---------------- K3: Q projection  g_q[M=4096, N=2048] = x @ Wq^T ----------
// 128x128 tile, BK=16, 256 threads, 8x8 per-thread fragments
__global__ __launch_bounds__(256) void qproj_kernel(
    const float* __restrict__ x, const float* __restrict__ Wqkv)
{
    __shared__ float As[16][128];
    __shared__ float Bs[16][128];
    const int tid = threadIdx.x;
    const int lr = tid >> 2;             // 0..63
    const int lc = (tid & 3) << 2;       // 0,4,8,12
    const int ty = tid >> 4, tx = tid & 15;

    const float* Ap = x    + (size_t)(blockIdx.y * 128) * C_DIM;
    const float* Bp = Wqkv + (size_t)(blockIdx.x * 128) * C_DIM;  // q rows are [0, 2048)

    float acc[8][8];
#pragma unroll
    for (int i = 0; i < 8; i++)
#pragma unroll
        for (int j = 0; j < 8; j++) acc[i][j] = 0.0f;

    for (int kt = 0; kt < C_DIM; kt += 16) {
        const float4 a0 = *(const float4*)(Ap + (size_t)lr        * C_DIM + kt + lc);
        const float4 a1 = *(const float4*)(Ap + (size_t)(lr + 64) * C_DIM + kt + lc);
        const float4 b0 = *(const float4*)(Bp + (size_t)lr        * C_DIM + kt + lc);
        const float4 b1 = *(const float4*)(Bp + (size_t)(lr + 64) * C_DIM + kt + lc);
        __syncthreads();
        As[lc+0][lr] = a0.x; As[lc+1][lr] = a0.y; As[lc+2][lr] = a0.z; As[lc+3][lr] = a0.w;
        As[lc+0][lr+64] = a1.x; As[lc+1][lr+64] = a1.y; As[lc+2][lr+64] = a1.z; As[lc+3][lr+64] = a1.w;
        Bs[lc+0][lr] = b0.x; Bs[lc+1][lr] = b0.y; Bs[lc+2][lr] = b0.z; Bs[lc+3][lr] = b0.w;
        Bs[lc+0][lr+64] = b1.x; Bs[lc+1][lr+64] = b1.y; Bs[lc+2][lr+64] = b1.z; Bs[lc+3][lr+64] = b1.w;
        __syncthreads();
#pragma unroll
        for (int k = 0; k < 16; k++) {
            const float4 a0v = *(const float4*)&As[k][ty * 8];
            const float4 a1v = *(const float4*)&As[k][ty * 8 + 4];
            const float4 b0v = *(const float4*)&Bs[k][tx * 8];
            const float4 b1v = *(const float4*)&Bs[k][tx * 8 + 4];
            const float av[8] = {a0v.x, a0v.y, a0v.z, a0v.w, a1v.x, a1v.y, a1v.z, a1v.w};
            const float bv[8] = {b0v.x, b0v.y, b0v.z, b0v.w, b1v.x, b1v.y, b1v.z, b1v.w};
#pragma unroll
            for (int i = 0; i < 8; i++)
#pragma unroll
                for (int j = 0; j < 8; j++)
                    acc[i][j] += av[i] * bv[j];
        }
    }
    float* Cp = g_q + (size_t)(blockIdx.y * 128 + ty * 8) * C_DIM + blockIdx.x * 128 + tx * 8;
#pragma unroll
    for (int i = 0; i < 8; i++) {
        *(float4*)(Cp + (size_t)i * C_DIM)     = make_float4(acc[i][0], acc[i][1], acc[i][2], acc[i][3]);
        *(float4*)(Cp + (size_t)i * C_DIM + 4) = make_float4(acc[i][4], acc[i][5], acc[i][6], acc[i][7]);
    }
}

// ---------------- K4: grouped K/V projection for selected heads -------------
// grid: (32 token-tiles, 16 heads, z in {0=k,1=v}); most blocks early-exit.
__global__ __launch_bounds__(256) void kvproj_kernel(
    const float* __restrict__ x, const float* __restrict__ Wqkv)
{
    const int h = blockIdx.y, z = blockIdx.z;
    const int cnt = g_cnt[h];
    const int m0 = blockIdx.x * 128;
    if (m0 >= cnt) return;

    __shared__ float As[16][128];
    __shared__ float Bs[16][128];
    const int tid = threadIdx.x;
    const int lr = tid >> 2, lc = (tid & 3) << 2;
    const int ty = tid >> 4, tx = tid & 15;

    const int* lst = g_list + h * BT;
    const int tokA = lst[min(m0 + lr,      cnt - 1)];
    const int tokB = lst[min(m0 + lr + 64, cnt - 1)];
    // k rows: [C, 2C), v rows: [2C, 3C); head h slice of HD rows
    const float* Bp = Wqkv + (size_t)(C_DIM * (1 + z) + h * HD) * C_DIM;

    float acc[8][8];
#pragma unroll
    for (int i = 0; i < 8; i++)
#pragma unroll
        for (int j = 0; j < 8; j++) acc[i][j] = 0.0f;

    for (int kt = 0; kt < C_DIM; kt += 16) {
        const float4 a0 = *(const float4*)(x + (size_t)tokA * C_DIM + kt + lc);
        const float4 a1 = *(const float4*)(x + (size_t)tokB * C_DIM + kt + lc);
        const float4 b0 = *(const float4*)(Bp + (size_t)lr        * C_DIM + kt + lc);
        const float4 b1 = *(const float4*)(Bp + (size_t)(lr + 64) * C_DIM + kt + lc);
        __syncthreads();
        As[lc+0][lr] = a0.x; As[lc+1][lr] = a0.y; As[lc+2][lr] = a0.z; As[lc+3][lr] = a0.w;
        As[lc+0][lr+64] = a1.x; As[lc+1][lr+64] = a1.y; As[lc+2][lr+64] = a1.z; As[lc+3][lr+64] = a1.w;
        Bs[lc+0][lr] = b0.x; Bs[lc+1][lr] = b0.y; Bs[lc+2][lr] = b0.z; Bs[lc+3][lr] = b0.w;
        Bs[lc+0][lr+64] = b1.x; Bs[lc+1][lr+64] = b1.y; Bs[lc+2][lr+64] = b1.z; Bs[lc+3][lr+64] = b1.w;
        __syncthreads();
#pragma unroll
        for (int k = 0; k < 16; k++) {
            const float4 a0v = *(const float4*)&As[k][ty * 8];
            const float4 a1v = *(const float4*)&As[k][ty * 8 + 4];
            const float4 b0v = *(const float4*)&Bs[k][tx * 8];
            const float4 b1v = *(const float4*)&Bs[k][tx * 8 + 4];
            const float av[8] = {a0v.x, a0v.y, a0v.z, a0v.w, a1v.x, a1v.y, a1v.z, a1v.w};
            const float bv[8] = {b0v.x, b0v.y, b0v.z, b0v.w, b1v.x, b1v.y, b1v.z, b1v.w};
#pragma unroll
            for (int i = 0; i < 8; i++)
#pragma unroll
                for (int j = 0; j < 8; j++)
                    acc[i][j] += av[i] * bv[j];
        }
    }
    float* dst = z ? g_vs : g_ks;
#pragma unroll
    for (int i = 0; i < 8; i++) {
        const int m = m0 + ty * 8 + i;
        if (m < cnt) {
            const int tok = lst[m];
            const float sc = z ? g_gv[tok] : 1.0f;
            *(float4*)(dst + (size_t)tok * HD + tx * 8) =
                make_float4(acc[i][0]*sc, acc[i][1]*sc, acc[i][2]*sc, acc[i][3]*sc);
            *(float4*)(dst + (size_t)tok * HD + tx * 8 + 4) =
                make_float4(acc[i][4]*sc, acc[i][5]*sc, acc[i][6]*sc, acc[i][7]*sc);
        }
    }
}

// ---------------- K5: causal flash MQA attention ----------------------------
// grid (32 q-tiles [reversed for balance], 16 heads, 2 batch); 256 threads.
// BQ=BKt=64, HD=128. smem: Qs/Ks transposed [128][68], Vs [64][128], Ps [64][68]
#define QS_OFF  0
#define KS_OFF  (128 * 68)
#define VS_OFF  (KS_OFF + 128 * 68)
#define PS_OFF  (VS_OFF + 64 * 128)
#define ATTN_SMEM_FLOATS (PS_OFF + 64 * 68)

__global__ __launch_bounds__(256) void attn_kernel(float* __restrict__ out)
{
    extern __shared__ float sm[];
    float* Qs = sm + QS_OFF;
    float* Ks = sm + KS_OFF;
    float* Vs = sm + VS_OFF;
    float* Ps = sm + PS_OFF;

    const int b  = blockIdx.z, h = blockIdx.y;
    const int qt = gridDim.x - 1 - blockIdx.x;      // longest blocks first
    const int tid = threadIdx.x, ty = tid >> 4, tx = tid & 15;

    // load Q tile transposed: Qs[d][r]
    const float* qbase = g_q + (size_t)(b * T_SZ + qt * 64) * C_DIM + h * HD;
    for (int i = tid; i < 64 * 32; i += 256) {
        const int r = i >> 5, c4 = i & 31;
        const float4 v = *(const float4*)(qbase + (size_t)r * C_DIM + (c4 << 2));
        Qs[(c4 * 4 + 0) * 68 + r] = v.x;
        Qs[(c4 * 4 + 1) * 68 + r] = v.y;
        Qs[(c4 * 4 + 2) * 68 + r] = v.z;
        Qs[(c4 * 4 + 3) * 68 + r] = v.w;
    }

    float m_[4], l_[4], o_[4][8];
#pragma unroll
    for (int i = 0; i < 4; i++) {
        m_[i] = -INFINITY; l_[i] = 0.0f;
#pragma unroll
        for (int j = 0; j < 8; j++) o_[i][j] = 0.0f;
    }

    const float4* kb = (const float4*)(g_ks + (size_t)b * T_SZ * HD);
    const float4* vb = (const float4*)(g_vs + (size_t)b * T_SZ * HD);
    const float SC = 0.08838834764831845f;  // 1/sqrt(128)

    for (int kt = 0; kt <= qt; kt++) {
        __syncthreads();   // protects Qs (1st iter) / Ks,Vs,Ps (later iters)
        for (int i = tid; i < 64 * 32; i += 256) {
            const int c = i >> 5, d4 = i & 31;
            const float4 v = kb[(size_t)(kt * 64 + c) * 32 + d4];
            Ks[(d4 * 4 + 0) * 68 + c] = v.x;
            Ks[(d4 * 4 + 1) * 68 + c] = v.y;
            Ks[(d4 * 4 + 2) * 68 + c] = v.z;
            Ks[(d4 * 4 + 3) * 68 + c] = v.w;
            ((float4*)Vs)[i] = vb[(size_t)(kt * 64) * 32 + i];
        }
        __syncthreads();

        // S = Q @ K^T  (4x4 per thread)
        float s[4][4];
#pragma unroll
        for (int i = 0; i < 4; i++)
#pragma unroll
            for (int j = 0; j < 4; j++) s[i][j] = 0.0f;
#pragma unroll 8
        for (int k = 0; k < 128; k++) {
            const float4 qa = *(const float4*)&Qs[k * 68 + ty * 4];
            const float4 ka = *(const float4*)&Ks[k * 68 + tx * 4];
            const float qv[4] = {qa.x, qa.y, qa.z, qa.w};
            const float kv[4] = {ka.x, ka.y, ka.z, ka.w};
#pragma unroll
            for (int i = 0; i < 4; i++)
#pragma unroll
                for (int j = 0; j < 4; j++)
                    s[i][j] += qv[i] * kv[j];
        }
#pragma unroll
        for (int i = 0; i < 4; i++)
#pragma unroll
            for (int j = 0; j < 4; j++) s[i][j] *= SC;
        if (kt == qt) {
#pragma unroll
            for (int i = 0; i < 4; i++)
#pragma unroll
                for (int j = 0; j < 4; j++)
                    if (tx * 4 + j > ty * 4 + i) s[i][j] = -INFINITY;
        }

        // online softmax per row (rows of this thread: ty*4 + i)
#pragma unroll
        for (int i = 0; i < 4; i++) {
            float mt = fmaxf(fmaxf(s[i][0], s[i][1]), fmaxf(s[i][2], s[i][3]));
            mt = fmaxf(mt, __shfl_xor_sync(0xffffffffu, mt, 1));
            mt = fmaxf(mt, __shfl_xor_sync(0xffffffffu, mt, 2));
            mt = fmaxf(mt, __shfl_xor_sync(0xffffffffu, mt, 4));
            mt = fmaxf(mt, __shfl_xor_sync(0xffffffffu, mt, 8));
            const float mn = fmaxf(m_[i], mt);
            const float alpha = __expf(m_[i] - mn);
            m_[i] = mn;
            float rs = 0.0f;
#pragma unroll
            for (int j = 0; j < 4; j++) {
                const float p = __expf(s[i][j] - mn);
                s[i][j] = p;
                rs += p;
            }
            rs += __shfl_xor_sync(0xffffffffu, rs, 1);
            rs += __shfl_xor_sync(0xffffffffu, rs, 2);
            rs += __shfl_xor_sync(0xffffffffu, rs, 4);
            rs += __shfl_xor_sync(0xffffffffu, rs, 8);
            l_[i] = l_[i] * alpha + rs;
#pragma unroll
            for (int j = 0; j < 8; j++) o_[i][j] *= alpha;
        }

        // write P transposed: Ps[c][r]
#pragma unroll
        for (int i = 0; i < 4; i++)
#pragma unroll
            for (int j = 0; j < 4; j++)
                Ps[(tx * 4 + j) * 68 + ty * 4 + i] = s[i][j];
        __syncthreads();

        // O += P @ V
#pragma unroll 4
        for (int j = 0; j < 64; j++) {
            const float4 pa  = *(const float4*)&Ps[j * 68 + ty * 4];
            const float4 va  = *(const float4*)&Vs[j * 128 + tx * 8];
            const float4 vbv = *(const float4*)&Vs[j * 128 + tx * 8 + 4];
            const float pv[4] = {pa.x, pa.y, pa.z, pa.w};
#pragma unroll
            for (int i = 0; i < 4; i++) {
                o_[i][0] += pv[i] * va.x;  o_[i][1] += pv[i] * va.y;
                o_[i][2] += pv[i] * va.z;  o_[i][3] += pv[i] * va.w;
                o_[i][4] += pv[i] * vbv.x; o_[i][5] += pv[i] * vbv.y;
                o_[i][6] += pv[i] * vbv.z; o_[i][7] += pv[i] * vbv.w;
            }
        }
    }

    float* ob = out + (size_t)(b * T_SZ + qt * 64) * C_DIM + h * HD;
#pragma unroll
    for (int i = 0; i < 4; i++) {
        const float inv = 1.0f / l_[i];
        *(float4*)(ob + (size_t)(ty * 4 + i) * C_DIM + tx * 8) =
            make_float4(o_[i][0]*inv, o_[i][1]*inv, o_[i][2]*inv, o_[i][3]*inv);
        *(float4*)(ob + (size_t)(ty * 4 + i) * C_DIM + tx * 8 + 4) =
            make_float4(o_[i][4]*inv, o_[i][5]*inv, o_[i][6]*inv, o_[i][7]*inv);
    }
}

// ---------------- launcher --------------------------------------------------
extern "C" void kernel_launch(void* const* d_in, const int* in_sizes, int n_in,
                              void* d_out, int out_size)
{
    const float* x    = (const float*)d_in[0];
    const float* Wg   = (const float*)d_in[1];
    const float* Wqkv = (const float*)d_in[2];
    float* out = (float*)d_out;

    const int attn_smem = ATTN_SMEM_FLOATS * (int)sizeof(float);  // 119,808 B
    cudaFuncSetAttribute(attn_kernel, cudaFuncAttributeMaxDynamicSharedMemorySize, attn_smem);

    zero_cnt_kernel<<<1, 32>>>();
    gating_kernel<<<BT, 128>>>(x, Wg);
    qproj_kernel<<<dim3(16, 32), 256>>>(x, Wqkv);
    kvproj_kernel<<<dim3(32, N_HEADS, 2), 256>>>(x, Wqkv);
    attn_kernel<<<dim3(32, N_HEADS, B_SZ), 256, attn_smem>>>(out);
}

// round 3
// speedup vs baseline: 1.7006x; 1.7006x over previous
#include <cuda_runtime.h>
#include <math.h>

#define C_DIM   2048
#define N_HEADS 16
#define HD      128
#define B_SZ    2
#define T_SZ    2048
#define BT      (B_SZ * T_SZ)

typedef unsigned long long u64;

// ---------------- packed f32x2 helpers (SASS FFMA2 — ptxas never emits these)
__device__ __forceinline__ u64 pk2(float lo, float hi) {
    u64 r; asm("mov.b64 %0, {%1, %2};" : "=l"(r) : "f"(lo), "f"(hi)); return r;
}
__device__ __forceinline__ void fma2(u64& d, u64 a, u64 b) {
    asm("fma.rn.f32x2 %0, %1, %2, %0;" : "+l"(d) : "l"(a), "l"(b));
}
__device__ __forceinline__ u64 mul2(u64 a, u64 b) {
    u64 d; asm("mul.rn.f32x2 %0, %1, %2;" : "=l"(d) : "l"(a), "l"(b)); return d;
}
__device__ __forceinline__ float2 upk2(u64 v) {
    float2 f; asm("mov.b64 {%0, %1}, %2;" : "=f"(f.x), "=f"(f.y) : "l"(v)); return f;
}

// ---------------- scratch (device globals: no allocations allowed) ----------
__device__ __align__(16) float g_q [BT * C_DIM];   // full Q projection [token, C]
__device__ __align__(16) float g_ks[BT * HD];      // selected-head K   [token, HD]
__device__ __align__(16) float g_vs[BT * HD];      // gated selected V  [token, HD]
__device__ float g_gv [BT];                         // top-1 softmax value per token
__device__ int   g_cnt[N_HEADS];                    // bucket counts
__device__ int   g_list[N_HEADS * BT];              // token lists per head

// ---------------- K0: reset bucket counts (graph replays!) ------------------
__global__ void zero_cnt_kernel() {
    if (threadIdx.x < N_HEADS) g_cnt[threadIdx.x] = 0;
}

// ---------------- K1: gating logits -> argmax head + top1 softmax value -----
__global__ __launch_bounds__(128) void gating_kernel(
    const float* __restrict__ x, const float* __restrict__ Wg)
{
    const int t = blockIdx.x;
    const float* xr = x + (size_t)t * C_DIM;

    float acc[N_HEADS];
#pragma unroll
    for (int h = 0; h < N_HEADS; h++) acc[h] = 0.0f;

    for (int k = threadIdx.x; k < C_DIM; k += 128) {
        const float xv = xr[k];
#pragma unroll
        for (int h = 0; h < N_HEADS; h++)
            acc[h] += xv * Wg[h * C_DIM + k];
    }
#pragma unroll
    for (int h = 0; h < N_HEADS; h++) {
#pragma unroll
        for (int off = 16; off > 0; off >>= 1)
            acc[h] += __shfl_xor_sync(0xffffffffu, acc[h], off);
    }
    __shared__ float red[4][N_HEADS];
    const int w = threadIdx.x >> 5, lane = threadIdx.x & 31;
    if (lane == 0) {
#pragma unroll
        for (int h = 0; h < N_HEADS; h++) red[w][h] = acc[h];
    }
    __syncthreads();
    if (threadIdx.x == 0) {
        float lg[N_HEADS];
#pragma unroll
        for (int h = 0; h < N_HEADS; h++)
            lg[h] = red[0][h] + red[1][h] + red[2][h] + red[3][h];
        float mx = lg[0]; int bi = 0;
#pragma unroll
        for (int h = 1; h < N_HEADS; h++)
            if (lg[h] > mx) { mx = lg[h]; bi = h; }
        float s = 0.0f;
#pragma unroll
        for (int h = 0; h < N_HEADS; h++) s += expf(lg[h] - mx);
        g_gv[t] = 1.0f / s;
        const int pos = atomicAdd(&g_cnt[bi], 1);
        g_list[bi * BT + pos] = t;
    }
}

// ---------------- K3: Q projection  g_q[4096, 2048] = x @ Wq^T --------------
// 128x128 tile, BK=16, 256 threads, 8x8 frags via f32x2, reg prefetch
__global__ __launch_bounds__(256, 2) void qproj_kernel(
    const float* __restrict__ x, const float* __restrict__ Wqkv)
{
    __shared__ float As[16][128];
    __shared__ float Bs[16][128];
    const int tid = threadIdx.x;
    const int lr = tid >> 2;             // 0..63
    const int lc = (tid & 3) << 2;       // 0,4,8,12
    const int ty = tid >> 4, tx = tid & 15;

    const float* Ap = x    + (size_t)(blockIdx.y * 128) * C_DIM;
    const float* Bp = Wqkv + (size_t)(blockIdx.x * 128) * C_DIM;  // q rows: [0, 2048)

    u64 acc2[8][4];
#pragma unroll
    for (int i = 0; i < 8; i++)
#pragma unroll
        for (int j = 0; j < 4; j++) acc2[i][j] = 0ULL;

    float4 a0 = *(const float4*)(Ap + (size_t)lr        * C_DIM + lc);
    float4 a1 = *(const float4*)(Ap + (size_t)(lr + 64) * C_DIM + lc);
    float4 b0 = *(const float4*)(Bp + (size_t)lr        * C_DIM + lc);
    float4 b1 = *(const float4*)(Bp + (size_t)(lr + 64) * C_DIM + lc);

    for (int kt = 0; kt < C_DIM; kt += 16) {
        __syncthreads();
        As[lc+0][lr] = a0.x; As[lc+1][lr] = a0.y; As[lc+2][lr] = a0.z; As[lc+3][lr] = a0.w;
        As[lc+0][lr+64] = a1.x; As[lc+1][lr+64] = a1.y; As[lc+2][lr+64] = a1.z; As[lc+3][lr+64] = a1.w;
        Bs[lc+0][lr] = b0.x; Bs[lc+1][lr] = b0.y; Bs[lc+2][lr] = b0.z; Bs[lc+3][lr] = b0.w;
        Bs[lc+0][lr+64] = b1.x; Bs[lc+1][lr+64] = b1.y; Bs[lc+2][lr+64] = b1.z; Bs[lc+3][lr+64] = b1.w;
        __syncthreads();
        if (kt + 16 < C_DIM) {
            a0 = *(const float4*)(Ap + (size_t)lr        * C_DIM + kt + 16 + lc);
            a1 = *(const float4*)(Ap + (size_t)(lr + 64) * C_DIM + kt + 16 + lc);
            b0 = *(const float4*)(Bp + (size_t)lr        * C_DIM + kt + 16 + lc);
            b1 = *(const float4*)(Bp + (size_t)(lr + 64) * C_DIM + kt + 16 + lc);
        }
#pragma unroll
        for (int k = 0; k < 16; k++) {
            const float4 a0v = *(const float4*)&As[k][ty * 8];
            const float4 a1v = *(const float4*)&As[k][ty * 8 + 4];
            const float4 b0v = *(const float4*)&Bs[k][tx * 8];
            const float4 b1v = *(const float4*)&Bs[k][tx * 8 + 4];
            const u64 bb[4] = {pk2(b0v.x, b0v.y), pk2(b0v.z, b0v.w),
                               pk2(b1v.x, b1v.y), pk2(b1v.z, b1v.w)};
            const float av[8] = {a0v.x, a0v.y, a0v.z, a0v.w, a1v.x, a1v.y, a1v.z, a1v.w};
#pragma unroll
            for (int i = 0; i < 8; i++) {
                const u64 aa = pk2(av[i], av[i]);
#pragma unroll
                for (int j = 0; j < 4; j++) fma2(acc2[i][j], aa, bb[j]);
            }
        }
    }
    float* Cp = g_q + (size_t)(blockIdx.y * 128 + ty * 8) * C_DIM + blockIdx.x * 128 + tx * 8;
#pragma unroll
    for (int i = 0; i < 8; i++) {
        const float2 c0 = upk2(acc2[i][0]), c1 = upk2(acc2[i][1]);
        const float2 c2 = upk2(acc2[i][2]), c3 = upk2(acc2[i][3]);
        *(float4*)(Cp + (size_t)i * C_DIM)     = make_float4(c0.x, c0.y, c1.x, c1.y);
        *(float4*)(Cp + (size_t)i * C_DIM + 4) = make_float4(c2.x, c2.y, c3.x, c3.y);
    }
}

// ---------------- K4: grouped K/V projection for selected heads -------------
// M=32 token tiles for parallelism. grid (128 tiles, 16 heads, z in {0=k,1=v})
__global__ __launch_bounds__(256) void kvproj_kernel(
    const float* __restrict__ x, const float* __restrict__ Wqkv)
{
    const int h = blockIdx.y, z = blockIdx.z;
    const int cnt = g_cnt[h];
    const int m0 = blockIdx.x * 32;
    if (m0 >= cnt) return;

    __shared__ float As[16][32];
    __shared__ float Bs[16][128];
    const int tid = threadIdx.x;
    const int blr = tid >> 2, blc = (tid & 3) << 2;   // B loader: rows blr, blr+64
    const int tx = tid & 31, ty = tid >> 5;           // compute: 4 rows x 4 cols

    const int* lst = g_list + h * BT;
    int tokA = 0;
    if (tid < 128) tokA = lst[min(m0 + (tid >> 2), cnt - 1)];
    const float* Bp = Wqkv + (size_t)(C_DIM * (1 + z) + h * HD) * C_DIM;

    u64 acc2[4][2];
#pragma unroll
    for (int i = 0; i < 4; i++) { acc2[i][0] = 0ULL; acc2[i][1] = 0ULL; }

    for (int kt = 0; kt < C_DIM; kt += 16) {
        float4 a0 = make_float4(0.f, 0.f, 0.f, 0.f);
        if (tid < 128)
            a0 = *(const float4*)(x + (size_t)tokA * C_DIM + kt + blc);
        const float4 b0 = *(const float4*)(Bp + (size_t)blr        * C_DIM + kt + blc);
        const float4 b1 = *(const float4*)(Bp + (size_t)(blr + 64) * C_DIM + kt + blc);
        __syncthreads();
        if (tid < 128) {
            const int ar = tid >> 2;
            As[blc+0][ar] = a0.x; As[blc+1][ar] = a0.y;
            As[blc+2][ar] = a0.z; As[blc+3][ar] = a0.w;
        }
        Bs[blc+0][blr] = b0.x; Bs[blc+1][blr] = b0.y; Bs[blc+2][blr] = b0.z; Bs[blc+3][blr] = b0.w;
        Bs[blc+0][blr+64] = b1.x; Bs[blc+1][blr+64] = b1.y; Bs[blc+2][blr+64] = b1.z; Bs[blc+3][blr+64] = b1.w;
        __syncthreads();
#pragma unroll
        for (int k = 0; k < 16; k++) {
            const float4 av = *(const float4*)&As[k][ty * 4];
            const float4 bv = *(const float4*)&Bs[k][tx * 4];
            const u64 b20 = pk2(bv.x, bv.y), b21 = pk2(bv.z, bv.w);
            const float aa[4] = {av.x, av.y, av.z, av.w};
#pragma unroll
            for (int i = 0; i < 4; i++) {
                const u64 a2 = pk2(aa[i], aa[i]);
                fma2(acc2[i][0], a2, b20);
                fma2(acc2[i][1], a2, b21);
            }
        }
    }
    float* dst = z ? g_vs : g_ks;
#pragma unroll
    for (int i = 0; i < 4; i++) {
        const int m = m0 + ty * 4 + i;
        if (m < cnt) {
            const int tok = lst[m];
            const float sc = z ? g_gv[tok] : 1.0f;
            const float2 c0 = upk2(acc2[i][0]), c1 = upk2(acc2[i][1]);
            *(float4*)(dst + (size_t)tok * HD + tx * 4) =
                make_float4(c0.x * sc, c0.y * sc, c1.x * sc, c1.y * sc);
        }
    }
}

// ---------------- K5: causal flash MQA attention ----------------------------
#define QS_OFF  0
#define KS_OFF  (128 * 68)
#define VS_OFF  (KS_OFF + 128 * 68)
#define PS_OFF  (VS_OFF + 64 * 128)
#define ATTN_SMEM_FLOATS (PS_OFF + 64 * 68)

__global__ __launch_bounds__(256) void attn_kernel(float* __restrict__ out)
{
    extern __shared__ float sm[];
    float* Qs = sm + QS_OFF;
    float* Ks = sm + KS_OFF;
    float* Vs = sm + VS_OFF;
    float* Ps = sm + PS_OFF;

    const int b  = blockIdx.z, h = blockIdx.y;
    const int qt = gridDim.x - 1 - blockIdx.x;
    const int tid = threadIdx.x, ty = tid >> 4, tx = tid & 15;

    const float* qbase = g_q + (size_t)(b * T_SZ + qt * 64) * C_DIM + h * HD;
    for (int i = tid; i < 64 * 32; i += 256) {
        const int r = i >> 5, c4 = i & 31;
        const float4 v = *(const float4*)(qbase + (size_t)r * C_DIM + (c4 << 2));
        Qs[(c4 * 4 + 0) * 68 + r] = v.x;
        Qs[(c4 * 4 + 1) * 68 + r] = v.y;
        Qs[(c4 * 4 + 2) * 68 + r] = v.z;
        Qs[(c4 * 4 + 3) * 68 + r] = v.w;
    }

    float m_[4], l_[4];
    u64 o2[4][4];
#pragma unroll
    for (int i = 0; i < 4; i++) {
        m_[i] = -INFINITY; l_[i] = 0.0f;
#pragma unroll
        for (int j = 0; j < 4; j++) o2[i][j] = 0ULL;
    }

    const float4* kb = (const float4*)(g_ks + (size_t)b * T_SZ * HD);
    const float4* vb = (const float4*)(g_vs + (size_t)b * T_SZ * HD);
    const float SC = 0.08838834764831845f;  // 1/sqrt(128)

    for (int kt = 0; kt <= qt; kt++) {
        __syncthreads();
        for (int i = tid; i < 64 * 32; i += 256) {
            const int c = i >> 5, d4 = i & 31;
            const float4 v = kb[(size_t)(kt * 64 + c) * 32 + d4];
            Ks[(d4 * 4 + 0) * 68 + c] = v.x;
            Ks[(d4 * 4 + 1) * 68 + c] = v.y;
            Ks[(d4 * 4 + 2) * 68 + c] = v.z;
            Ks[(d4 * 4 + 3) * 68 + c] = v.w;
            ((float4*)Vs)[i] = vb[(size_t)(kt * 64) * 32 + i];
        }
        __syncthreads();

        // S = Q @ K^T via f32x2 (pairs along j)
        u64 s2[4][2];
#pragma unroll
        for (int i = 0; i < 4; i++) { s2[i][0] = 0ULL; s2[i][1] = 0ULL; }
#pragma unroll 8
        for (int k = 0; k < 128; k++) {
            const float4 qa = *(const float4*)&Qs[k * 68 + ty * 4];
            const float4 ka = *(const float4*)&Ks[k * 68 + tx * 4];
            const u64 k20 = pk2(ka.x, ka.y), k21 = pk2(ka.z, ka.w);
            const float qv[4] = {qa.x, qa.y, qa.z, qa.w};
#pragma unroll
            for (int i = 0; i < 4; i++) {
                const u64 q2 = pk2(qv[i], qv[i]);
                fma2(s2[i][0], q2, k20);
                fma2(s2[i][1], q2, k21);
            }
        }
        float s[4][4];
#pragma unroll
        for (int i = 0; i < 4; i++) {
            const float2 p0 = upk2(s2[i][0]), p1 = upk2(s2[i][1]);
            s[i][0] = p0.x * SC; s[i][1] = p0.y * SC;
            s[i][2] = p1.x * SC; s[i][3] = p1.y * SC;
        }
        if (kt == qt) {
#pragma unroll
            for (int i = 0; i < 4; i++)
#pragma unroll
                for (int j = 0; j < 4; j++)
                    if (tx * 4 + j > ty * 4 + i) s[i][j] = -INFINITY;
        }

        // online softmax per row
#pragma unroll
        for (int i = 0; i < 4; i++) {
            float mt = fmaxf(fmaxf(s[i][0], s[i][1]), fmaxf(s[i][2], s[i][3]));
            mt = fmaxf(mt, __shfl_xor_sync(0xffffffffu, mt, 1));
            mt = fmaxf(mt, __shfl_xor_sync(0xffffffffu, mt, 2));
            mt = fmaxf(mt, __shfl_xor_sync(0xffffffffu, mt, 4));
            mt = fmaxf(mt, __shfl_xor_sync(0xffffffffu, mt, 8));
            const float mn = fmaxf(m_[i], mt);
            const float alpha = __expf(m_[i] - mn);
            m_[i] = mn;
            float rs = 0.0f;
#pragma unroll
            for (int j = 0; j < 4; j++) {
                const float p = __expf(s[i][j] - mn);
                s[i][j] = p;
                rs += p;
            }
            rs += __shfl_xor_sync(0xffffffffu, rs, 1);
            rs += __shfl_xor_sync(0xffffffffu, rs, 2);
            rs += __shfl_xor_sync(0xffffffffu, rs, 4);
            rs += __shfl_xor_sync(0xffffffffu, rs, 8);
            l_[i] = l_[i] * alpha + rs;
            const u64 al2 = pk2(alpha, alpha);
#pragma unroll
            for (int j = 0; j < 4; j++) o2[i][j] = mul2(o2[i][j], al2);
        }

#pragma unroll
        for (int i = 0; i < 4; i++)
#pragma unroll
            for (int j = 0; j < 4; j++)
                Ps[(tx * 4 + j) * 68 + ty * 4 + i] = s[i][j];
        __syncthreads();

        // O += P @ V via f32x2
#pragma unroll 4
        for (int j = 0; j < 64; j++) {
            const float4 pa  = *(const float4*)&Ps[j * 68 + ty * 4];
            const float4 va  = *(const float4*)&Vs[j * 128 + tx * 8];
            const float4 vbv = *(const float4*)&Vs[j * 128 + tx * 8 + 4];
            const u64 v2[4] = {pk2(va.x, va.y), pk2(va.z, va.w),
                               pk2(vbv.x, vbv.y), pk2(vbv.z, vbv.w)};
            const float pv[4] = {pa.x, pa.y, pa.z, pa.w};
#pragma unroll
            for (int i = 0; i < 4; i++) {
                const u64 p2 = pk2(pv[i], pv[i]);
#pragma unroll
                for (int jj = 0; jj < 4; jj++) fma2(o2[i][jj], p2, v2[jj]);
            }
        }
    }

    float* ob = out + (size_t)(b * T_SZ + qt * 64) * C_DIM + h * HD;
#pragma unroll
    for (int i = 0; i < 4; i++) {
        const float inv = 1.0f / l_[i];
        const float2 c0 = upk2(o2[i][0]), c1 = upk2(o2[i][1]);
        const float2 c2 = upk2(o2[i][2]), c3 = upk2(o2[i][3]);
        *(float4*)(ob + (size_t)(ty * 4 + i) * C_DIM + tx * 8) =
            make_float4(c0.x*inv, c0.y*inv, c1.x*inv, c1.y*inv);
        *(float4*)(ob + (size_t)(ty * 4 + i) * C_DIM + tx * 8 + 4) =
            make_float4(c2.x*inv, c2.y*inv, c3.x*inv, c3.y*inv);
    }
}

// ---------------- launcher --------------------------------------------------
extern "C" void kernel_launch(void* const* d_in, const int* in_sizes, int n_in,
                              void* d_out, int out_size)
{
    const float* x    = (const float*)d_in[0];
    const float* Wg   = (const float*)d_in[1];
    const float* Wqkv = (const float*)d_in[2];
    float* out = (float*)d_out;

    const int attn_smem = ATTN_SMEM_FLOATS * (int)sizeof(float);  // 119,808 B
    cudaFuncSetAttribute(attn_kernel, cudaFuncAttributeMaxDynamicSharedMemorySize, attn_smem);

    zero_cnt_kernel<<<1, 32>>>();
    gating_kernel<<<BT, 128>>>(x, Wg);
    qproj_kernel<<<dim3(16, 32), 256>>>(x, Wqkv);
    kvproj_kernel<<<dim3(128, N_HEADS, 2), 256>>>(x, Wqkv);
    attn_kernel<<<dim3(32, N_HEADS, B_SZ), 256, attn_smem>>>(out);
}

// round 6
// speedup vs baseline: 2.1614x; 1.2710x over previous
#include <cuda_runtime.h>
#include <cuda_bf16.h>
#include <math.h>

#define C_DIM   2048
#define N_HEADS 16
#define HD      128
#define B_SZ    2
#define T_SZ    2048
#define BT      (B_SZ * T_SZ)

typedef unsigned long long u64;
typedef unsigned int u32;

// ---------------- packed f32x2 helpers (SASS FFMA2) -------------------------
__device__ __forceinline__ u64 pk2(float lo, float hi) {
    u64 r; asm("mov.b64 %0, {%1, %2};" : "=l"(r) : "f"(lo), "f"(hi)); return r;
}
__device__ __forceinline__ void fma2(u64& d, u64 a, u64 b) {
    asm("fma.rn.f32x2 %0, %1, %2, %0;" : "+l"(d) : "l"(a), "l"(b));
}
__device__ __forceinline__ u64 mul2(u64 a, u64 b) {
    u64 d; asm("mul.rn.f32x2 %0, %1, %2;" : "=l"(d) : "l"(a), "l"(b)); return d;
}
__device__ __forceinline__ float2 upk2(u64 v) {
    float2 f; asm("mov.b64 {%0, %1}, %2;" : "=f"(f.x), "=f"(f.y) : "l"(v)); return f;
}

// ---------------- mma.sync / ldmatrix helpers (compute_103-safe) ------------
__device__ __forceinline__ u32 smem_u32(const void* p) {
    u32 a; asm("{ .reg .u64 t; cvta.to.shared.u64 t, %1; cvt.u32.u64 %0, t; }"
               : "=r"(a) : "l"(p));
    return a;
}
#define LDSM_X4(r0, r1, r2, r3, addr) \
    asm volatile("ldmatrix.sync.aligned.m8n8.x4.shared.b16 {%0,%1,%2,%3}, [%4];" \
        : "=r"(r0), "=r"(r1), "=r"(r2), "=r"(r3) : "r"(addr))
#define LDSM_X2(r0, r1, addr) \
    asm volatile("ldmatrix.sync.aligned.m8n8.x2.shared.b16 {%0,%1}, [%2];" \
        : "=r"(r0), "=r"(r1) : "r"(addr))
#define MMA16816(d, a, b) \
    asm volatile("mma.sync.aligned.m16n8k16.row.col.f32.bf16.bf16.f32 " \
        "{%0,%1,%2,%3}, {%4,%5,%6,%7}, {%8,%9}, {%0,%1,%2,%3};" \
        : "+f"((d)[0]), "+f"((d)[1]), "+f"((d)[2]), "+f"((d)[3]) \
        : "r"((a)[0]), "r"((a)[1]), "r"((a)[2]), "r"((a)[3]), "r"((b)[0]), "r"((b)[1]))

// ---------------- scratch ----------------------------------------------------
__device__ __align__(16) float g_q [BT * C_DIM];
__device__ __align__(16) float g_ks[BT * HD];
__device__ __align__(16) float g_vs[BT * HD];
__device__ float g_gv [BT];
__device__ int   g_cnt[N_HEADS];
__device__ int   g_list[N_HEADS * BT];
__device__ __align__(16) __nv_bfloat16 g_xh[BT * C_DIM];
__device__ __align__(16) __nv_bfloat16 g_xl[BT * C_DIM];
__device__ __align__(16) __nv_bfloat16 g_wh[C_DIM * C_DIM];
__device__ __align__(16) __nv_bfloat16 g_wl[C_DIM * C_DIM];

// ---------------- K0: zero counters + K/V accumulators -----------------------
__global__ __launch_bounds__(256) void zero_kernel() {
    const int i = blockIdx.x * 256 + threadIdx.x;
    const float4 z = make_float4(0.f, 0.f, 0.f, 0.f);
    if (i < BT * HD / 4) { ((float4*)g_ks)[i] = z; ((float4*)g_vs)[i] = z; }
    if (blockIdx.x == 0 && threadIdx.x < N_HEADS) g_cnt[threadIdx.x] = 0;
}

// ---------------- K1: split fp32 -> bf16 hi/lo --------------------------------
__global__ __launch_bounds__(256) void cvt_kernel(
    const float* __restrict__ src, __nv_bfloat16* __restrict__ hi,
    __nv_bfloat16* __restrict__ lo, int n4)
{
    const int i = blockIdx.x * 256 + threadIdx.x;
    if (i >= n4) return;
    const float4 v = ((const float4*)src)[i];
    const float f[4] = {v.x, v.y, v.z, v.w};
    __nv_bfloat16 h[4], l[4];
#pragma unroll
    for (int j = 0; j < 4; j++) {
        h[j] = __float2bfloat16(f[j]);
        l[j] = __float2bfloat16(f[j] - __bfloat162float(h[j]));
    }
    __nv_bfloat162* H = (__nv_bfloat162*)hi;
    __nv_bfloat162* L = (__nv_bfloat162*)lo;
    H[2*i]   = __halves2bfloat162(h[0], h[1]);
    H[2*i+1] = __halves2bfloat162(h[2], h[3]);
    L[2*i]   = __halves2bfloat162(l[0], l[1]);
    L[2*i+1] = __halves2bfloat162(l[2], l[3]);
}

// ---------------- K2: gating -> argmax head + top1 softmax value --------------
__global__ __launch_bounds__(128) void gating_kernel(
    const float* __restrict__ x, const float* __restrict__ Wg)
{
    const int t = blockIdx.x;
    const float* xr = x + (size_t)t * C_DIM;
    float acc[N_HEADS];
#pragma unroll
    for (int h = 0; h < N_HEADS; h++) acc[h] = 0.0f;
    for (int k = threadIdx.x; k < C_DIM; k += 128) {
        const float xv = xr[k];
#pragma unroll
        for (int h = 0; h < N_HEADS; h++)
            acc[h] += xv * Wg[h * C_DIM + k];
    }
#pragma unroll
    for (int h = 0; h < N_HEADS; h++) {
#pragma unroll
        for (int off = 16; off > 0; off >>= 1)
            acc[h] += __shfl_xor_sync(0xffffffffu, acc[h], off);
    }
    __shared__ float red[4][N_HEADS];
    const int w = threadIdx.x >> 5, lane = threadIdx.x & 31;
    if (lane == 0) {
#pragma unroll
        for (int h = 0; h < N_HEADS; h++) red[w][h] = acc[h];
    }
    __syncthreads();
    if (threadIdx.x == 0) {
        float lg[N_HEADS];
#pragma unroll
        for (int h = 0; h < N_HEADS; h++)
            lg[h] = red[0][h] + red[1][h] + red[2][h] + red[3][h];
        float mx = lg[0]; int bi = 0;
#pragma unroll
        for (int h = 1; h < N_HEADS; h++)
            if (lg[h] > mx) { mx = lg[h]; bi = h; }
        float s = 0.0f;
#pragma unroll
        for (int h = 0; h < N_HEADS; h++) s += expf(lg[h] - mx);
        g_gv[t] = 1.0f / s;
        const int pos = atomicAdd(&g_cnt[bi], 1);
        g_list[bi * BT + pos] = t;
    }
}

// ---------------- K3: Q projection via mma.sync bf16 hi/lo 3-pass -------------
// CTA tile 128x128, K-chunk 32, 8 warps (2x4), warp tile 64x32.
#define QSTR 40   // smem row stride in bf16 (32 data + 8 pad) -> conflict-free ldmatrix

__global__ __launch_bounds__(256) void qproj_mma_kernel()
{
    __shared__ __nv_bfloat16 Ah[128 * QSTR], Al[128 * QSTR];
    __shared__ __nv_bfloat16 Bh[128 * QSTR], Bl[128 * QSTR];

    const int tid = threadIdx.x, lane = tid & 31, wid = tid >> 5;
    const int wm = (wid >> 2) * 64;      // warp row offset (0 or 64)
    const int wn = (wid & 3) * 32;       // warp col offset (0,32,64,96)
    const int m0 = blockIdx.y * 128, n0 = blockIdx.x * 128;

    const u32 sAh = smem_u32(Ah), sAl = smem_u32(Al);
    const u32 sBh = smem_u32(Bh), sBl = smem_u32(Bl);

    float acc[4][4][4];
#pragma unroll
    for (int i = 0; i < 4; i++)
#pragma unroll
        for (int j = 0; j < 4; j++)
#pragma unroll
            for (int r = 0; r < 4; r++) acc[i][j][r] = 0.0f;

    // ldmatrix per-lane base offsets
    const int q = lane >> 3, r8 = lane & 7;       // A: quadrant / row
    const int arow = (q & 1) * 8 + r8, acolq = (q >> 1) * 8;
    const int l2 = lane & 15;
    const int brow = l2 & 7, bcolq = (l2 >> 3) * 8;

    for (int kt = 0; kt < C_DIM; kt += 32) {
        __syncthreads();
        // load 128x32 bf16 tiles (hi+lo for A and B): 512 uint4 per array
        for (int u = tid; u < 512; u += 256) {
            const int rr = u >> 2, cc = (u & 3) * 8;
            const size_t ga = (size_t)(m0 + rr) * C_DIM + kt + cc;
            const size_t gb = (size_t)(n0 + rr) * C_DIM + kt + cc;
            *(uint4*)&Ah[rr * QSTR + cc] = *(const uint4*)&g_xh[ga];
            *(uint4*)&Al[rr * QSTR + cc] = *(const uint4*)&g_xl[ga];
            *(uint4*)&Bh[rr * QSTR + cc] = *(const uint4*)&g_wh[gb];
            *(uint4*)&Bl[rr * QSTR + cc] = *(const uint4*)&g_wl[gb];
        }
        __syncthreads();

#pragma unroll
        for (int ks = 0; ks < 2; ks++) {
            const int acol = ks * 16 + acolq;
            const int bcol = ks * 16 + bcolq;
            u32 a_hi[4][4], a_lo[4][4], b_hi[4][2], b_lo[4][2];
#pragma unroll
            for (int mt = 0; mt < 4; mt++) {
                const u32 off = ((wm + mt * 16 + arow) * QSTR + acol) * 2;
                LDSM_X4(a_hi[mt][0], a_hi[mt][1], a_hi[mt][2], a_hi[mt][3], sAh + off);
                LDSM_X4(a_lo[mt][0], a_lo[mt][1], a_lo[mt][2], a_lo[mt][3], sAl + off);
            }
#pragma unroll
            for (int nt = 0; nt < 4; nt++) {
                const u32 off = ((wn + nt * 8 + brow) * QSTR + bcol) * 2;
                LDSM_X2(b_hi[nt][0], b_hi[nt][1], sBh + off);
                LDSM_X2(b_lo[nt][0], b_lo[nt][1], sBl + off);
            }
#pragma unroll
            for (int mt = 0; mt < 4; mt++)
#pragma unroll
                for (int nt = 0; nt < 4; nt++) {
                    MMA16816(acc[mt][nt], a_hi[mt], b_hi[nt]);
                    MMA16816(acc[mt][nt], a_hi[mt], b_lo[nt]);
                    MMA16816(acc[mt][nt], a_lo[mt], b_hi[nt]);
                }
        }
    }

    // epilogue: c0,c1 -> (row, col..col+1); c2,c3 -> (row+8, ...)
    const int er = lane >> 2, ec = (lane & 3) * 2;
#pragma unroll
    for (int mt = 0; mt < 4; mt++) {
        const size_t row = (size_t)(m0 + wm + mt * 16 + er);
#pragma unroll
        for (int nt = 0; nt < 4; nt++) {
            const int col = n0 + wn + nt * 8 + ec;
            *(float2*)&g_q[row * C_DIM + col]       = make_float2(acc[mt][nt][0], acc[mt][nt][1]);
            *(float2*)&g_q[(row + 8) * C_DIM + col] = make_float2(acc[mt][nt][2], acc[mt][nt][3]);
        }
    }
}

// ---------------- K4: grouped K/V projection, split-K=4 + atomics -------------
#define KV_SPLITS 4
#define KV_KCH (C_DIM / KV_SPLITS)

__global__ __launch_bounds__(256) void kvproj_kernel(
    const float* __restrict__ x, const float* __restrict__ Wqkv)
{
    const int h = blockIdx.y;
    const int kv = blockIdx.z & 1, sp = blockIdx.z >> 1;
    const int cnt = g_cnt[h];
    const int m0 = blockIdx.x * 32;
    if (m0 >= cnt) return;

    __shared__ float As[16][32];
    __shared__ float Bs[16][128];
    const int tid = threadIdx.x;
    const int blr = tid >> 2, blc = (tid & 3) << 2;
    const int tx = tid & 31, ty = tid >> 5;

    const int* lst = g_list + h * BT;
    int tokA = 0;
    if (tid < 128) tokA = lst[min(m0 + (tid >> 2), cnt - 1)];
    const float* Bp = Wqkv + (size_t)(C_DIM * (1 + kv) + h * HD) * C_DIM;

    u64 acc2[4][2];
#pragma unroll
    for (int i = 0; i < 4; i++) { acc2[i][0] = 0ULL; acc2[i][1] = 0ULL; }

    const int k0 = sp * KV_KCH;
    for (int kt = k0; kt < k0 + KV_KCH; kt += 16) {
        float4 a0 = make_float4(0.f, 0.f, 0.f, 0.f);
        if (tid < 128)
            a0 = *(const float4*)(x + (size_t)tokA * C_DIM + kt + blc);
        const float4 b0 = *(const float4*)(Bp + (size_t)blr        * C_DIM + kt + blc);
        const float4 b1 = *(const float4*)(Bp + (size_t)(blr + 64) * C_DIM + kt + blc);
        __syncthreads();
        if (tid < 128) {
            const int ar = tid >> 2;
            As[blc+0][ar] = a0.x; As[blc+1][ar] = a0.y;
            As[blc+2][ar] = a0.z; As[blc+3][ar] = a0.w;
        }
        Bs[blc+0][blr] = b0.x; Bs[blc+1][blr] = b0.y; Bs[blc+2][blr] = b0.z; Bs[blc+3][blr] = b0.w;
        Bs[blc+0][blr+64] = b1.x; Bs[blc+1][blr+64] = b1.y; Bs[blc+2][blr+64] = b1.z; Bs[blc+3][blr+64] = b1.w;
        __syncthreads();
#pragma unroll
        for (int k = 0; k < 16; k++) {
            const float4 av = *(const float4*)&As[k][ty * 4];
            const float4 bv = *(const float4*)&Bs[k][tx * 4];
            const u64 b20 = pk2(bv.x, bv.y), b21 = pk2(bv.z, bv.w);
            const float aa[4] = {av.x, av.y, av.z, av.w};
#pragma unroll
            for (int i = 0; i < 4; i++) {
                const u64 a2 = pk2(aa[i], aa[i]);
                fma2(acc2[i][0], a2, b20);
                fma2(acc2[i][1], a2, b21);
            }
        }
    }
    float* dst = kv ? g_vs : g_ks;
#pragma unroll
    for (int i = 0; i < 4; i++) {
        const int m = m0 + ty * 4 + i;
        if (m < cnt) {
            const int tok = lst[m];
            const float sc = kv ? g_gv[tok] : 1.0f;
            const float2 c0 = upk2(acc2[i][0]), c1 = upk2(acc2[i][1]);
            float* d = dst + (size_t)tok * HD + tx * 4;
            atomicAdd(d + 0, c0.x * sc);
            atomicAdd(d + 1, c0.y * sc);
            atomicAdd(d + 2, c1.x * sc);
            atomicAdd(d + 3, c1.y * sc);
        }
    }
}

// ---------------- K5: causal flash MQA attention (f32x2) ----------------------
#define QS_OFF  0
#define KS_OFF  (128 * 68)
#define VS_OFF  (KS_OFF + 128 * 68)
#define PS_OFF  (VS_OFF + 64 * 128)
#define ATTN_SMEM_FLOATS (PS_OFF + 64 * 68)

__global__ __launch_bounds__(256) void attn_kernel(float* __restrict__ out)
{
    extern __shared__ float sm[];
    float* Qs = sm + QS_OFF;
    float* Ks = sm + KS_OFF;
    float* Vs = sm + VS_OFF;
    float* Ps = sm + PS_OFF;

    const int b  = blockIdx.z, h = blockIdx.y;
    const int qt = gridDim.x - 1 - blockIdx.x;
    const int tid = threadIdx.x, ty = tid >> 4, tx = tid & 15;

    const float* qbase = g_q + (size_t)(b * T_SZ + qt * 64) * C_DIM + h * HD;
    for (int i = tid; i < 64 * 32; i += 256) {
        const int r = i >> 5, c4 = i & 31;
        const float4 v = *(const float4*)(qbase + (size_t)r * C_DIM + (c4 << 2));
        Qs[(c4 * 4 + 0) * 68 + r] = v.x;
        Qs[(c4 * 4 + 1) * 68 + r] = v.y;
        Qs[(c4 * 4 + 2) * 68 + r] = v.z;
        Qs[(c4 * 4 + 3) * 68 + r] = v.w;
    }

    float m_[4], l_[4];
    u64 o2[4][4];
#pragma unroll
    for (int i = 0; i < 4; i++) {
        m_[i] = -INFINITY; l_[i] = 0.0f;
#pragma unroll
        for (int j = 0; j < 4; j++) o2[i][j] = 0ULL;
    }

    const float4* kb = (const float4*)(g_ks + (size_t)b * T_SZ * HD);
    const float4* vb = (const float4*)(g_vs + (size_t)b * T_SZ * HD);
    const float SC = 0.08838834764831845f;

    for (int kt = 0; kt <= qt; kt++) {
        __syncthreads();
        for (int i = tid; i < 64 * 32; i += 256) {
            const int c = i >> 5, d4 = i & 31;
            const float4 v = kb[(size_t)(kt * 64 + c) * 32 + d4];
            Ks[(d4 * 4 + 0) * 68 + c] = v.x;
            Ks[(d4 * 4 + 1) * 68 + c] = v.y;
            Ks[(d4 * 4 + 2) * 68 + c] = v.z;
            Ks[(d4 * 4 + 3) * 68 + c] = v.w;
            ((float4*)Vs)[i] = vb[(size_t)(kt * 64) * 32 + i];
        }
        __syncthreads();

        u64 s2[4][2];
#pragma unroll
        for (int i = 0; i < 4; i++) { s2[i][0] = 0ULL; s2[i][1] = 0ULL; }
#pragma unroll 8
        for (int k = 0; k < 128; k++) {
            const float4 qa = *(const float4*)&Qs[k * 68 + ty * 4];
            const float4 ka = *(const float4*)&Ks[k * 68 + tx * 4];
            const u64 k20 = pk2(ka.x, ka.y), k21 = pk2(ka.z, ka.w);
            const float qv[4] = {qa.x, qa.y, qa.z, qa.w};
#pragma unroll
            for (int i = 0; i < 4; i++) {
                const u64 q2 = pk2(qv[i], qv[i]);
                fma2(s2[i][0], q2, k20);
                fma2(s2[i][1], q2, k21);
            }
        }
        float s[4][4];
#pragma unroll
        for (int i = 0; i < 4; i++) {
            const float2 p0 = upk2(s2[i][0]), p1 = upk2(s2[i][1]);
            s[i][0] = p0.x * SC; s[i][1] = p0.y * SC;
            s[i][2] = p1.x * SC; s[i][3] = p1.y * SC;
        }
        if (kt == qt) {
#pragma unroll
            for (int i = 0; i < 4; i++)
#pragma unroll
                for (int j = 0; j < 4; j++)
                    if (tx * 4 + j > ty * 4 + i) s[i][j] = -INFINITY;
        }

#pragma unroll
        for (int i = 0; i < 4; i++) {
            float mt = fmaxf(fmaxf(s[i][0], s[i][1]), fmaxf(s[i][2], s[i][3]));
            mt = fmaxf(mt, __shfl_xor_sync(0xffffffffu, mt, 1));
            mt = fmaxf(mt, __shfl_xor_sync(0xffffffffu, mt, 2));
            mt = fmaxf(mt, __shfl_xor_sync(0xffffffffu, mt, 4));
            mt = fmaxf(mt, __shfl_xor_sync(0xffffffffu, mt, 8));
            const float mn = fmaxf(m_[i], mt);
            const float alpha = __expf(m_[i] - mn);
            m_[i] = mn;
            float rs = 0.0f;
#pragma unroll
            for (int j = 0; j < 4; j++) {
                const float p = __expf(s[i][j] - mn);
                s[i][j] = p;
                rs += p;
            }
            rs += __shfl_xor_sync(0xffffffffu, rs, 1);
            rs += __shfl_xor_sync(0xffffffffu, rs, 2);
            rs += __shfl_xor_sync(0xffffffffu, rs, 4);
            rs += __shfl_xor_sync(0xffffffffu, rs, 8);
            l_[i] = l_[i] * alpha + rs;
            const u64 al2 = pk2(alpha, alpha);
#pragma unroll
            for (int j = 0; j < 4; j++) o2[i][j] = mul2(o2[i][j], al2);
        }

#pragma unroll
        for (int i = 0; i < 4; i++)
#pragma unroll
            for (int j = 0; j < 4; j++)
                Ps[(tx * 4 + j) * 68 + ty * 4 + i] = s[i][j];
        __syncthreads();

#pragma unroll 4
        for (int j = 0; j < 64; j++) {
            const float4 pa  = *(const float4*)&Ps[j * 68 + ty * 4];
            const float4 va  = *(const float4*)&Vs[j * 128 + tx * 8];
            const float4 vbv = *(const float4*)&Vs[j * 128 + tx * 8 + 4];
            const u64 v2[4] = {pk2(va.x, va.y), pk2(va.z, va.w),
                               pk2(vbv.x, vbv.y), pk2(vbv.z, vbv.w)};
            const float pv[4] = {pa.x, pa.y, pa.z, pa.w};
#pragma unroll
            for (int i = 0; i < 4; i++) {
                const u64 p2 = pk2(pv[i], pv[i]);
#pragma unroll
                for (int jj = 0; jj < 4; jj++) fma2(o2[i][jj], p2, v2[jj]);
            }
        }
    }

    float* ob = out + (size_t)(b * T_SZ + qt * 64) * C_DIM + h * HD;
#pragma unroll
    for (int i = 0; i < 4; i++) {
        const float inv = 1.0f / l_[i];
        const float2 c0 = upk2(o2[i][0]), c1 = upk2(o2[i][1]);
        const float2 c2 = upk2(o2[i][2]), c3 = upk2(o2[i][3]);
        *(float4*)(ob + (size_t)(ty * 4 + i) * C_DIM + tx * 8) =
            make_float4(c0.x*inv, c0.y*inv, c1.x*inv, c1.y*inv);
        *(float4*)(ob + (size_t)(ty * 4 + i) * C_DIM + tx * 8 + 4) =
            make_float4(c2.x*inv, c2.y*inv, c3.x*inv, c3.y*inv);
    }
}

// ---------------- launcher ----------------------------------------------------
extern "C" void kernel_launch(void* const* d_in, const int* in_sizes, int n_in,
                              void* d_out, int out_size)
{
    const float* x    = (const float*)d_in[0];
    const float* Wg   = (const float*)d_in[1];
    const float* Wqkv = (const float*)d_in[2];
    float* out = (float*)d_out;

    const int attn_smem = ATTN_SMEM_FLOATS * (int)sizeof(float);
    cudaFuncSetAttribute(attn_kernel, cudaFuncAttributeMaxDynamicSharedMemorySize, attn_smem);

    __nv_bfloat16 *xh, *xl, *wh, *wl;
    cudaGetSymbolAddress((void**)&xh, g_xh);
    cudaGetSymbolAddress((void**)&xl, g_xl);
    cudaGetSymbolAddress((void**)&wh, g_wh);
    cudaGetSymbolAddress((void**)&wl, g_wl);

    zero_kernel<<<512, 256>>>();
    cvt_kernel<<<(BT * C_DIM / 4 + 255) / 256, 256>>>(x, xh, xl, BT * C_DIM / 4);
    cvt_kernel<<<(C_DIM * C_DIM / 4 + 255) / 256, 256>>>(Wqkv, wh, wl, C_DIM * C_DIM / 4);
    gating_kernel<<<BT, 128>>>(x, Wg);
    qproj_mma_kernel<<<dim3(C_DIM / 128, BT / 128), 256>>>();
    kvproj_kernel<<<dim3(128, N_HEADS, 2 * KV_SPLITS), 256>>>(x, Wqkv);
    attn_kernel<<<dim3(32, N_HEADS, B_SZ), 256, attn_smem>>>(out);
}

// round 7
// speedup vs baseline: 4.9749x; 2.3017x over previous
#include <cuda_runtime.h>
#include <cuda_bf16.h>
#include <math.h>

#define C_DIM   2048
#define N_HEADS 16
#define HD      128
#define B_SZ    2
#define T_SZ    2048
#define BT      (B_SZ * T_SZ)

typedef unsigned long long u64;
typedef unsigned int u32;

// ---------------- packed f32x2 helpers (SASS FFMA2) -------------------------
__device__ __forceinline__ u64 pk2(float lo, float hi) {
    u64 r; asm("mov.b64 %0, {%1, %2};" : "=l"(r) : "f"(lo), "f"(hi)); return r;
}
__device__ __forceinline__ void fma2(u64& d, u64 a, u64 b) {
    asm("fma.rn.f32x2 %0, %1, %2, %0;" : "+l"(d) : "l"(a), "l"(b));
}
__device__ __forceinline__ float2 upk2(u64 v) {
    float2 f; asm("mov.b64 {%0, %1}, %2;" : "=f"(f.x), "=f"(f.y) : "l"(v)); return f;
}

// ---------------- mma.sync / ldmatrix helpers (compute_103-safe) ------------
__device__ __forceinline__ u32 smem_u32(const void* p) {
    u32 a; asm("{ .reg .u64 t; cvta.to.shared.u64 t, %1; cvt.u32.u64 %0, t; }"
               : "=r"(a) : "l"(p));
    return a;
}
#define LDSM_X4(r0, r1, r2, r3, addr) \
    asm volatile("ldmatrix.sync.aligned.m8n8.x4.shared.b16 {%0,%1,%2,%3}, [%4];" \
        : "=r"(r0), "=r"(r1), "=r"(r2), "=r"(r3) : "r"(addr))
#define LDSM_X4T(r0, r1, r2, r3, addr) \
    asm volatile("ldmatrix.sync.aligned.m8n8.x4.trans.shared.b16 {%0,%1,%2,%3}, [%4];" \
        : "=r"(r0), "=r"(r1), "=r"(r2), "=r"(r3) : "r"(addr))
#define LDSM_X2(r0, r1, addr) \
    asm volatile("ldmatrix.sync.aligned.m8n8.x2.shared.b16 {%0,%1}, [%2];" \
        : "=r"(r0), "=r"(r1) : "r"(addr))
#define MMA16816(d, a, b) \
    asm volatile("mma.sync.aligned.m16n8k16.row.col.f32.bf16.bf16.f32 " \
        "{%0,%1,%2,%3}, {%4,%5,%6,%7}, {%8,%9}, {%0,%1,%2,%3};" \
        : "+f"((d)[0]), "+f"((d)[1]), "+f"((d)[2]), "+f"((d)[3]) \
        : "r"((a)[0]), "r"((a)[1]), "r"((a)[2]), "r"((a)[3]), "r"((b)[0]), "r"((b)[1]))

__device__ __forceinline__ u32 pack_bf2(__nv_bfloat16 a, __nv_bfloat16 b) {
    __nv_bfloat162 t = __halves2bfloat162(a, b);
    return *(u32*)&t;
}

// ---------------- scratch ----------------------------------------------------
__device__ __align__(16) float g_ks[BT * HD];
__device__ __align__(16) float g_vs[BT * HD];
__device__ float g_gv [BT];
__device__ int   g_cnt[N_HEADS];
__device__ int   g_list[N_HEADS * BT];
__device__ __align__(16) __nv_bfloat16 g_xh[BT * C_DIM];
__device__ __align__(16) __nv_bfloat16 g_xl[BT * C_DIM];
__device__ __align__(16) __nv_bfloat16 g_wh[C_DIM * C_DIM];
__device__ __align__(16) __nv_bfloat16 g_wl[C_DIM * C_DIM];
__device__ __align__(16) __nv_bfloat16 g_qh[BT * C_DIM];   // scaled Q hi
__device__ __align__(16) __nv_bfloat16 g_ql[BT * C_DIM];   // scaled Q lo
__device__ __align__(16) __nv_bfloat16 g_kh[BT * HD];
__device__ __align__(16) __nv_bfloat16 g_kl[BT * HD];
__device__ __align__(16) __nv_bfloat16 g_vh[BT * HD];
__device__ __align__(16) __nv_bfloat16 g_vl[BT * HD];

// ---------------- K0: zero counters + K/V accumulators -----------------------
__global__ __launch_bounds__(256) void zero_kernel() {
    const int i = blockIdx.x * 256 + threadIdx.x;
    const float4 z = make_float4(0.f, 0.f, 0.f, 0.f);
    if (i < BT * HD / 4) { ((float4*)g_ks)[i] = z; ((float4*)g_vs)[i] = z; }
    if (blockIdx.x == 0 && threadIdx.x < N_HEADS) g_cnt[threadIdx.x] = 0;
}

// ---------------- K1: split fp32 -> bf16 hi/lo --------------------------------
__global__ __launch_bounds__(256) void cvt_kernel(
    const float* __restrict__ src, __nv_bfloat16* __restrict__ hi,
    __nv_bfloat16* __restrict__ lo, int n4)
{
    const int i = blockIdx.x * 256 + threadIdx.x;
    if (i >= n4) return;
    const float4 v = ((const float4*)src)[i];
    const float f[4] = {v.x, v.y, v.z, v.w};
    __nv_bfloat16 h[4], l[4];
#pragma unroll
    for (int j = 0; j < 4; j++) {
        h[j] = __float2bfloat16(f[j]);
        l[j] = __float2bfloat16(f[j] - __bfloat162float(h[j]));
    }
    __nv_bfloat162* H = (__nv_bfloat162*)hi;
    __nv_bfloat162* L = (__nv_bfloat162*)lo;
    H[2*i]   = __halves2bfloat162(h[0], h[1]);
    H[2*i+1] = __halves2bfloat162(h[2], h[3]);
    L[2*i]   = __halves2bfloat162(l[0], l[1]);
    L[2*i+1] = __halves2bfloat162(l[2], l[3]);
}

// ---------------- K2: gating -> argmax head + top1 softmax value --------------
__global__ __launch_bounds__(128) void gating_kernel(
    const float* __restrict__ x, const float* __restrict__ Wg)
{
    const int t = blockIdx.x;
    const float* xr = x + (size_t)t * C_DIM;
    float acc[N_HEADS];
#pragma unroll
    for (int h = 0; h < N_HEADS; h++) acc[h] = 0.0f;
    for (int k = threadIdx.x; k < C_DIM; k += 128) {
        const float xv = xr[k];
#pragma unroll
        for (int h = 0; h < N_HEADS; h++)
            acc[h] += xv * Wg[h * C_DIM + k];
    }
#pragma unroll
    for (int h = 0; h < N_HEADS; h++) {
#pragma unroll
        for (int off = 16; off > 0; off >>= 1)
            acc[h] += __shfl_xor_sync(0xffffffffu, acc[h], off);
    }
    __shared__ float red[4][N_HEADS];
    const int w = threadIdx.x >> 5, lane = threadIdx.x & 31;
    if (lane == 0) {
#pragma unroll
        for (int h = 0; h < N_HEADS; h++) red[w][h] = acc[h];
    }
    __syncthreads();
    if (threadIdx.x == 0) {
        float lg[N_HEADS];
#pragma unroll
        for (int h = 0; h < N_HEADS; h++)
            lg[h] = red[0][h] + red[1][h] + red[2][h] + red[3][h];
        float mx = lg[0]; int bi = 0;
#pragma unroll
        for (int h = 1; h < N_HEADS; h++)
            if (lg[h] > mx) { mx = lg[h]; bi = h; }
        float s = 0.0f;
#pragma unroll
        for (int h = 0; h < N_HEADS; h++) s += expf(lg[h] - mx);
        g_gv[t] = 1.0f / s;
        const int pos = atomicAdd(&g_cnt[bi], 1);
        g_list[bi * BT + pos] = t;
    }
}

// ---------------- K3: Q projection via mma.sync bf16 hi/lo 3-pass -------------
// CTA tile 128x128, K-chunk 32, 8 warps. Epilogue: scale by 1/sqrt(HD), split
// into bf16 hi/lo for the tensor-core attention.
#define QSTR 40

__global__ __launch_bounds__(256) void qproj_mma_kernel()
{
    __shared__ __nv_bfloat16 Ah[128 * QSTR], Al[128 * QSTR];
    __shared__ __nv_bfloat16 Bh[128 * QSTR], Bl[128 * QSTR];

    const int tid = threadIdx.x, lane = tid & 31, wid = tid >> 5;
    const int wm = (wid >> 2) * 64;
    const int wn = (wid & 3) * 32;
    const int m0 = blockIdx.y * 128, n0 = blockIdx.x * 128;

    const u32 sAh = smem_u32(Ah), sAl = smem_u32(Al);
    const u32 sBh = smem_u32(Bh), sBl = smem_u32(Bl);

    float acc[4][4][4];
#pragma unroll
    for (int i = 0; i < 4; i++)
#pragma unroll
        for (int j = 0; j < 4; j++)
#pragma unroll
            for (int r = 0; r < 4; r++) acc[i][j][r] = 0.0f;

    const int q = lane >> 3, r8 = lane & 7;
    const int arow = (q & 1) * 8 + r8, acolq = (q >> 1) * 8;
    const int l2 = lane & 15;
    const int brow = l2 & 7, bcolq = (l2 >> 3) * 8;

    for (int kt = 0; kt < C_DIM; kt += 32) {
        __syncthreads();
        for (int u = tid; u < 512; u += 256) {
            const int rr = u >> 2, cc = (u & 3) * 8;
            const size_t ga = (size_t)(m0 + rr) * C_DIM + kt + cc;
            const size_t gb = (size_t)(n0 + rr) * C_DIM + kt + cc;
            *(uint4*)&Ah[rr * QSTR + cc] = *(const uint4*)&g_xh[ga];
            *(uint4*)&Al[rr * QSTR + cc] = *(const uint4*)&g_xl[ga];
            *(uint4*)&Bh[rr * QSTR + cc] = *(const uint4*)&g_wh[gb];
            *(uint4*)&Bl[rr * QSTR + cc] = *(const uint4*)&g_wl[gb];
        }
        __syncthreads();

#pragma unroll
        for (int ks = 0; ks < 2; ks++) {
            const int acol = ks * 16 + acolq;
            const int bcol = ks * 16 + bcolq;
            u32 a_hi[4][4], a_lo[4][4], b_hi[4][2], b_lo[4][2];
#pragma unroll
            for (int mt = 0; mt < 4; mt++) {
                const u32 off = ((wm + mt * 16 + arow) * QSTR + acol) * 2;
                LDSM_X4(a_hi[mt][0], a_hi[mt][1], a_hi[mt][2], a_hi[mt][3], sAh + off);
                LDSM_X4(a_lo[mt][0], a_lo[mt][1], a_lo[mt][2], a_lo[mt][3], sAl + off);
            }
#pragma unroll
            for (int nt = 0; nt < 4; nt++) {
                const u32 off = ((wn + nt * 8 + brow) * QSTR + bcol) * 2;
                LDSM_X2(b_hi[nt][0], b_hi[nt][1], sBh + off);
                LDSM_X2(b_lo[nt][0], b_lo[nt][1], sBl + off);
            }
#pragma unroll
            for (int mt = 0; mt < 4; mt++)
#pragma unroll
                for (int nt = 0; nt < 4; nt++) {
                    MMA16816(acc[mt][nt], a_hi[mt], b_hi[nt]);
                    MMA16816(acc[mt][nt], a_hi[mt], b_lo[nt]);
                    MMA16816(acc[mt][nt], a_lo[mt], b_hi[nt]);
                }
        }
    }

    const float SC = 0.08838834764831845f;  // 1/sqrt(128)
    const int er = lane >> 2, ec = (lane & 3) * 2;
#pragma unroll
    for (int mt = 0; mt < 4; mt++) {
        const size_t row = (size_t)(m0 + wm + mt * 16 + er);
#pragma unroll
        for (int nt = 0; nt < 4; nt++) {
            const int col = n0 + wn + nt * 8 + ec;
#pragma unroll
            for (int half = 0; half < 2; half++) {
                const float v0 = acc[mt][nt][half * 2 + 0] * SC;
                const float v1 = acc[mt][nt][half * 2 + 1] * SC;
                const __nv_bfloat16 h0 = __float2bfloat16(v0);
                const __nv_bfloat16 h1 = __float2bfloat16(v1);
                const __nv_bfloat16 e0 = __float2bfloat16(v0 - __bfloat162float(h0));
                const __nv_bfloat16 e1 = __float2bfloat16(v1 - __bfloat162float(h1));
                const size_t o = (row + half * 8) * C_DIM + col;
                *(u32*)&g_qh[o] = pack_bf2(h0, h1);
                *(u32*)&g_ql[o] = pack_bf2(e0, e1);
            }
        }
    }
}

// ---------------- K4: grouped K/V projection, split-K=4 + atomics -------------
#define KV_SPLITS 4
#define KV_KCH (C_DIM / KV_SPLITS)

__global__ __launch_bounds__(256) void kvproj_kernel(
    const float* __restrict__ x, const float* __restrict__ Wqkv)
{
    const int h = blockIdx.y;
    const int kv = blockIdx.z & 1, sp = blockIdx.z >> 1;
    const int cnt = g_cnt[h];
    const int m0 = blockIdx.x * 32;
    if (m0 >= cnt) return;

    __shared__ float As[16][32];
    __shared__ float Bs[16][128];
    const int tid = threadIdx.x;
    const int blr = tid >> 2, blc = (tid & 3) << 2;
    const int tx = tid & 31, ty = tid >> 5;

    const int* lst = g_list + h * BT;
    int tokA = 0;
    if (tid < 128) tokA = lst[min(m0 + (tid >> 2), cnt - 1)];
    const float* Bp = Wqkv + (size_t)(C_DIM * (1 + kv) + h * HD) * C_DIM;

    u64 acc2[4][2];
#pragma unroll
    for (int i = 0; i < 4; i++) { acc2[i][0] = 0ULL; acc2[i][1] = 0ULL; }

    const int k0 = sp * KV_KCH;
    for (int kt = k0; kt < k0 + KV_KCH; kt += 16) {
        float4 a0 = make_float4(0.f, 0.f, 0.f, 0.f);
        if (tid < 128)
            a0 = *(const float4*)(x + (size_t)tokA * C_DIM + kt + blc);
        const float4 b0 = *(const float4*)(Bp + (size_t)blr        * C_DIM + kt + blc);
        const float4 b1 = *(const float4*)(Bp + (size_t)(blr + 64) * C_DIM + kt + blc);
        __syncthreads();
        if (tid < 128) {
            const int ar = tid >> 2;
            As[blc+0][ar] = a0.x; As[blc+1][ar] = a0.y;
            As[blc+2][ar] = a0.z; As[blc+3][ar] = a0.w;
        }
        Bs[blc+0][blr] = b0.x; Bs[blc+1][blr] = b0.y; Bs[blc+2][blr] = b0.z; Bs[blc+3][blr] = b0.w;
        Bs[blc+0][blr+64] = b1.x; Bs[blc+1][blr+64] = b1.y; Bs[blc+2][blr+64] = b1.z; Bs[blc+3][blr+64] = b1.w;
        __syncthreads();
#pragma unroll
        for (int k = 0; k < 16; k++) {
            const float4 av = *(const float4*)&As[k][ty * 4];
            const float4 bv = *(const float4*)&Bs[k][tx * 4];
            const u64 b20 = pk2(bv.x, bv.y), b21 = pk2(bv.z, bv.w);
            const float aa[4] = {av.x, av.y, av.z, av.w};
#pragma unroll
            for (int i = 0; i < 4; i++) {
                const u64 a2 = pk2(aa[i], aa[i]);
                fma2(acc2[i][0], a2, b20);
                fma2(acc2[i][1], a2, b21);
            }
        }
    }
    float* dst = kv ? g_vs : g_ks;
#pragma unroll
    for (int i = 0; i < 4; i++) {
        const int m = m0 + ty * 4 + i;
        if (m < cnt) {
            const int tok = lst[m];
            const float sc = kv ? g_gv[tok] : 1.0f;
            const float2 c0 = upk2(acc2[i][0]), c1 = upk2(acc2[i][1]);
            float* d = dst + (size_t)tok * HD + tx * 4;
            atomicAdd(d + 0, c0.x * sc);
            atomicAdd(d + 1, c0.y * sc);
            atomicAdd(d + 2, c1.x * sc);
            atomicAdd(d + 3, c1.y * sc);
        }
    }
}

// ---------------- K4b: convert K/V fp32 -> bf16 hi/lo -------------------------
__global__ __launch_bounds__(256) void kvcvt_kernel() {
    const int i = blockIdx.x * 256 + threadIdx.x;
    if (i >= BT * HD / 4) return;
#pragma unroll
    for (int a = 0; a < 2; a++) {
        const float4 v = a ? ((const float4*)g_vs)[i] : ((const float4*)g_ks)[i];
        const float f[4] = {v.x, v.y, v.z, v.w};
        __nv_bfloat16 h[4], l[4];
#pragma unroll
        for (int j = 0; j < 4; j++) {
            h[j] = __float2bfloat16(f[j]);
            l[j] = __float2bfloat16(f[j] - __bfloat162float(h[j]));
        }
        u32* H = (u32*)(a ? g_vh : g_kh);
        u32* L = (u32*)(a ? g_vl : g_kl);
        H[2*i]   = pack_bf2(h[0], h[1]);
        H[2*i+1] = pack_bf2(h[2], h[3]);
        L[2*i]   = pack_bf2(l[0], l[1]);
        L[2*i+1] = pack_bf2(l[2], l[3]);
    }
}

// ---------------- K5: tensor-core causal flash MQA attention ------------------
// 4 warps, BQ=64 (16 rows/warp), BK=64, HD=128. bf16 hi/lo 3-pass for S and PV.
#define ASTR 136
#define ATTN_SMEM (6 * 64 * ASTR * 2)

__global__ __launch_bounds__(128) void attn_mma_kernel(float* __restrict__ out)
{
    extern __shared__ char sbuf[];
    __nv_bfloat16* Qh = (__nv_bfloat16*)sbuf;
    __nv_bfloat16* Ql = Qh + 64 * ASTR;
    __nv_bfloat16* Kh = Ql + 64 * ASTR;
    __nv_bfloat16* Kl = Kh + 64 * ASTR;
    __nv_bfloat16* Vh = Kl + 64 * ASTR;
    __nv_bfloat16* Vl = Vh + 64 * ASTR;

    const int b  = blockIdx.z, h = blockIdx.y;
    const int qt = gridDim.x - 1 - blockIdx.x;
    const int tid = threadIdx.x, lane = tid & 31, wid = tid >> 5;
    const int wm = wid * 16;

    const u32 sQh = smem_u32(Qh), sQl = smem_u32(Ql);
    const u32 sKh = smem_u32(Kh), sKl = smem_u32(Kl);
    const u32 sVh = smem_u32(Vh), sVl = smem_u32(Vl);

    // load Q tile once (pre-scaled): [64][128] from g_qh/g_ql slice
    for (int u = tid; u < 1024; u += 128) {
        const int r = u >> 4, c = (u & 15) * 8;
        const size_t g = (size_t)(b * T_SZ + qt * 64 + r) * C_DIM + h * HD + c;
        *(uint4*)&Qh[r * ASTR + c] = *(const uint4*)&g_qh[g];
        *(uint4*)&Ql[r * ASTR + c] = *(const uint4*)&g_ql[g];
    }

    // fragment lane geometry
    const int q = lane >> 3, r8 = lane & 7;
    const int arow = (q & 1) * 8 + r8, acolq = (q >> 1) * 8;        // A (non-trans)
    const int b4row = (lane >> 4) * 8 + (lane & 7);                 // B x4 (non-trans)
    const int b4colq = ((lane >> 3) & 1) * 8;
    const int er = lane >> 2, ec = (lane & 3) * 2;

    float m0 = -1e30f, m1 = -1e30f, l0 = 0.f, l1 = 0.f;
    float O[16][4];
#pragma unroll
    for (int t = 0; t < 16; t++)
#pragma unroll
        for (int r = 0; r < 4; r++) O[t][r] = 0.f;

    for (int kt = 0; kt <= qt; kt++) {
        __syncthreads();
        for (int u = tid; u < 1024; u += 128) {
            const int r = u >> 4, c = (u & 15) * 8;
            const size_t g = (size_t)(b * T_SZ + kt * 64 + r) * HD + c;
            *(uint4*)&Kh[r * ASTR + c] = *(const uint4*)&g_kh[g];
            *(uint4*)&Kl[r * ASTR + c] = *(const uint4*)&g_kl[g];
            *(uint4*)&Vh[r * ASTR + c] = *(const uint4*)&g_vh[g];
            *(uint4*)&Vl[r * ASTR + c] = *(const uint4*)&g_vl[g];
        }
        __syncthreads();

        // ---- S = Q @ K^T (scaled), bf16 hi/lo 3-pass ----
        float S[8][4];
#pragma unroll
        for (int t = 0; t < 8; t++)
#pragma unroll
            for (int r = 0; r < 4; r++) S[t][r] = 0.f;

#pragma unroll
        for (int ks = 0; ks < 8; ks++) {
            u32 qh[4], ql[4];
            const u32 qoff = ((wm + arow) * ASTR + ks * 16 + acolq) * 2;
            LDSM_X4(qh[0], qh[1], qh[2], qh[3], sQh + qoff);
            LDSM_X4(ql[0], ql[1], ql[2], ql[3], sQl + qoff);
#pragma unroll
            for (int nt2 = 0; nt2 < 4; nt2++) {
                u32 kh[4], kl[4];
                const u32 koff = ((nt2 * 16 + b4row) * ASTR + ks * 16 + b4colq) * 2;
                LDSM_X4(kh[0], kh[1], kh[2], kh[3], sKh + koff);
                LDSM_X4(kl[0], kl[1], kl[2], kl[3], sKl + koff);
                MMA16816(S[2*nt2],   qh, kh);     MMA16816(S[2*nt2],   qh, kl);
                MMA16816(S[2*nt2],   ql, kh);
                MMA16816(S[2*nt2+1], qh, kh + 2); MMA16816(S[2*nt2+1], qh, kl + 2);
                MMA16816(S[2*nt2+1], ql, kh + 2);
            }
        }

        // ---- causal mask on diagonal tile ----
        if (kt == qt) {
#pragma unroll
            for (int t = 0; t < 8; t++)
#pragma unroll
                for (int j = 0; j < 2; j++) {
                    const int col = t * 8 + ec + j;
                    if (col > wm + er)     S[t][j]     = -1e30f;
                    if (col > wm + er + 8) S[t][2 + j] = -1e30f;
                }
        }

        // ---- online softmax ----
        float mt0 = -1e30f, mt1 = -1e30f;
#pragma unroll
        for (int t = 0; t < 8; t++) {
            mt0 = fmaxf(mt0, fmaxf(S[t][0], S[t][1]));
            mt1 = fmaxf(mt1, fmaxf(S[t][2], S[t][3]));
        }
        mt0 = fmaxf(mt0, __shfl_xor_sync(0xffffffffu, mt0, 1));
        mt0 = fmaxf(mt0, __shfl_xor_sync(0xffffffffu, mt0, 2));
        mt1 = fmaxf(mt1, __shfl_xor_sync(0xffffffffu, mt1, 1));
        mt1 = fmaxf(mt1, __shfl_xor_sync(0xffffffffu, mt1, 2));
        const float mn0 = fmaxf(m0, mt0), mn1 = fmaxf(m1, mt1);
        const float a0 = __expf(m0 - mn0), a1 = __expf(m1 - mn1);
        m0 = mn0; m1 = mn1;
        l0 *= a0; l1 *= a1;
#pragma unroll
        for (int t = 0; t < 16; t++) {
            O[t][0] *= a0; O[t][1] *= a0;
            O[t][2] *= a1; O[t][3] *= a1;
        }

        u32 ph[8][2], pl[8][2];
        float rs0 = 0.f, rs1 = 0.f;
#pragma unroll
        for (int t = 0; t < 8; t++) {
            const float p0 = __expf(S[t][0] - mn0), p1 = __expf(S[t][1] - mn0);
            const float p2 = __expf(S[t][2] - mn1), p3 = __expf(S[t][3] - mn1);
            rs0 += p0 + p1; rs1 += p2 + p3;
            const __nv_bfloat16 h0 = __float2bfloat16(p0), h1 = __float2bfloat16(p1);
            const __nv_bfloat16 h2 = __float2bfloat16(p2), h3 = __float2bfloat16(p3);
            ph[t][0] = pack_bf2(h0, h1);
            ph[t][1] = pack_bf2(h2, h3);
            pl[t][0] = pack_bf2(__float2bfloat16(p0 - __bfloat162float(h0)),
                                __float2bfloat16(p1 - __bfloat162float(h1)));
            pl[t][1] = pack_bf2(__float2bfloat16(p2 - __bfloat162float(h2)),
                                __float2bfloat16(p3 - __bfloat162float(h3)));
        }
        rs0 += __shfl_xor_sync(0xffffffffu, rs0, 1);
        rs0 += __shfl_xor_sync(0xffffffffu, rs0, 2);
        rs1 += __shfl_xor_sync(0xffffffffu, rs1, 1);
        rs1 += __shfl_xor_sync(0xffffffffu, rs1, 2);
        l0 += rs0; l1 += rs1;

        // ---- O += P @ V, bf16 hi/lo 3-pass; V via ldmatrix.trans ----
#pragma unroll
        for (int ks2 = 0; ks2 < 4; ks2++) {
            const u32 ah[4] = {ph[2*ks2][0], ph[2*ks2][1], ph[2*ks2+1][0], ph[2*ks2+1][1]};
            const u32 al[4] = {pl[2*ks2][0], pl[2*ks2][1], pl[2*ks2+1][0], pl[2*ks2+1][1]};
#pragma unroll
            for (int nt2 = 0; nt2 < 8; nt2++) {
                u32 vh[4], vl[4];
                const u32 voff = ((ks2 * 16 + (lane & 15)) * ASTR
                                  + nt2 * 16 + (lane >> 4) * 8) * 2;
                LDSM_X4T(vh[0], vh[1], vh[2], vh[3], sVh + voff);
                LDSM_X4T(vl[0], vl[1], vl[2], vl[3], sVl + voff);
                MMA16816(O[2*nt2],   ah, vh);     MMA16816(O[2*nt2],   al, vh);
                MMA16816(O[2*nt2],   ah, vl);
                MMA16816(O[2*nt2+1], ah, vh + 2); MMA16816(O[2*nt2+1], al, vh + 2);
                MMA16816(O[2*nt2+1], ah, vl + 2);
            }
        }
    }

    // ---- write output ----
    const float inv0 = 1.0f / l0, inv1 = 1.0f / l1;
    const size_t row0 = (size_t)(b * T_SZ + qt * 64 + wm + er);
#pragma unroll
    for (int t = 0; t < 16; t++) {
        const int col = h * HD + t * 8 + ec;
        *(float2*)&out[row0 * C_DIM + col]       = make_float2(O[t][0] * inv0, O[t][1] * inv0);
        *(float2*)&out[(row0 + 8) * C_DIM + col] = make_float2(O[t][2] * inv1, O[t][3] * inv1);
    }
}

// ---------------- launcher ----------------------------------------------------
extern "C" void kernel_launch(void* const* d_in, const int* in_sizes, int n_in,
                              void* d_out, int out_size)
{
    const float* x    = (const float*)d_in[0];
    const float* Wg   = (const float*)d_in[1];
    const float* Wqkv = (const float*)d_in[2];
    float* out = (float*)d_out;

    cudaFuncSetAttribute(attn_mma_kernel, cudaFuncAttributeMaxDynamicSharedMemorySize, ATTN_SMEM);

    __nv_bfloat16 *xh, *xl, *wh, *wl;
    cudaGetSymbolAddress((void**)&xh, g_xh);
    cudaGetSymbolAddress((void**)&xl, g_xl);
    cudaGetSymbolAddress((void**)&wh, g_wh);
    cudaGetSymbolAddress((void**)&wl, g_wl);

    zero_kernel<<<512, 256>>>();
    cvt_kernel<<<(BT * C_DIM / 4 + 255) / 256, 256>>>(x, xh, xl, BT * C_DIM / 4);
    cvt_kernel<<<(C_DIM * C_DIM / 4 + 255) / 256, 256>>>(Wqkv, wh, wl, C_DIM * C_DIM / 4);
    gating_kernel<<<BT, 128>>>(x, Wg);
    qproj_mma_kernel<<<dim3(C_DIM / 128, BT / 128), 256>>>();
    kvproj_kernel<<<dim3(128, N_HEADS, 2 * KV_SPLITS), 256>>>(x, Wqkv);
    kvcvt_kernel<<<(BT * HD / 4 + 255) / 256, 256>>>();
    attn_mma_kernel<<<dim3(32, N_HEADS, B_SZ), 128, ATTN_SMEM>>>(out);
}

// round 9
// speedup vs baseline: 5.1765x; 1.0405x over previous
#include <cuda_runtime.h>
#include <cuda_bf16.h>
#include <cuda_fp16.h>
#include <math.h>

#define C_DIM   2048
#define N_HEADS 16
#define HD      128
#define B_SZ    2
#define T_SZ    2048
#define BT      (B_SZ * T_SZ)

typedef unsigned long long u64;
typedef unsigned int u32;

#define LOG2E 1.4426950408889634f

// ---------------- packed f32x2 helpers (SASS FFMA2) -------------------------
__device__ __forceinline__ u64 pk2(float lo, float hi) {
    u64 r; asm("mov.b64 %0, {%1, %2};" : "=l"(r) : "f"(lo), "f"(hi)); return r;
}
__device__ __forceinline__ void fma2(u64& d, u64 a, u64 b) {
    asm("fma.rn.f32x2 %0, %1, %2, %0;" : "+l"(d) : "l"(a), "l"(b));
}
__device__ __forceinline__ float2 upk2(u64 v) {
    float2 f; asm("mov.b64 {%0, %1}, %2;" : "=f"(f.x), "=f"(f.y) : "l"(v)); return f;
}

// ---------------- mma.sync / ldmatrix helpers (compute_103-safe) ------------
__device__ __forceinline__ u32 smem_u32(const void* p) {
    u32 a; asm("{ .reg .u64 t; cvta.to.shared.u64 t, %1; cvt.u32.u64 %0, t; }"
               : "=r"(a) : "l"(p));
    return a;
}
#define LDSM_X4(r0, r1, r2, r3, addr) \
    asm volatile("ldmatrix.sync.aligned.m8n8.x4.shared.b16 {%0,%1,%2,%3}, [%4];" \
        : "=r"(r0), "=r"(r1), "=r"(r2), "=r"(r3) : "r"(addr))
#define LDSM_X4T(r0, r1, r2, r3, addr) \
    asm volatile("ldmatrix.sync.aligned.m8n8.x4.trans.shared.b16 {%0,%1,%2,%3}, [%4];" \
        : "=r"(r0), "=r"(r1), "=r"(r2), "=r"(r3) : "r"(addr))
#define LDSM_X2(r0, r1, addr) \
    asm volatile("ldmatrix.sync.aligned.m8n8.x2.shared.b16 {%0,%1}, [%2];" \
        : "=r"(r0), "=r"(r1) : "r"(addr))
#define MMA16816(d, a, b) \
    asm volatile("mma.sync.aligned.m16n8k16.row.col.f32.bf16.bf16.f32 " \
        "{%0,%1,%2,%3}, {%4,%5,%6,%7}, {%8,%9}, {%0,%1,%2,%3};" \
        : "+f"((d)[0]), "+f"((d)[1]), "+f"((d)[2]), "+f"((d)[3]) \
        : "r"((a)[0]), "r"((a)[1]), "r"((a)[2]), "r"((a)[3]), "r"((b)[0]), "r"((b)[1]))
#define MMA16816H(d, a, b) \
    asm volatile("mma.sync.aligned.m16n8k16.row.col.f32.f16.f16.f32 " \
        "{%0,%1,%2,%3}, {%4,%5,%6,%7}, {%8,%9}, {%0,%1,%2,%3};" \
        : "+f"((d)[0]), "+f"((d)[1]), "+f"((d)[2]), "+f"((d)[3]) \
        : "r"((a)[0]), "r"((a)[1]), "r"((a)[2]), "r"((a)[3]), "r"((b)[0]), "r"((b)[1]))

__device__ __forceinline__ u32 pack_bf2(__nv_bfloat16 a, __nv_bfloat16 b) {
    __nv_bfloat162 t = __halves2bfloat162(a, b);
    return *(u32*)&t;
}
__device__ __forceinline__ u32 pack_h2(__half a, __half b) {
    __half2 t = __halves2half2(a, b);
    return *(u32*)&t;
}
__device__ __forceinline__ float ex2f(float x) {
    float r; asm("ex2.approx.f32 %0, %1;" : "=f"(r) : "f"(x)); return r;
}
__device__ __forceinline__ u32 cvtf16x2(float lo, float hi) {
    u32 r; asm("cvt.rn.f16x2.f32 %0, %1, %2;" : "=r"(r) : "f"(hi), "f"(lo)); return r;
}

// ---------------- scratch ----------------------------------------------------
__device__ __align__(16) float g_ks[BT * HD];
__device__ __align__(16) float g_vs[BT * HD];
__device__ float g_gv [BT];
__device__ int   g_cnt[N_HEADS];
__device__ int   g_list[N_HEADS * BT];
__device__ __align__(16) __nv_bfloat16 g_xh[BT * C_DIM];
__device__ __align__(16) __nv_bfloat16 g_xl[BT * C_DIM];
__device__ __align__(16) __nv_bfloat16 g_wh[C_DIM * C_DIM];
__device__ __align__(16) __nv_bfloat16 g_wl[C_DIM * C_DIM];
__device__ __align__(16) __nv_bfloat16 g_qh[BT * C_DIM];   // scaled Q hi
__device__ __align__(16) __nv_bfloat16 g_ql[BT * C_DIM];   // scaled Q lo
__device__ __align__(16) __nv_bfloat16 g_kh[BT * HD];
__device__ __align__(16) __nv_bfloat16 g_kl[BT * HD];
__device__ __align__(16) __half        g_vh[BT * HD];      // V f16 hi
__device__ __align__(16) __half        g_vl[BT * HD];      // V f16 lo

// ---------------- K0: zero counters + K/V accumulators -----------------------
__global__ __launch_bounds__(256) void zero_kernel() {
    const int i = blockIdx.x * 256 + threadIdx.x;
    const float4 z = make_float4(0.f, 0.f, 0.f, 0.f);
    if (i < BT * HD / 4) { ((float4*)g_ks)[i] = z; ((float4*)g_vs)[i] = z; }
    if (blockIdx.x == 0 && threadIdx.x < N_HEADS) g_cnt[threadIdx.x] = 0;
}

// ---------------- K1: split fp32 -> bf16 hi/lo (weights) ----------------------
__global__ __launch_bounds__(256) void cvt_kernel(
    const float* __restrict__ src, __nv_bfloat16* __restrict__ hi,
    __nv_bfloat16* __restrict__ lo, int n4)
{
    const int i = blockIdx.x * 256 + threadIdx.x;
    if (i >= n4) return;
    const float4 v = ((const float4*)src)[i];
    const float f[4] = {v.x, v.y, v.z, v.w};
    __nv_bfloat16 h[4], l[4];
#pragma unroll
    for (int j = 0; j < 4; j++) {
        h[j] = __float2bfloat16(f[j]);
        l[j] = __float2bfloat16(f[j] - __bfloat162float(h[j]));
    }
    u32* H = (u32*)hi; u32* L = (u32*)lo;
    H[2*i]   = pack_bf2(h[0], h[1]);
    H[2*i+1] = pack_bf2(h[2], h[3]);
    L[2*i]   = pack_bf2(l[0], l[1]);
    L[2*i+1] = pack_bf2(l[2], l[3]);
}

// ---------------- K2: fused x hi/lo conversion + gating -----------------------
// 16 tokens per block; Wg tiled through smem (read 256x instead of 4096x).
#define GT   16
#define XSTR 144

__global__ __launch_bounds__(256) void xcvt_gate_kernel(
    const float* __restrict__ x, const float* __restrict__ Wg)
{
    __shared__ float Xs[GT * XSTR];
    __shared__ float Ws[16 * 128];
    const int tid = threadIdx.x;
    const int t0 = blockIdx.x * GT;

    float acc[N_HEADS];
#pragma unroll
    for (int h = 0; h < N_HEADS; h++) acc[h] = 0.0f;

    for (int kc = 0; kc < C_DIM / 128; kc++) {
        __syncthreads();
        for (int u = tid; u < 512; u += 256) {          // Wg tile 16x128
            const int h = u >> 5, c4 = u & 31;
            *(float4*)&Ws[h * 128 + c4 * 4] =
                *(const float4*)&Wg[(size_t)h * C_DIM + kc * 128 + c4 * 4];
        }
        for (int u = tid; u < GT * 32; u += 256) {      // x tile 16x128 + hi/lo out
            const int r = u >> 5, c4 = u & 31;
            const size_t g = (size_t)(t0 + r) * C_DIM + kc * 128 + c4 * 4;
            const float4 v = *(const float4*)&x[g];
            *(float4*)&Xs[r * XSTR + c4 * 4] = v;
            const float f[4] = {v.x, v.y, v.z, v.w};
            __nv_bfloat16 h_[4], l_[4];
#pragma unroll
            for (int j = 0; j < 4; j++) {
                h_[j] = __float2bfloat16(f[j]);
                l_[j] = __float2bfloat16(f[j] - __bfloat162float(h_[j]));
            }
            ((u32*)&g_xh[g])[0] = pack_bf2(h_[0], h_[1]);
            ((u32*)&g_xh[g])[1] = pack_bf2(h_[2], h_[3]);
            ((u32*)&g_xl[g])[0] = pack_bf2(l_[0], l_[1]);
            ((u32*)&g_xl[g])[1] = pack_bf2(l_[2], l_[3]);
        }
        __syncthreads();
        const int r = tid >> 4, i = tid & 15;
#pragma unroll
        for (int k = 0; k < 8; k++) {
            const float xv = Xs[r * XSTR + k * 16 + i];
#pragma unroll
            for (int h = 0; h < N_HEADS; h++)
                acc[h] += xv * Ws[h * 128 + k * 16 + i];
        }
    }
    // reduce over the 16 lanes covering one token
#pragma unroll
    for (int off = 1; off < 16; off <<= 1) {
#pragma unroll
        for (int h = 0; h < N_HEADS; h++)
            acc[h] += __shfl_xor_sync(0xffffffffu, acc[h], off);
    }
    if ((tid & 15) == 0) {
        const int t = t0 + (tid >> 4);
        float mx = acc[0]; int bi = 0;
#pragma unroll
        for (int h = 1; h < N_HEADS; h++)
            if (acc[h] > mx) { mx = acc[h]; bi = h; }
        float s = 0.0f;
#pragma unroll
        for (int h = 0; h < N_HEADS; h++) s += expf(acc[h] - mx);
        g_gv[t] = 1.0f / s;
        const int pos = atomicAdd(&g_cnt[bi], 1);
        g_list[bi * BT + pos] = t;
    }
}

// ---------------- K3: Q projection via mma.sync bf16 hi/lo 3-pass -------------
#define QSTR 40

__global__ __launch_bounds__(256) void qproj_mma_kernel()
{
    __shared__ __nv_bfloat16 Ah[128 * QSTR], Al[128 * QSTR];
    __shared__ __nv_bfloat16 Bh[128 * QSTR], Bl[128 * QSTR];

    const int tid = threadIdx.x, lane = tid & 31, wid = tid >> 5;
    const int wm = (wid >> 2) * 64;
    const int wn = (wid & 3) * 32;
    const int m0 = blockIdx.y * 128, n0 = blockIdx.x * 128;

    const u32 sAh = smem_u32(Ah), sAl = smem_u32(Al);
    const u32 sBh = smem_u32(Bh), sBl = smem_u32(Bl);

    float acc[4][4][4];
#pragma unroll
    for (int i = 0; i < 4; i++)
#pragma unroll
        for (int j = 0; j < 4; j++)
#pragma unroll
            for (int r = 0; r < 4; r++) acc[i][j][r] = 0.0f;

    const int q = lane >> 3, r8 = lane & 7;
    const int arow = (q & 1) * 8 + r8, acolq = (q >> 1) * 8;
    const int l2 = lane & 15;
    const int brow = l2 & 7, bcolq = (l2 >> 3) * 8;

    for (int kt = 0; kt < C_DIM; kt += 32) {
        __syncthreads();
        for (int u = tid; u < 512; u += 256) {
            const int rr = u >> 2, cc = (u & 3) * 8;
            const size_t ga = (size_t)(m0 + rr) * C_DIM + kt + cc;
            const size_t gb = (size_t)(n0 + rr) * C_DIM + kt + cc;
            *(uint4*)&Ah[rr * QSTR + cc] = *(const uint4*)&g_xh[ga];
            *(uint4*)&Al[rr * QSTR + cc] = *(const uint4*)&g_xl[ga];
            *(uint4*)&Bh[rr * QSTR + cc] = *(const uint4*)&g_wh[gb];
            *(uint4*)&Bl[rr * QSTR + cc] = *(const uint4*)&g_wl[gb];
        }
        __syncthreads();

#pragma unroll
        for (int ks = 0; ks < 2; ks++) {
            const int acol = ks * 16 + acolq;
            const int bcol = ks * 16 + bcolq;
            u32 a_hi[4][4], a_lo[4][4], b_hi[4][2], b_lo[4][2];
#pragma unroll
            for (int mt = 0; mt < 4; mt++) {
                const u32 off = ((wm + mt * 16 + arow) * QSTR + acol) * 2;
                LDSM_X4(a_hi[mt][0], a_hi[mt][1], a_hi[mt][2], a_hi[mt][3], sAh + off);
                LDSM_X4(a_lo[mt][0], a_lo[mt][1], a_lo[mt][2], a_lo[mt][3], sAl + off);
            }
#pragma unroll
            for (int nt = 0; nt < 4; nt++) {
                const u32 off = ((wn + nt * 8 + brow) * QSTR + bcol) * 2;
                LDSM_X2(b_hi[nt][0], b_hi[nt][1], sBh + off);
                LDSM_X2(b_lo[nt][0], b_lo[nt][1], sBl + off);
            }
#pragma unroll
            for (int mt = 0; mt < 4; mt++)
#pragma unroll
                for (int nt = 0; nt < 4; nt++) {
                    MMA16816(acc[mt][nt], a_hi[mt], b_hi[nt]);
                    MMA16816(acc[mt][nt], a_hi[mt], b_lo[nt]);
                    MMA16816(acc[mt][nt], a_lo[mt], b_hi[nt]);
                }
        }
    }

    const float SC = 0.08838834764831845f;  // 1/sqrt(128)
    const int er = lane >> 2, ec = (lane & 3) * 2;
#pragma unroll
    for (int mt = 0; mt < 4; mt++) {
        const size_t row = (size_t)(m0 + wm + mt * 16 + er);
#pragma unroll
        for (int nt = 0; nt < 4; nt++) {
            const int col = n0 + wn + nt * 8 + ec;
#pragma unroll
            for (int half = 0; half < 2; half++) {
                const float v0 = acc[mt][nt][half * 2 + 0] * SC;
                const float v1 = acc[mt][nt][half * 2 + 1] * SC;
                const __nv_bfloat16 h0 = __float2bfloat16(v0);
                const __nv_bfloat16 h1 = __float2bfloat16(v1);
                const __nv_bfloat16 e0 = __float2bfloat16(v0 - __bfloat162float(h0));
                const __nv_bfloat16 e1 = __float2bfloat16(v1 - __bfloat162float(h1));
                const size_t o = (row + half * 8) * C_DIM + col;
                *(u32*)&g_qh[o] = pack_bf2(h0, h1);
                *(u32*)&g_ql[o] = pack_bf2(e0, e1);
            }
        }
    }
}

// ---------------- K4: grouped K/V projection, split-K=4 + atomics -------------
#define KV_SPLITS 4
#define KV_KCH (C_DIM / KV_SPLITS)

__global__ __launch_bounds__(256) void kvproj_kernel(
    const float* __restrict__ x, const float* __restrict__ Wqkv)
{
    const int h = blockIdx.y;
    const int kv = blockIdx.z & 1, sp = blockIdx.z >> 1;
    const int cnt = g_cnt[h];
    const int m0 = blockIdx.x * 32;
    if (m0 >= cnt) return;

    __shared__ float As[16][32];
    __shared__ float Bs[16][128];
    const int tid = threadIdx.x;
    const int blr = tid >> 2, blc = (tid & 3) << 2;
    const int tx = tid & 31, ty = tid >> 5;

    const int* lst = g_list + h * BT;
    int tokA = 0;
    if (tid < 128) tokA = lst[min(m0 + (tid >> 2), cnt - 1)];
    const float* Bp = Wqkv + (size_t)(C_DIM * (1 + kv) + h * HD) * C_DIM;

    u64 acc2[4][2];
#pragma unroll
    for (int i = 0; i < 4; i++) { acc2[i][0] = 0ULL; acc2[i][1] = 0ULL; }

    const int k0 = sp * KV_KCH;
    for (int kt = k0; kt < k0 + KV_KCH; kt += 16) {
        float4 a0 = make_float4(0.f, 0.f, 0.f, 0.f);
        if (tid < 128)
            a0 = *(const float4*)(x + (size_t)tokA * C_DIM + kt + blc);
        const float4 b0 = *(const float4*)(Bp + (size_t)blr        * C_DIM + kt + blc);
        const float4 b1 = *(const float4*)(Bp + (size_t)(blr + 64) * C_DIM + kt + blc);
        __syncthreads();
        if (tid < 128) {
            const int ar = tid >> 2;
            As[blc+0][ar] = a0.x; As[blc+1][ar] = a0.y;
            As[blc+2][ar] = a0.z; As[blc+3][ar] = a0.w;
        }
        Bs[blc+0][blr] = b0.x; Bs[blc+1][blr] = b0.y; Bs[blc+2][blr] = b0.z; Bs[blc+3][blr] = b0.w;
        Bs[blc+0][blr+64] = b1.x; Bs[blc+1][blr+64] = b1.y; Bs[blc+2][blr+64] = b1.z; Bs[blc+3][blr+64] = b1.w;
        __syncthreads();
#pragma unroll
        for (int k = 0; k < 16; k++) {
            const float4 av = *(const float4*)&As[k][ty * 4];
            const float4 bv = *(const float4*)&Bs[k][tx * 4];
            const u64 b20 = pk2(bv.x, bv.y), b21 = pk2(bv.z, bv.w);
            const float aa[4] = {av.x, av.y, av.z, av.w};
#pragma unroll
            for (int i = 0; i < 4; i++) {
                const u64 a2 = pk2(aa[i], aa[i]);
                fma2(acc2[i][0], a2, b20);
                fma2(acc2[i][1], a2, b21);
            }
        }
    }
    float* dst = kv ? g_vs : g_ks;
#pragma unroll
    for (int i = 0; i < 4; i++) {
        const int m = m0 + ty * 4 + i;
        if (m < cnt) {
            const int tok = lst[m];
            const float sc = kv ? g_gv[tok] : 1.0f;
            const float2 c0 = upk2(acc2[i][0]), c1 = upk2(acc2[i][1]);
            float* d = dst + (size_t)tok * HD + tx * 4;
            atomicAdd(d + 0, c0.x * sc);
            atomicAdd(d + 1, c0.y * sc);
            atomicAdd(d + 2, c1.x * sc);
            atomicAdd(d + 3, c1.y * sc);
        }
    }
}

// ---------------- K4b: K fp32 -> bf16 hi/lo ; V fp32 -> f16 hi/lo -------------
__global__ __launch_bounds__(256) void kvcvt_kernel() {
    const int i = blockIdx.x * 256 + threadIdx.x;
    if (i >= BT * HD / 4) return;
    {
        const float4 v = ((const float4*)g_ks)[i];
        const float f[4] = {v.x, v.y, v.z, v.w};
        __nv_bfloat16 h[4], l[4];
#pragma unroll
        for (int j = 0; j < 4; j++) {
            h[j] = __float2bfloat16(f[j]);
            l[j] = __float2bfloat16(f[j] - __bfloat162float(h[j]));
        }
        ((u32*)g_kh)[2*i]   = pack_bf2(h[0], h[1]);
        ((u32*)g_kh)[2*i+1] = pack_bf2(h[2], h[3]);
        ((u32*)g_kl)[2*i]   = pack_bf2(l[0], l[1]);
        ((u32*)g_kl)[2*i+1] = pack_bf2(l[2], l[3]);
    }
    {
        const float4 v = ((const float4*)g_vs)[i];
        const float f[4] = {v.x, v.y, v.z, v.w};
        __half h[4], l[4];
#pragma unroll
        for (int j = 0; j < 4; j++) {
            h[j] = __float2half(f[j]);
            l[j] = __float2half(f[j] - __half2float(h[j]));
        }
        ((u32*)g_vh)[2*i]   = pack_h2(h[0], h[1]);
        ((u32*)g_vh)[2*i+1] = pack_h2(h[2], h[3]);
        ((u32*)g_vl)[2*i]   = pack_h2(l[0], l[1]);
        ((u32*)g_vl)[2*i+1] = pack_h2(l[2], l[3]);
    }
}

// ---------------- K5: tensor-core causal flash MQA attention ------------------
// 4 warps, BQ=64, BK=64, HD=128. S: bf16 hi/lo 3-pass. P: f16. V: f16 hi/lo.
// Row sums via MMA against an all-ones f16 fragment.
#define ASTR 136
#define ATTN_SMEM (6 * 64 * ASTR * 2)

__global__ __launch_bounds__(128, 2) void attn_mma_kernel(float* __restrict__ out)
{
    extern __shared__ char sbuf[];
    __nv_bfloat16* Qh = (__nv_bfloat16*)sbuf;
    __nv_bfloat16* Ql = Qh + 64 * ASTR;
    __nv_bfloat16* Kh = Ql + 64 * ASTR;
    __nv_bfloat16* Kl = Kh + 64 * ASTR;
    __half*        Vh = (__half*)(Kl + 64 * ASTR);
    __half*        Vl = Vh + 64 * ASTR;

    const int b  = blockIdx.z, h = blockIdx.y;
    const int qt = gridDim.x - 1 - blockIdx.x;
    const int tid = threadIdx.x, lane = tid & 31, wid = tid >> 5;
    const int wm = wid * 16;

    const u32 sQh = smem_u32(Qh), sQl = smem_u32(Ql);
    const u32 sKh = smem_u32(Kh), sKl = smem_u32(Kl);
    const u32 sVh = smem_u32(Vh), sVl = smem_u32(Vl);

    for (int u = tid; u < 1024; u += 128) {
        const int r = u >> 4, c = (u & 15) * 8;
        const size_t g = (size_t)(b * T_SZ + qt * 64 + r) * C_DIM + h * HD + c;
        *(uint4*)&Qh[r * ASTR + c] = *(const uint4*)&g_qh[g];
        *(uint4*)&Ql[r * ASTR + c] = *(const uint4*)&g_ql[g];
    }

    const int q = lane >> 3, r8 = lane & 7;
    const int arow = (q & 1) * 8 + r8, acolq = (q >> 1) * 8;
    const int b4row = (lane >> 4) * 8 + (lane & 7);
    const int b4colq = ((lane >> 3) & 1) * 8;
    const int er = lane >> 2, ec = (lane & 3) * 2;

    float m0 = -1e30f, m1 = -1e30f;
    float La[4] = {0.f, 0.f, 0.f, 0.f};
    float O[16][4];
#pragma unroll
    for (int t = 0; t < 16; t++)
#pragma unroll
        for (int r = 0; r < 4; r++) O[t][r] = 0.f;

    const u32 ones2 = 0x3C003C00u;
    const u32 onesfrag[2] = {ones2, ones2};

    for (int kt = 0; kt <= qt; kt++) {
        __syncthreads();
        for (int u = tid; u < 1024; u += 128) {
            const int r = u >> 4, c = (u & 15) * 8;
            const size_t g = (size_t)(b * T_SZ + kt * 64 + r) * HD + c;
            *(uint4*)&Kh[r * ASTR + c] = *(const uint4*)&g_kh[g];
            *(uint4*)&Kl[r * ASTR + c] = *(const uint4*)&g_kl[g];
            *(uint4*)&Vh[r * ASTR + c] = *(const uint4*)&g_vh[g];
            *(uint4*)&Vl[r * ASTR + c] = *(const uint4*)&g_vl[g];
        }
        __syncthreads();

        // ---- S = Q @ K^T (pre-scaled), bf16 hi/lo 3-pass ----
        float S[8][4];
#pragma unroll
        for (int t = 0; t < 8; t++)
#pragma unroll
            for (int r = 0; r < 4; r++) S[t][r] = 0.f;

#pragma unroll
        for (int ks = 0; ks < 8; ks++) {
            u32 qh[4], ql[4];
            const u32 qoff = ((wm + arow) * ASTR + ks * 16 + acolq) * 2;
            LDSM_X4(qh[0], qh[1], qh[2], qh[3], sQh + qoff);
            LDSM_X4(ql[0], ql[1], ql[2], ql[3], sQl + qoff);
#pragma unroll
            for (int nt2 = 0; nt2 < 4; nt2++) {
                u32 kh[4], kl[4];
                const u32 koff = ((nt2 * 16 + b4row) * ASTR + ks * 16 + b4colq) * 2;
                LDSM_X4(kh[0], kh[1], kh[2], kh[3], sKh + koff);
                LDSM_X4(kl[0], kl[1], kl[2], kl[3], sKl + koff);
                MMA16816(S[2*nt2],   qh, kh);     MMA16816(S[2*nt2],   qh, kl);
                MMA16816(S[2*nt2],   ql, kh);
                MMA16816(S[2*nt2+1], qh, kh + 2); MMA16816(S[2*nt2+1], qh, kl + 2);
                MMA16816(S[2*nt2+1], ql, kh + 2);
            }
        }

        if (kt == qt) {
#pragma unroll
            for (int t = 0; t < 8; t++)
#pragma unroll
                for (int j = 0; j < 2; j++) {
                    const int col = t * 8 + ec + j;
                    if (col > wm + er)     S[t][j]     = -1e30f;
                    if (col > wm + er + 8) S[t][2 + j] = -1e30f;
                }
        }

        // ---- online softmax (P in f16; row-sums via MMA) ----
        float mt0 = -1e30f, mt1 = -1e30f;
#pragma unroll
        for (int t = 0; t < 8; t++) {
            mt0 = fmaxf(mt0, fmaxf(S[t][0], S[t][1]));
            mt1 = fmaxf(mt1, fmaxf(S[t][2], S[t][3]));
        }
        mt0 = fmaxf(mt0, __shfl_xor_sync(0xffffffffu, mt0, 1));
        mt0 = fmaxf(mt0, __shfl_xor_sync(0xffffffffu, mt0, 2));
        mt1 = fmaxf(mt1, __shfl_xor_sync(0xffffffffu, mt1, 1));
        mt1 = fmaxf(mt1, __shfl_xor_sync(0xffffffffu, mt1, 2));
        const float mn0 = fmaxf(m0, mt0), mn1 = fmaxf(m1, mt1);
        const float a0 = __expf(m0 - mn0), a1 = __expf(m1 - mn1);
        m0 = mn0; m1 = mn1;
        La[0] *= a0; La[1] *= a0; La[2] *= a1; La[3] *= a1;
#pragma unroll
        for (int t = 0; t < 16; t++) {
            O[t][0] *= a0; O[t][1] *= a0;
            O[t][2] *= a1; O[t][3] *= a1;
        }

        const float mnl0 = mn0 * LOG2E, mnl1 = mn1 * LOG2E;
        u32 ph[8][2];
#pragma unroll
        for (int t = 0; t < 8; t++) {
            const float p0 = ex2f(fmaf(S[t][0], LOG2E, -mnl0));
            const float p1 = ex2f(fmaf(S[t][1], LOG2E, -mnl0));
            const float p2 = ex2f(fmaf(S[t][2], LOG2E, -mnl1));
            const float p3 = ex2f(fmaf(S[t][3], LOG2E, -mnl1));
            ph[t][0] = cvtf16x2(p0, p1);
            ph[t][1] = cvtf16x2(p2, p3);
        }

        // ---- O += P @ (Vh + Vl), f16 2-pass; ldmatrix.trans for V ----
#pragma unroll
        for (int ks2 = 0; ks2 < 4; ks2++) {
            const u32 ah[4] = {ph[2*ks2][0], ph[2*ks2][1], ph[2*ks2+1][0], ph[2*ks2+1][1]};
            MMA16816H(La, ah, onesfrag);   // row sums
#pragma unroll
            for (int nt2 = 0; nt2 < 8; nt2++) {
                u32 vh[4], vl[4];
                const u32 voff = ((ks2 * 16 + (lane & 15)) * ASTR
                                  + nt2 * 16 + (lane >> 4) * 8) * 2;
                LDSM_X4T(vh[0], vh[1], vh[2], vh[3], sVh + voff);
                LDSM_X4T(vl[0], vl[1], vl[2], vl[3], sVl + voff);
                MMA16816H(O[2*nt2],   ah, vh);     MMA16816H(O[2*nt2],   ah, vl);
                MMA16816H(O[2*nt2+1], ah, vh + 2); MMA16816H(O[2*nt2+1], ah, vl + 2);
            }
        }
    }

    const float inv0 = 1.0f / La[0], inv1 = 1.0f / La[2];
    const size_t row0 = (size_t)(b * T_SZ + qt * 64 + wm + er);
#pragma unroll
    for (int t = 0; t < 16; t++) {
        const int col = h * HD + t * 8 + ec;
        *(float2*)&out[row0 * C_DIM + col]       = make_float2(O[t][0] * inv0, O[t][1] * inv0);
        *(float2*)&out[(row0 + 8) * C_DIM + col] = make_float2(O[t][2] * inv1, O[t][3] * inv1);
    }
}

// ---------------- launcher ----------------------------------------------------
extern "C" void kernel_launch(void* const* d_in, const int* in_sizes, int n_in,
                              void* d_out, int out_size)
{
    const float* x    = (const float*)d_in[0];
    const float* Wg   = (const float*)d_in[1];
    const float* Wqkv = (const float*)d_in[2];
    float* out = (float*)d_out;

    cudaFuncSetAttribute(attn_mma_kernel, cudaFuncAttributeMaxDynamicSharedMemorySize, ATTN_SMEM);

    __nv_bfloat16 *wh, *wl;
    cudaGetSymbolAddress((void**)&wh, g_wh);
    cudaGetSymbolAddress((void**)&wl, g_wl);

    zero_kernel<<<512, 256>>>();
    cvt_kernel<<<(C_DIM * C_DIM / 4 + 255) / 256, 256>>>(Wqkv, wh, wl, C_DIM * C_DIM / 4);
    xcvt_gate_kernel<<<BT / GT, 256>>>(x, Wg);
    qproj_mma_kernel<<<dim3(C_DIM / 128, BT / 128), 256>>>();
    kvproj_kernel<<<dim3(128, N_HEADS, 2 * KV_SPLITS), 256>>>(x, Wqkv);
    kvcvt_kernel<<<(BT * HD / 4 + 255) / 256, 256>>>();
    attn_mma_kernel<<<dim3(32, N_HEADS, B_SZ), 128, ATTN_SMEM>>>(out);
}

// round 10
// speedup vs baseline: 5.4611x; 1.0550x over previous
#include <cuda_runtime.h>
#include <cuda_bf16.h>
#include <cuda_fp16.h>
#include <math.h>

#define C_DIM   2048
#define N_HEADS 16
#define HD      128
#define B_SZ    2
#define T_SZ    2048
#define BT      (B_SZ * T_SZ)

typedef unsigned long long u64;
typedef unsigned int u32;

#define LOG2E 1.4426950408889634f

// ---------------- packed f32x2 helpers (SASS FFMA2) -------------------------
__device__ __forceinline__ u64 pk2(float lo, float hi) {
    u64 r; asm("mov.b64 %0, {%1, %2};" : "=l"(r) : "f"(lo), "f"(hi)); return r;
}
__device__ __forceinline__ void fma2(u64& d, u64 a, u64 b) {
    asm("fma.rn.f32x2 %0, %1, %2, %0;" : "+l"(d) : "l"(a), "l"(b));
}
__device__ __forceinline__ float2 upk2(u64 v) {
    float2 f; asm("mov.b64 {%0, %1}, %2;" : "=f"(f.x), "=f"(f.y) : "l"(v)); return f;
}

// ---------------- mma.sync / ldmatrix / cp.async helpers --------------------
__device__ __forceinline__ u32 smem_u32(const void* p) {
    u32 a; asm("{ .reg .u64 t; cvta.to.shared.u64 t, %1; cvt.u32.u64 %0, t; }"
               : "=r"(a) : "l"(p));
    return a;
}
#define LDSM_X4(r0, r1, r2, r3, addr) \
    asm volatile("ldmatrix.sync.aligned.m8n8.x4.shared.b16 {%0,%1,%2,%3}, [%4];" \
        : "=r"(r0), "=r"(r1), "=r"(r2), "=r"(r3) : "r"(addr))
#define LDSM_X4T(r0, r1, r2, r3, addr) \
    asm volatile("ldmatrix.sync.aligned.m8n8.x4.trans.shared.b16 {%0,%1,%2,%3}, [%4];" \
        : "=r"(r0), "=r"(r1), "=r"(r2), "=r"(r3) : "r"(addr))
#define LDSM_X2(r0, r1, addr) \
    asm volatile("ldmatrix.sync.aligned.m8n8.x2.shared.b16 {%0,%1}, [%2];" \
        : "=r"(r0), "=r"(r1) : "r"(addr))
#define MMA16816(d, a, b) \
    asm volatile("mma.sync.aligned.m16n8k16.row.col.f32.bf16.bf16.f32 " \
        "{%0,%1,%2,%3}, {%4,%5,%6,%7}, {%8,%9}, {%0,%1,%2,%3};" \
        : "+f"((d)[0]), "+f"((d)[1]), "+f"((d)[2]), "+f"((d)[3]) \
        : "r"((a)[0]), "r"((a)[1]), "r"((a)[2]), "r"((a)[3]), "r"((b)[0]), "r"((b)[1]))
#define MMA16816H(d, a, b) \
    asm volatile("mma.sync.aligned.m16n8k16.row.col.f32.f16.f16.f32 " \
        "{%0,%1,%2,%3}, {%4,%5,%6,%7}, {%8,%9}, {%0,%1,%2,%3};" \
        : "+f"((d)[0]), "+f"((d)[1]), "+f"((d)[2]), "+f"((d)[3]) \
        : "r"((a)[0]), "r"((a)[1]), "r"((a)[2]), "r"((a)[3]), "r"((b)[0]), "r"((b)[1]))
#define CP16(daddr, gsrc) \
    asm volatile("cp.async.cg.shared.global [%0], [%1], 16;" \
        :: "r"(daddr), "l"(gsrc) : "memory")
#define CP_COMMIT() asm volatile("cp.async.commit_group;" ::: "memory")
#define CP_WAIT0()  asm volatile("cp.async.wait_group 0;" ::: "memory")
#define CP_WAIT1()  asm volatile("cp.async.wait_group 1;" ::: "memory")

__device__ __forceinline__ u32 pack_bf2(__nv_bfloat16 a, __nv_bfloat16 b) {
    __nv_bfloat162 t = __halves2bfloat162(a, b);
    return *(u32*)&t;
}
__device__ __forceinline__ u32 pack_h2(__half a, __half b) {
    __half2 t = __halves2half2(a, b);
    return *(u32*)&t;
}
__device__ __forceinline__ float ex2f(float x) {
    float r; asm("ex2.approx.f32 %0, %1;" : "=f"(r) : "f"(x)); return r;
}
__device__ __forceinline__ u32 cvtf16x2(float lo, float hi) {
    u32 r; asm("cvt.rn.f16x2.f32 %0, %1, %2;" : "=r"(r) : "f"(hi), "f"(lo)); return r;
}

// ---------------- scratch ----------------------------------------------------
__device__ __align__(16) float g_ks[BT * HD];
__device__ __align__(16) float g_vs[BT * HD];
__device__ float g_gv [BT];
__device__ int   g_cnt[N_HEADS];
__device__ int   g_list[N_HEADS * BT];
__device__ __align__(16) __nv_bfloat16 g_xh[BT * C_DIM];
__device__ __align__(16) __nv_bfloat16 g_xl[BT * C_DIM];
__device__ __align__(16) __nv_bfloat16 g_wh[C_DIM * C_DIM];
__device__ __align__(16) __nv_bfloat16 g_wl[C_DIM * C_DIM];
__device__ __align__(16) __nv_bfloat16 g_qh[BT * C_DIM];   // scaled Q hi
__device__ __align__(16) __nv_bfloat16 g_ql[BT * C_DIM];   // scaled Q lo
__device__ __align__(16) __nv_bfloat16 g_kh[BT * HD];
__device__ __align__(16) __nv_bfloat16 g_kl[BT * HD];
__device__ __align__(16) __half        g_vh[BT * HD];      // V f16 hi
__device__ __align__(16) __half        g_vl[BT * HD];      // V f16 lo

// ---------------- K0: zero counters + K/V accumulators -----------------------
__global__ __launch_bounds__(256) void zero_kernel() {
    const int i = blockIdx.x * 256 + threadIdx.x;
    const float4 z = make_float4(0.f, 0.f, 0.f, 0.f);
    if (i < BT * HD / 4) { ((float4*)g_ks)[i] = z; ((float4*)g_vs)[i] = z; }
    if (blockIdx.x == 0 && threadIdx.x < N_HEADS) g_cnt[threadIdx.x] = 0;
}

// ---------------- K1: split fp32 -> bf16 hi/lo (Q weights only) ---------------
__global__ __launch_bounds__(256) void cvt_kernel(
    const float* __restrict__ src, __nv_bfloat16* __restrict__ hi,
    __nv_bfloat16* __restrict__ lo, int n4)
{
    const int i = blockIdx.x * 256 + threadIdx.x;
    if (i >= n4) return;
    const float4 v = ((const float4*)src)[i];
    const float f[4] = {v.x, v.y, v.z, v.w};
    __nv_bfloat16 h[4], l[4];
#pragma unroll
    for (int j = 0; j < 4; j++) {
        h[j] = __float2bfloat16(f[j]);
        l[j] = __float2bfloat16(f[j] - __bfloat162float(h[j]));
    }
    u32* H = (u32*)hi; u32* L = (u32*)lo;
    H[2*i]   = pack_bf2(h[0], h[1]);
    H[2*i+1] = pack_bf2(h[2], h[3]);
    L[2*i]   = pack_bf2(l[0], l[1]);
    L[2*i+1] = pack_bf2(l[2], l[3]);
}

// ---------------- K2: fused x hi/lo conversion + gating -----------------------
#define GT   16
#define XSTR 144

__global__ __launch_bounds__(256) void xcvt_gate_kernel(
    const float* __restrict__ x, const float* __restrict__ Wg)
{
    __shared__ float Xs[GT * XSTR];
    __shared__ float Ws[16 * 128];
    const int tid = threadIdx.x;
    const int t0 = blockIdx.x * GT;

    float acc[N_HEADS];
#pragma unroll
    for (int h = 0; h < N_HEADS; h++) acc[h] = 0.0f;

    for (int kc = 0; kc < C_DIM / 128; kc++) {
        __syncthreads();
        for (int u = tid; u < 512; u += 256) {
            const int h = u >> 5, c4 = u & 31;
            *(float4*)&Ws[h * 128 + c4 * 4] =
                *(const float4*)&Wg[(size_t)h * C_DIM + kc * 128 + c4 * 4];
        }
        for (int u = tid; u < GT * 32; u += 256) {
            const int r = u >> 5, c4 = u & 31;
            const size_t g = (size_t)(t0 + r) * C_DIM + kc * 128 + c4 * 4;
            const float4 v = *(const float4*)&x[g];
            *(float4*)&Xs[r * XSTR + c4 * 4] = v;
            const float f[4] = {v.x, v.y, v.z, v.w};
            __nv_bfloat16 h_[4], l_[4];
#pragma unroll
            for (int j = 0; j < 4; j++) {
                h_[j] = __float2bfloat16(f[j]);
                l_[j] = __float2bfloat16(f[j] - __bfloat162float(h_[j]));
            }
            ((u32*)&g_xh[g])[0] = pack_bf2(h_[0], h_[1]);
            ((u32*)&g_xh[g])[1] = pack_bf2(h_[2], h_[3]);
            ((u32*)&g_xl[g])[0] = pack_bf2(l_[0], l_[1]);
            ((u32*)&g_xl[g])[1] = pack_bf2(l_[2], l_[3]);
        }
        __syncthreads();
        const int r = tid >> 4, i = tid & 15;
#pragma unroll
        for (int k = 0; k < 8; k++) {
            const float xv = Xs[r * XSTR + k * 16 + i];
#pragma unroll
            for (int h = 0; h < N_HEADS; h++)
                acc[h] += xv * Ws[h * 128 + k * 16 + i];
        }
    }
#pragma unroll
    for (int off = 1; off < 16; off <<= 1) {
#pragma unroll
        for (int h = 0; h < N_HEADS; h++)
            acc[h] += __shfl_xor_sync(0xffffffffu, acc[h], off);
    }
    if ((tid & 15) == 0) {
        const int t = t0 + (tid >> 4);
        float mx = acc[0]; int bi = 0;
#pragma unroll
        for (int h = 1; h < N_HEADS; h++)
            if (acc[h] > mx) { mx = acc[h]; bi = h; }
        float s = 0.0f;
#pragma unroll
        for (int h = 0; h < N_HEADS; h++) s += expf(acc[h] - mx);
        g_gv[t] = 1.0f / s;
        const int pos = atomicAdd(&g_cnt[bi], 1);
        g_list[bi * BT + pos] = t;
    }
}

// ---------------- K3: Q projection, mma.sync + cp.async double-buffer ---------
// CTA tile 128x128, K-chunk 32, 2-stage pipeline. bf16 hi/lo 3-pass.
#define QSTR 40
#define QP_SZ   (128 * QSTR)          // elements per array per stage
#define QP_SZB  (QP_SZ * 2)           // bytes
#define QP_STAGEB (4 * QP_SZB)        // bytes per stage (Ah,Al,Bh,Bl)
#define QP_SMEM (2 * QP_STAGEB)       // 81920 B

__global__ __launch_bounds__(256, 2) void qproj_mma_kernel()
{
    extern __shared__ __nv_bfloat16 qsm[];
    const u32 sb = smem_u32(qsm);

    const int tid = threadIdx.x, lane = tid & 31, wid = tid >> 5;
    const int wm = (wid >> 2) * 64;
    const int wn = (wid & 3) * 32;
    const int m0 = blockIdx.y * 128, n0 = blockIdx.x * 128;

    float acc[4][4][4];
#pragma unroll
    for (int i = 0; i < 4; i++)
#pragma unroll
        for (int j = 0; j < 4; j++)
#pragma unroll
            for (int r = 0; r < 4; r++) acc[i][j][r] = 0.0f;

    const int q = lane >> 3, r8 = lane & 7;
    const int arow = (q & 1) * 8 + r8, acolq = (q >> 1) * 8;
    const int l2 = lane & 15;
    const int brow = l2 & 7, bcolq = (l2 >> 3) * 8;

    // per-thread cp.async assignments: 2048 16B-chunks per stage, 8 per thread
    // u: [arr(2b)][row(7b)][chunk(2b)]
    auto issue_stage = [&](int kt, int s) {
#pragma unroll
        for (int v = 0; v < 8; v++) {
            const int u = tid + v * 256;
            const int arr = u >> 9;
            const int rr = (u >> 2) & 127;
            const int cc = (u & 3) * 8;
            const __nv_bfloat16* gp;
            if (arr == 0)      gp = g_xh + (size_t)(m0 + rr) * C_DIM + kt + cc;
            else if (arr == 1) gp = g_xl + (size_t)(m0 + rr) * C_DIM + kt + cc;
            else if (arr == 2) gp = g_wh + (size_t)(n0 + rr) * C_DIM + kt + cc;
            else               gp = g_wl + (size_t)(n0 + rr) * C_DIM + kt + cc;
            const u32 da = sb + s * QP_STAGEB + arr * QP_SZB + (rr * QSTR + cc) * 2;
            CP16(da, gp);
        }
        CP_COMMIT();
    };

    issue_stage(0, 0);

    const int NIT = C_DIM / 32;   // 64
    for (int i = 0; i < NIT; i++) {
        const int s = i & 1;
        if (i + 1 < NIT) { issue_stage((i + 1) * 32, s ^ 1); CP_WAIT1(); }
        else             { CP_WAIT0(); }
        __syncthreads();

        const u32 sAh = sb + s * QP_STAGEB;
        const u32 sAl = sAh + QP_SZB;
        const u32 sBh = sAl + QP_SZB;
        const u32 sBl = sBh + QP_SZB;

#pragma unroll
        for (int ks = 0; ks < 2; ks++) {
            const int acol = ks * 16 + acolq;
            const int bcol = ks * 16 + bcolq;
            u32 a_hi[4][4], a_lo[4][4], b_hi[4][2], b_lo[4][2];
#pragma unroll
            for (int mt = 0; mt < 4; mt++) {
                const u32 off = ((wm + mt * 16 + arow) * QSTR + acol) * 2;
                LDSM_X4(a_hi[mt][0], a_hi[mt][1], a_hi[mt][2], a_hi[mt][3], sAh + off);
                LDSM_X4(a_lo[mt][0], a_lo[mt][1], a_lo[mt][2], a_lo[mt][3], sAl + off);
            }
#pragma unroll
            for (int nt = 0; nt < 4; nt++) {
                const u32 off = ((wn + nt * 8 + brow) * QSTR + bcol) * 2;
                LDSM_X2(b_hi[nt][0], b_hi[nt][1], sBh + off);
                LDSM_X2(b_lo[nt][0], b_lo[nt][1], sBl + off);
            }
#pragma unroll
            for (int mt = 0; mt < 4; mt++)
#pragma unroll
                for (int nt = 0; nt < 4; nt++) {
                    MMA16816(acc[mt][nt], a_hi[mt], b_hi[nt]);
                    MMA16816(acc[mt][nt], a_hi[mt], b_lo[nt]);
                    MMA16816(acc[mt][nt], a_lo[mt], b_hi[nt]);
                }
        }
        __syncthreads();
    }

    const float SC = 0.08838834764831845f;  // 1/sqrt(128)
    const int er = lane >> 2, ec = (lane & 3) * 2;
#pragma unroll
    for (int mt = 0; mt < 4; mt++) {
        const size_t row = (size_t)(m0 + wm + mt * 16 + er);
#pragma unroll
        for (int nt = 0; nt < 4; nt++) {
            const int col = n0 + wn + nt * 8 + ec;
#pragma unroll
            for (int half = 0; half < 2; half++) {
                const float v0 = acc[mt][nt][half * 2 + 0] * SC;
                const float v1 = acc[mt][nt][half * 2 + 1] * SC;
                const __nv_bfloat16 h0 = __float2bfloat16(v0);
                const __nv_bfloat16 h1 = __float2bfloat16(v1);
                const __nv_bfloat16 e0 = __float2bfloat16(v0 - __bfloat162float(h0));
                const __nv_bfloat16 e1 = __float2bfloat16(v1 - __bfloat162float(h1));
                const size_t o = (row + half * 8) * C_DIM + col;
                *(u32*)&g_qh[o] = pack_bf2(h0, h1);
                *(u32*)&g_ql[o] = pack_bf2(e0, e1);
            }
        }
    }
}

// ---------------- K4: grouped K/V projection, split-K=4 + atomics -------------
#define KV_SPLITS 4
#define KV_KCH (C_DIM / KV_SPLITS)

__global__ __launch_bounds__(256) void kvproj_kernel(
    const float* __restrict__ x, const float* __restrict__ Wqkv)
{
    const int h = blockIdx.y;
    const int kv = blockIdx.z & 1, sp = blockIdx.z >> 1;
    const int cnt = g_cnt[h];
    const int m0 = blockIdx.x * 32;
    if (m0 >= cnt) return;

    __shared__ float As[16][32];
    __shared__ float Bs[16][128];
    const int tid = threadIdx.x;
    const int blr = tid >> 2, blc = (tid & 3) << 2;
    const int tx = tid & 31, ty = tid >> 5;

    const int* lst = g_list + h * BT;
    int tokA = 0;
    if (tid < 128) tokA = lst[min(m0 + (tid >> 2), cnt - 1)];
    const float* Bp = Wqkv + (size_t)(C_DIM * (1 + kv) + h * HD) * C_DIM;

    u64 acc2[4][2];
#pragma unroll
    for (int i = 0; i < 4; i++) { acc2[i][0] = 0ULL; acc2[i][1] = 0ULL; }

    const int k0 = sp * KV_KCH;
    for (int kt = k0; kt < k0 + KV_KCH; kt += 16) {
        float4 a0 = make_float4(0.f, 0.f, 0.f, 0.f);
        if (tid < 128)
            a0 = *(const float4*)(x + (size_t)tokA * C_DIM + kt + blc);
        const float4 b0 = *(const float4*)(Bp + (size_t)blr        * C_DIM + kt + blc);
        const float4 b1 = *(const float4*)(Bp + (size_t)(blr + 64) * C_DIM + kt + blc);
        __syncthreads();
        if (tid < 128) {
            const int ar = tid >> 2;
            As[blc+0][ar] = a0.x; As[blc+1][ar] = a0.y;
            As[blc+2][ar] = a0.z; As[blc+3][ar] = a0.w;
        }
        Bs[blc+0][blr] = b0.x; Bs[blc+1][blr] = b0.y; Bs[blc+2][blr] = b0.z; Bs[blc+3][blr] = b0.w;
        Bs[blc+0][blr+64] = b1.x; Bs[blc+1][blr+64] = b1.y; Bs[blc+2][blr+64] = b1.z; Bs[blc+3][blr+64] = b1.w;
        __syncthreads();
#pragma unroll
        for (int k = 0; k < 16; k++) {
            const float4 av = *(const float4*)&As[k][ty * 4];
            const float4 bv = *(const float4*)&Bs[k][tx * 4];
            const u64 b20 = pk2(bv.x, bv.y), b21 = pk2(bv.z, bv.w);
            const float aa[4] = {av.x, av.y, av.z, av.w};
#pragma unroll
            for (int i = 0; i < 4; i++) {
                const u64 a2 = pk2(aa[i], aa[i]);
                fma2(acc2[i][0], a2, b20);
                fma2(acc2[i][1], a2, b21);
            }
        }
    }
    float* dst = kv ? g_vs : g_ks;
#pragma unroll
    for (int i = 0; i < 4; i++) {
        const int m = m0 + ty * 4 + i;
        if (m < cnt) {
            const int tok = lst[m];
            const float sc = kv ? g_gv[tok] : 1.0f;
            const float2 c0 = upk2(acc2[i][0]), c1 = upk2(acc2[i][1]);
            float* d = dst + (size_t)tok * HD + tx * 4;
            atomicAdd(d + 0, c0.x * sc);
            atomicAdd(d + 1, c0.y * sc);
            atomicAdd(d + 2, c1.x * sc);
            atomicAdd(d + 3, c1.y * sc);
        }
    }
}

// ---------------- K4b: K fp32 -> bf16 hi/lo ; V fp32 -> f16 hi/lo -------------
__global__ __launch_bounds__(256) void kvcvt_kernel() {
    const int i = blockIdx.x * 256 + threadIdx.x;
    if (i >= BT * HD / 4) return;
    {
        const float4 v = ((const float4*)g_ks)[i];
        const float f[4] = {v.x, v.y, v.z, v.w};
        __nv_bfloat16 h[4], l[4];
#pragma unroll
        for (int j = 0; j < 4; j++) {
            h[j] = __float2bfloat16(f[j]);
            l[j] = __float2bfloat16(f[j] - __bfloat162float(h[j]));
        }
        ((u32*)g_kh)[2*i]   = pack_bf2(h[0], h[1]);
        ((u32*)g_kh)[2*i+1] = pack_bf2(h[2], h[3]);
        ((u32*)g_kl)[2*i]   = pack_bf2(l[0], l[1]);
        ((u32*)g_kl)[2*i+1] = pack_bf2(l[2], l[3]);
    }
    {
        const float4 v = ((const float4*)g_vs)[i];
        const float f[4] = {v.x, v.y, v.z, v.w};
        __half h[4], l[4];
#pragma unroll
        for (int j = 0; j < 4; j++) {
            h[j] = __float2half(f[j]);
            l[j] = __float2half(f[j] - __half2float(h[j]));
        }
        ((u32*)g_vh)[2*i]   = pack_h2(h[0], h[1]);
        ((u32*)g_vh)[2*i+1] = pack_h2(h[2], h[3]);
        ((u32*)g_vl)[2*i]   = pack_h2(l[0], l[1]);
        ((u32*)g_vl)[2*i+1] = pack_h2(l[2], l[3]);
    }
}

// ---------------- K5: tensor-core causal flash MQA attention ------------------
#define ASTR 136
#define ATTN_SMEM (6 * 64 * ASTR * 2)

__global__ __launch_bounds__(128, 2) void attn_mma_kernel(float* __restrict__ out)
{
    extern __shared__ char sbuf[];
    __nv_bfloat16* Qh = (__nv_bfloat16*)sbuf;
    __nv_bfloat16* Ql = Qh + 64 * ASTR;
    __nv_bfloat16* Kh = Ql + 64 * ASTR;
    __nv_bfloat16* Kl = Kh + 64 * ASTR;
    __half*        Vh = (__half*)(Kl + 64 * ASTR);
    __half*        Vl = Vh + 64 * ASTR;

    const int b  = blockIdx.z, h = blockIdx.y;
    const int qt = gridDim.x - 1 - blockIdx.x;
    const int tid = threadIdx.x, lane = tid & 31, wid = tid >> 5;
    const int wm = wid * 16;

    const u32 sQh = smem_u32(Qh), sQl = smem_u32(Ql);
    const u32 sKh = smem_u32(Kh), sKl = smem_u32(Kl);
    const u32 sVh = smem_u32(Vh), sVl = smem_u32(Vl);

    for (int u = tid; u < 1024; u += 128) {
        const int r = u >> 4, c = (u & 15) * 8;
        const size_t g = (size_t)(b * T_SZ + qt * 64 + r) * C_DIM + h * HD + c;
        *(uint4*)&Qh[r * ASTR + c] = *(const uint4*)&g_qh[g];
        *(uint4*)&Ql[r * ASTR + c] = *(const uint4*)&g_ql[g];
    }

    const int q = lane >> 3, r8 = lane & 7;
    const int arow = (q & 1) * 8 + r8, acolq = (q >> 1) * 8;
    const int b4row = (lane >> 4) * 8 + (lane & 7);
    const int b4colq = ((lane >> 3) & 1) * 8;
    const int er = lane >> 2, ec = (lane & 3) * 2;

    float m0 = -1e30f, m1 = -1e30f;
    float La[4] = {0.f, 0.f, 0.f, 0.f};
    float O[16][4];
#pragma unroll
    for (int t = 0; t < 16; t++)
#pragma unroll
        for (int r = 0; r < 4; r++) O[t][r] = 0.f;

    const u32 ones2 = 0x3C003C00u;
    const u32 onesfrag[2] = {ones2, ones2};

    for (int kt = 0; kt <= qt; kt++) {
        __syncthreads();
        for (int u = tid; u < 1024; u += 128) {
            const int r = u >> 4, c = (u & 15) * 8;
            const size_t g = (size_t)(b * T_SZ + kt * 64 + r) * HD + c;
            *(uint4*)&Kh[r * ASTR + c] = *(const uint4*)&g_kh[g];
            *(uint4*)&Kl[r * ASTR + c] = *(const uint4*)&g_kl[g];
            *(uint4*)&Vh[r * ASTR + c] = *(const uint4*)&g_vh[g];
            *(uint4*)&Vl[r * ASTR + c] = *(const uint4*)&g_vl[g];
        }
        __syncthreads();

        float S[8][4];
#pragma unroll
        for (int t = 0; t < 8; t++)
#pragma unroll
            for (int r = 0; r < 4; r++) S[t][r] = 0.f;

#pragma unroll
        for (int ks = 0; ks < 8; ks++) {
            u32 qh[4], ql[4];
            const u32 qoff = ((wm + arow) * ASTR + ks * 16 + acolq) * 2;
            LDSM_X4(qh[0], qh[1], qh[2], qh[3], sQh + qoff);
            LDSM_X4(ql[0], ql[1], ql[2], ql[3], sQl + qoff);
#pragma unroll
            for (int nt2 = 0; nt2 < 4; nt2++) {
                u32 kh[4], kl[4];
                const u32 koff = ((nt2 * 16 + b4row) * ASTR + ks * 16 + b4colq) * 2;
                LDSM_X4(kh[0], kh[1], kh[2], kh[3], sKh + koff);
                LDSM_X4(kl[0], kl[1], kl[2], kl[3], sKl + koff);
                MMA16816(S[2*nt2],   qh, kh);     MMA16816(S[2*nt2],   qh, kl);
                MMA16816(S[2*nt2],   ql, kh);
                MMA16816(S[2*nt2+1], qh, kh + 2); MMA16816(S[2*nt2+1], qh, kl + 2);
                MMA16816(S[2*nt2+1], ql, kh + 2);
            }
        }

        if (kt == qt) {
#pragma unroll
            for (int t = 0; t < 8; t++)
#pragma unroll
                for (int j = 0; j < 2; j++) {
                    const int col = t * 8 + ec + j;
                    if (col > wm + er)     S[t][j]     = -1e30f;
                    if (col > wm + er + 8) S[t][2 + j] = -1e30f;
                }
        }

        float mt0 = -1e30f, mt1 = -1e30f;
#pragma unroll
        for (int t = 0; t < 8; t++) {
            mt0 = fmaxf(mt0, fmaxf(S[t][0], S[t][1]));
            mt1 = fmaxf(mt1, fmaxf(S[t][2], S[t][3]));
        }
        mt0 = fmaxf(mt0, __shfl_xor_sync(0xffffffffu, mt0, 1));
        mt0 = fmaxf(mt0, __shfl_xor_sync(0xffffffffu, mt0, 2));
        mt1 = fmaxf(mt1, __shfl_xor_sync(0xffffffffu, mt1, 1));
        mt1 = fmaxf(mt1, __shfl_xor_sync(0xffffffffu, mt1, 2));
        const float mn0 = fmaxf(m0, mt0), mn1 = fmaxf(m1, mt1);
        const float a0 = __expf(m0 - mn0), a1 = __expf(m1 - mn1);
        m0 = mn0; m1 = mn1;
        La[0] *= a0; La[1] *= a0; La[2] *= a1; La[3] *= a1;
#pragma unroll
        for (int t = 0; t < 16; t++) {
            O[t][0] *= a0; O[t][1] *= a0;
            O[t][2] *= a1; O[t][3] *= a1;
        }

        const float mnl0 = mn0 * LOG2E, mnl1 = mn1 * LOG2E;
        u32 ph[8][2];
#pragma unroll
        for (int t = 0; t < 8; t++) {
            const float p0 = ex2f(fmaf(S[t][0], LOG2E, -mnl0));
            const float p1 = ex2f(fmaf(S[t][1], LOG2E, -mnl0));
            const float p2 = ex2f(fmaf(S[t][2], LOG2E, -mnl1));
            const float p3 = ex2f(fmaf(S[t][3], LOG2E, -mnl1));
            ph[t][0] = cvtf16x2(p0, p1);
            ph[t][1] = cvtf16x2(p2, p3);
        }

#pragma unroll
        for (int ks2 = 0; ks2 < 4; ks2++) {
            const u32 ah[4] = {ph[2*ks2][0], ph[2*ks2][1], ph[2*ks2+1][0], ph[2*ks2+1][1]};
            MMA16816H(La, ah, onesfrag);
#pragma unroll
            for (int nt2 = 0; nt2 < 8; nt2++) {
                u32 vh[4], vl[4];
                const u32 voff = ((ks2 * 16 + (lane & 15)) * ASTR
                                  + nt2 * 16 + (lane >> 4) * 8) * 2;
                LDSM_X4T(vh[0], vh[1], vh[2], vh[3], sVh + voff);
                LDSM_X4T(vl[0], vl[1], vl[2], vl[3], sVl + voff);
                MMA16816H(O[2*nt2],   ah, vh);     MMA16816H(O[2*nt2],   ah, vl);
                MMA16816H(O[2*nt2+1], ah, vh + 2); MMA16816H(O[2*nt2+1], ah, vl + 2);
            }
        }
    }

    const float inv0 = 1.0f / La[0], inv1 = 1.0f / La[2];
    const size_t row0 = (size_t)(b * T_SZ + qt * 64 + wm + er);
#pragma unroll
    for (int t = 0; t < 16; t++) {
        const int col = h * HD + t * 8 + ec;
        *(float2*)&out[row0 * C_DIM + col]       = make_float2(O[t][0] * inv0, O[t][1] * inv0);
        *(float2*)&out[(row0 + 8) * C_DIM + col] = make_float2(O[t][2] * inv1, O[t][3] * inv1);
    }
}

// ---------------- launcher ----------------------------------------------------
extern "C" void kernel_launch(void* const* d_in, const int* in_sizes, int n_in,
                              void* d_out, int out_size)
{
    const float* x    = (const float*)d_in[0];
    const float* Wg   = (const float*)d_in[1];
    const float* Wqkv = (const float*)d_in[2];
    float* out = (float*)d_out;

    cudaFuncSetAttribute(attn_mma_kernel, cudaFuncAttributeMaxDynamicSharedMemorySize, ATTN_SMEM);
    cudaFuncSetAttribute(qproj_mma_kernel, cudaFuncAttributeMaxDynamicSharedMemorySize, QP_SMEM);

    __nv_bfloat16 *wh, *wl;
    cudaGetSymbolAddress((void**)&wh, g_wh);
    cudaGetSymbolAddress((void**)&wl, g_wl);

    zero_kernel<<<512, 256>>>();
    cvt_kernel<<<(C_DIM * C_DIM / 4 + 255) / 256, 256>>>(Wqkv, wh, wl, C_DIM * C_DIM / 4);
    xcvt_gate_kernel<<<BT / GT, 256>>>(x, Wg);
    qproj_mma_kernel<<<dim3(C_DIM / 128, BT / 128), 256, QP_SMEM>>>();
    kvproj_kernel<<<dim3(128, N_HEADS, 2 * KV_SPLITS), 256>>>(x, Wqkv);
    kvcvt_kernel<<<(BT * HD / 4 + 255) / 256, 256>>>();
    attn_mma_kernel<<<dim3(32, N_HEADS, B_SZ), 128, ATTN_SMEM>>>(out);
}

// round 12
// speedup vs baseline: 6.0187x; 1.1021x over previous
#include <cuda_runtime.h>
#include <cuda_bf16.h>
#include <cuda_fp16.h>
#include <math.h>

#define C_DIM   2048
#define N_HEADS 16
#define HD      128
#define B_SZ    2
#define T_SZ    2048
#define BT      (B_SZ * T_SZ)

typedef unsigned long long u64;
typedef unsigned int u32;

#define LOG2E 1.4426950408889634f

// ---------------- packed f32x2 helpers (SASS FFMA2) -------------------------
__device__ __forceinline__ u64 pk2(float lo, float hi) {
    u64 r; asm("mov.b64 %0, {%1, %2};" : "=l"(r) : "f"(lo), "f"(hi)); return r;
}
__device__ __forceinline__ void fma2(u64& d, u64 a, u64 b) {
    asm("fma.rn.f32x2 %0, %1, %2, %0;" : "+l"(d) : "l"(a), "l"(b));
}
__device__ __forceinline__ float2 upk2(u64 v) {
    float2 f; asm("mov.b64 {%0, %1}, %2;" : "=f"(f.x), "=f"(f.y) : "l"(v)); return f;
}

// ---------------- mma.sync / ldmatrix / cp.async helpers --------------------
__device__ __forceinline__ u32 smem_u32(const void* p) {
    u32 a; asm("{ .reg .u64 t; cvta.to.shared.u64 t, %1; cvt.u32.u64 %0, t; }"
               : "=r"(a) : "l"(p));
    return a;
}
#define LDSM_X4(r0, r1, r2, r3, addr) \
    asm volatile("ldmatrix.sync.aligned.m8n8.x4.shared.b16 {%0,%1,%2,%3}, [%4];" \
        : "=r"(r0), "=r"(r1), "=r"(r2), "=r"(r3) : "r"(addr))
#define LDSM_X4T(r0, r1, r2, r3, addr) \
    asm volatile("ldmatrix.sync.aligned.m8n8.x4.trans.shared.b16 {%0,%1,%2,%3}, [%4];" \
        : "=r"(r0), "=r"(r1), "=r"(r2), "=r"(r3) : "r"(addr))
#define LDSM_X2(r0, r1, addr) \
    asm volatile("ldmatrix.sync.aligned.m8n8.x2.shared.b16 {%0,%1}, [%2];" \
        : "=r"(r0), "=r"(r1) : "r"(addr))
#define MMA16816(d, a, b) \
    asm volatile("mma.sync.aligned.m16n8k16.row.col.f32.bf16.bf16.f32 " \
        "{%0,%1,%2,%3}, {%4,%5,%6,%7}, {%8,%9}, {%0,%1,%2,%3};" \
        : "+f"((d)[0]), "+f"((d)[1]), "+f"((d)[2]), "+f"((d)[3]) \
        : "r"((a)[0]), "r"((a)[1]), "r"((a)[2]), "r"((a)[3]), "r"((b)[0]), "r"((b)[1]))
#define MMA16816H(d, a, b) \
    asm volatile("mma.sync.aligned.m16n8k16.row.col.f32.f16.f16.f32 " \
        "{%0,%1,%2,%3}, {%4,%5,%6,%7}, {%8,%9}, {%0,%1,%2,%3};" \
        : "+f"((d)[0]), "+f"((d)[1]), "+f"((d)[2]), "+f"((d)[3]) \
        : "r"((a)[0]), "r"((a)[1]), "r"((a)[2]), "r"((a)[3]), "r"((b)[0]), "r"((b)[1]))
#define CP16(daddr, gsrc) \
    asm volatile("cp.async.cg.shared.global [%0], [%1], 16;" \
        :: "r"(daddr), "l"(gsrc) : "memory")
#define CP_COMMIT() asm volatile("cp.async.commit_group;" ::: "memory")
#define CP_WAIT0()  asm volatile("cp.async.wait_group 0;" ::: "memory")
#define CP_WAIT1()  asm volatile("cp.async.wait_group 1;" ::: "memory")

__device__ __forceinline__ u32 pack_bf2(__nv_bfloat16 a, __nv_bfloat16 b) {
    __nv_bfloat162 t = __halves2bfloat162(a, b);
    return *(u32*)&t;
}
__device__ __forceinline__ u32 pack_h2(__half a, __half b) {
    __half2 t = __halves2half2(a, b);
    return *(u32*)&t;
}
__device__ __forceinline__ float ex2f(float x) {
    float r; asm("ex2.approx.f32 %0, %1;" : "=f"(r) : "f"(x)); return r;
}
__device__ __forceinline__ u32 cvtf16x2(float lo, float hi) {
    u32 r; asm("cvt.rn.f16x2.f32 %0, %1, %2;" : "=r"(r) : "f"(hi), "f"(lo)); return r;
}

// ---------------- scratch ----------------------------------------------------
__device__ __align__(16) float g_ks[BT * HD];
__device__ __align__(16) float g_vs[BT * HD];
__device__ float g_gv [BT];
__device__ int   g_cnt[N_HEADS];
__device__ int   g_list[N_HEADS * BT];
__device__ __align__(16) __nv_bfloat16 g_xh[BT * C_DIM];
__device__ __align__(16) __nv_bfloat16 g_xl[BT * C_DIM];
__device__ __align__(16) __nv_bfloat16 g_wh[C_DIM * C_DIM];
__device__ __align__(16) __nv_bfloat16 g_wl[C_DIM * C_DIM];
__device__ __align__(16) __nv_bfloat16 g_qh[BT * C_DIM];   // scaled Q hi
__device__ __align__(16) __nv_bfloat16 g_ql[BT * C_DIM];   // scaled Q lo
__device__ __align__(16) __nv_bfloat16 g_kh[BT * HD];
__device__ __align__(16) __nv_bfloat16 g_kl[BT * HD];
__device__ __align__(16) __half        g_vh[BT * HD];      // V f16

// ---------------- K0: zero counters + K/V accumulators -----------------------
__global__ __launch_bounds__(256) void zero_kernel() {
    const int i = blockIdx.x * 256 + threadIdx.x;
    const float4 z = make_float4(0.f, 0.f, 0.f, 0.f);
    if (i < BT * HD / 4) { ((float4*)g_ks)[i] = z; ((float4*)g_vs)[i] = z; }
    if (blockIdx.x == 0 && threadIdx.x < N_HEADS) g_cnt[threadIdx.x] = 0;
}

// ---------------- K1: split fp32 -> bf16 hi/lo (Q weights only) ---------------
__global__ __launch_bounds__(256) void cvt_kernel(
    const float* __restrict__ src, __nv_bfloat16* __restrict__ hi,
    __nv_bfloat16* __restrict__ lo, int n4)
{
    const int i = blockIdx.x * 256 + threadIdx.x;
    if (i >= n4) return;
    const float4 v = ((const float4*)src)[i];
    const float f[4] = {v.x, v.y, v.z, v.w};
    __nv_bfloat16 h[4], l[4];
#pragma unroll
    for (int j = 0; j < 4; j++) {
        h[j] = __float2bfloat16(f[j]);
        l[j] = __float2bfloat16(f[j] - __bfloat162float(h[j]));
    }
    u32* H = (u32*)hi; u32* L = (u32*)lo;
    H[2*i]   = pack_bf2(h[0], h[1]);
    H[2*i+1] = pack_bf2(h[2], h[3]);
    L[2*i]   = pack_bf2(l[0], l[1]);
    L[2*i+1] = pack_bf2(l[2], l[3]);
}

// ---------------- K2: fused x hi/lo conversion + gating -----------------------
#define GT   16
#define XSTR 144

__global__ __launch_bounds__(256) void xcvt_gate_kernel(
    const float* __restrict__ x, const float* __restrict__ Wg)
{
    __shared__ float Xs[GT * XSTR];
    __shared__ float Ws[16 * 128];
    const int tid = threadIdx.x;
    const int t0 = blockIdx.x * GT;

    float acc[N_HEADS];
#pragma unroll
    for (int h = 0; h < N_HEADS; h++) acc[h] = 0.0f;

    for (int kc = 0; kc < C_DIM / 128; kc++) {
        __syncthreads();
        for (int u = tid; u < 512; u += 256) {
            const int h = u >> 5, c4 = u & 31;
            *(float4*)&Ws[h * 128 + c4 * 4] =
                *(const float4*)&Wg[(size_t)h * C_DIM + kc * 128 + c4 * 4];
        }
        for (int u = tid; u < GT * 32; u += 256) {
            const int r = u >> 5, c4 = u & 31;
            const size_t g = (size_t)(t0 + r) * C_DIM + kc * 128 + c4 * 4;
            const float4 v = *(const float4*)&x[g];
            *(float4*)&Xs[r * XSTR + c4 * 4] = v;
            const float f[4] = {v.x, v.y, v.z, v.w};
            __nv_bfloat16 h_[4], l_[4];
#pragma unroll
            for (int j = 0; j < 4; j++) {
                h_[j] = __float2bfloat16(f[j]);
                l_[j] = __float2bfloat16(f[j] - __bfloat162float(h_[j]));
            }
            ((u32*)&g_xh[g])[0] = pack_bf2(h_[0], h_[1]);
            ((u32*)&g_xh[g])[1] = pack_bf2(h_[2], h_[3]);
            ((u32*)&g_xl[g])[0] = pack_bf2(l_[0], l_[1]);
            ((u32*)&g_xl[g])[1] = pack_bf2(l_[2], l_[3]);
        }
        __syncthreads();
        const int r = tid >> 4, i = tid & 15;
#pragma unroll
        for (int k = 0; k < 8; k++) {
            const float xv = Xs[r * XSTR + k * 16 + i];
#pragma unroll
            for (int h = 0; h < N_HEADS; h++)
                acc[h] += xv * Ws[h * 128 + k * 16 + i];
        }
    }
#pragma unroll
    for (int off = 1; off < 16; off <<= 1) {
#pragma unroll
        for (int h = 0; h < N_HEADS; h++)
            acc[h] += __shfl_xor_sync(0xffffffffu, acc[h], off);
    }
    if ((tid & 15) == 0) {
        const int t = t0 + (tid >> 4);
        float mx = acc[0]; int bi = 0;
#pragma unroll
        for (int h = 1; h < N_HEADS; h++)
            if (acc[h] > mx) { mx = acc[h]; bi = h; }
        float s = 0.0f;
#pragma unroll
        for (int h = 0; h < N_HEADS; h++) s += expf(acc[h] - mx);
        g_gv[t] = 1.0f / s;
        const int pos = atomicAdd(&g_cnt[bi], 1);
        g_list[bi * BT + pos] = t;
    }
}

// ---------------- K3: Q projection, mma.sync + cp.async double-buffer ---------
#define QSTR 40
#define QP_SZ   (128 * QSTR)
#define QP_SZB  (QP_SZ * 2)
#define QP_STAGEB (4 * QP_SZB)
#define QP_SMEM (2 * QP_STAGEB)

__global__ __launch_bounds__(256, 2) void qproj_mma_kernel()
{
    extern __shared__ __nv_bfloat16 qsm[];
    const u32 sb = smem_u32(qsm);

    const int tid = threadIdx.x, lane = tid & 31, wid = tid >> 5;
    const int wm = (wid >> 2) * 64;
    const int wn = (wid & 3) * 32;
    const int m0 = blockIdx.y * 128, n0 = blockIdx.x * 128;

    float acc[4][4][4];
#pragma unroll
    for (int i = 0; i < 4; i++)
#pragma unroll
        for (int j = 0; j < 4; j++)
#pragma unroll
            for (int r = 0; r < 4; r++) acc[i][j][r] = 0.0f;

    const int q = lane >> 3, r8 = lane & 7;
    const int arow = (q & 1) * 8 + r8, acolq = (q >> 1) * 8;
    const int l2 = lane & 15;
    const int brow = l2 & 7, bcolq = (l2 >> 3) * 8;

    auto issue_stage = [&](int kt, int s) {
#pragma unroll
        for (int v = 0; v < 8; v++) {
            const int u = tid + v * 256;
            const int arr = u >> 9;
            const int rr = (u >> 2) & 127;
            const int cc = (u & 3) * 8;
            const __nv_bfloat16* gp;
            if (arr == 0)      gp = g_xh + (size_t)(m0 + rr) * C_DIM + kt + cc;
            else if (arr == 1) gp = g_xl + (size_t)(m0 + rr) * C_DIM + kt + cc;
            else if (arr == 2) gp = g_wh + (size_t)(n0 + rr) * C_DIM + kt + cc;
            else               gp = g_wl + (size_t)(n0 + rr) * C_DIM + kt + cc;
            const u32 da = sb + s * QP_STAGEB + arr * QP_SZB + (rr * QSTR + cc) * 2;
            CP16(da, gp);
        }
        CP_COMMIT();
    };

    issue_stage(0, 0);

    const int NIT = C_DIM / 32;
    for (int i = 0; i < NIT; i++) {
        const int s = i & 1;
        if (i + 1 < NIT) { issue_stage((i + 1) * 32, s ^ 1); CP_WAIT1(); }
        else             { CP_WAIT0(); }
        __syncthreads();

        const u32 sAh = sb + s * QP_STAGEB;
        const u32 sAl = sAh + QP_SZB;
        const u32 sBh = sAl + QP_SZB;
        const u32 sBl = sBh + QP_SZB;

#pragma unroll
        for (int ks = 0; ks < 2; ks++) {
            const int acol = ks * 16 + acolq;
            const int bcol = ks * 16 + bcolq;
            u32 a_hi[4][4], a_lo[4][4], b_hi[4][2], b_lo[4][2];
#pragma unroll
            for (int mt = 0; mt < 4; mt++) {
                const u32 off = ((wm + mt * 16 + arow) * QSTR + acol) * 2;
                LDSM_X4(a_hi[mt][0], a_hi[mt][1], a_hi[mt][2], a_hi[mt][3], sAh + off);
                LDSM_X4(a_lo[mt][0], a_lo[mt][1], a_lo[mt][2], a_lo[mt][3], sAl + off);
            }
#pragma unroll
            for (int nt = 0; nt < 4; nt++) {
                const u32 off = ((wn + nt * 8 + brow) * QSTR + bcol) * 2;
                LDSM_X2(b_hi[nt][0], b_hi[nt][1], sBh + off);
                LDSM_X2(b_lo[nt][0], b_lo[nt][1], sBl + off);
            }
#pragma unroll
            for (int mt = 0; mt < 4; mt++)
#pragma unroll
                for (int nt = 0; nt < 4; nt++) {
                    MMA16816(acc[mt][nt], a_hi[mt], b_hi[nt]);
                    MMA16816(acc[mt][nt], a_hi[mt], b_lo[nt]);
                    MMA16816(acc[mt][nt], a_lo[mt], b_hi[nt]);
                }
        }
        __syncthreads();
    }

    const float SC = 0.08838834764831845f;  // 1/sqrt(128)
    const int er = lane >> 2, ec = (lane & 3) * 2;
#pragma unroll
    for (int mt = 0; mt < 4; mt++) {
        const size_t row = (size_t)(m0 + wm + mt * 16 + er);
#pragma unroll
        for (int nt = 0; nt < 4; nt++) {
            const int col = n0 + wn + nt * 8 + ec;
#pragma unroll
            for (int half = 0; half < 2; half++) {
                const float v0 = acc[mt][nt][half * 2 + 0] * SC;
                const float v1 = acc[mt][nt][half * 2 + 1] * SC;
                const __nv_bfloat16 h0 = __float2bfloat16(v0);
                const __nv_bfloat16 h1 = __float2bfloat16(v1);
                const __nv_bfloat16 e0 = __float2bfloat16(v0 - __bfloat162float(h0));
                const __nv_bfloat16 e1 = __float2bfloat16(v1 - __bfloat162float(h1));
                const size_t o = (row + half * 8) * C_DIM + col;
                *(u32*)&g_qh[o] = pack_bf2(h0, h1);
                *(u32*)&g_ql[o] = pack_bf2(e0, e1);
            }
        }
    }
}

// ---------------- K4: grouped K/V projection, split-K=4 + atomics -------------
#define KV_SPLITS 4
#define KV_KCH (C_DIM / KV_SPLITS)

__global__ __launch_bounds__(256) void kvproj_kernel(
    const float* __restrict__ x, const float* __restrict__ Wqkv)
{
    const int h = blockIdx.y;
    const int kv = blockIdx.z & 1, sp = blockIdx.z >> 1;
    const int cnt = g_cnt[h];
    const int m0 = blockIdx.x * 32;
    if (m0 >= cnt) return;

    __shared__ float As[16][32];
    __shared__ float Bs[16][128];
    const int tid = threadIdx.x;
    const int blr = tid >> 2, blc = (tid & 3) << 2;
    const int tx = tid & 31, ty = tid >> 5;

    const int* lst = g_list + h * BT;
    int tokA = 0;
    if (tid < 128) tokA = lst[min(m0 + (tid >> 2), cnt - 1)];
    const float* Bp = Wqkv + (size_t)(C_DIM * (1 + kv) + h * HD) * C_DIM;

    u64 acc2[4][2];
#pragma unroll
    for (int i = 0; i < 4; i++) { acc2[i][0] = 0ULL; acc2[i][1] = 0ULL; }

    const int k0 = sp * KV_KCH;
    for (int kt = k0; kt < k0 + KV_KCH; kt += 16) {
        float4 a0 = make_float4(0.f, 0.f, 0.f, 0.f);
        if (tid < 128)
            a0 = *(const float4*)(x + (size_t)tokA * C_DIM + kt + blc);
        const float4 b0 = *(const float4*)(Bp + (size_t)blr        * C_DIM + kt + blc);
        const float4 b1 = *(const float4*)(Bp + (size_t)(blr + 64) * C_DIM + kt + blc);
        __syncthreads();
        if (tid < 128) {
            const int ar = tid >> 2;
            As[blc+0][ar] = a0.x; As[blc+1][ar] = a0.y;
            As[blc+2][ar] = a0.z; As[blc+3][ar] = a0.w;
        }
        Bs[blc+0][blr] = b0.x; Bs[blc+1][blr] = b0.y; Bs[blc+2][blr] = b0.z; Bs[blc+3][blr] = b0.w;
        Bs[blc+0][blr+64] = b1.x; Bs[blc+1][blr+64] = b1.y; Bs[blc+2][blr+64] = b1.z; Bs[blc+3][blr+64] = b1.w;
        __syncthreads();
#pragma unroll
        for (int k = 0; k < 16; k++) {
            const float4 av = *(const float4*)&As[k][ty * 4];
            const float4 bv = *(const float4*)&Bs[k][tx * 4];
            const u64 b20 = pk2(bv.x, bv.y), b21 = pk2(bv.z, bv.w);
            const float aa[4] = {av.x, av.y, av.z, av.w};
#pragma unroll
            for (int i = 0; i < 4; i++) {
                const u64 a2 = pk2(aa[i], aa[i]);
                fma2(acc2[i][0], a2, b20);
                fma2(acc2[i][1], a2, b21);
            }
        }
    }
    float* dst = kv ? g_vs : g_ks;
#pragma unroll
    for (int i = 0; i < 4; i++) {
        const int m = m0 + ty * 4 + i;
        if (m < cnt) {
            const int tok = lst[m];
            const float sc = kv ? g_gv[tok] : 1.0f;
            const float2 c0 = upk2(acc2[i][0]), c1 = upk2(acc2[i][1]);
            float* d = dst + (size_t)tok * HD + tx * 4;
            atomicAdd(d + 0, c0.x * sc);
            atomicAdd(d + 1, c0.y * sc);
            atomicAdd(d + 2, c1.x * sc);
            atomicAdd(d + 3, c1.y * sc);
        }
    }
}

// ---------------- K4b: K fp32 -> bf16 hi/lo ; V fp32 -> f16 -------------------
__global__ __launch_bounds__(256) void kvcvt_kernel() {
    const int i = blockIdx.x * 256 + threadIdx.x;
    if (i >= BT * HD / 4) return;
    {
        const float4 v = ((const float4*)g_ks)[i];
        const float f[4] = {v.x, v.y, v.z, v.w};
        __nv_bfloat16 h[4], l[4];
#pragma unroll
        for (int j = 0; j < 4; j++) {
            h[j] = __float2bfloat16(f[j]);
            l[j] = __float2bfloat16(f[j] - __bfloat162float(h[j]));
        }
        ((u32*)g_kh)[2*i]   = pack_bf2(h[0], h[1]);
        ((u32*)g_kh)[2*i+1] = pack_bf2(h[2], h[3]);
        ((u32*)g_kl)[2*i]   = pack_bf2(l[0], l[1]);
        ((u32*)g_kl)[2*i+1] = pack_bf2(l[2], l[3]);
    }
    {
        const float4 v = ((const float4*)g_vs)[i];
        ((u32*)g_vh)[2*i]   = cvtf16x2(v.x, v.y);
        ((u32*)g_vh)[2*i+1] = cvtf16x2(v.z, v.w);
    }
}

// ---------------- K5: tensor-core causal flash MQA attention ------------------
// BQ=128, 8 warps (16 rows each), BK=64, cp.async double-buffered K/V.
// S: bf16 hi/lo 3-pass. P: f16. V: f16 single. Row sums via ones-MMA.
#define ASTR 136
#define AQ_B   (128 * ASTR * 2)          // one Q array bytes (34816)
#define AST_B  (64 * ASTR * 2)           // one K/V array bytes (17408)
#define ASTG_B (3 * AST_B)               // stage bytes (Kh,Kl,Vh) = 52224
#define ATTN_SMEM (2 * AQ_B + 2 * ASTG_B)  // 174080

__global__ __launch_bounds__(256, 1) void attn_mma_kernel(float* __restrict__ out)
{
    extern __shared__ char sbuf[];
    const u32 sb = smem_u32(sbuf);
    const u32 sQh = sb, sQl = sb + AQ_B;
    const u32 stage0 = sb + 2 * AQ_B;

    const int b  = blockIdx.z, h = blockIdx.y;
    const int qt = gridDim.x - 1 - blockIdx.x;     // longest first
    const int q0 = qt * 128;
    const int tid = threadIdx.x, lane = tid & 31, wid = tid >> 5;
    const int wm = wid * 16;

    // Q tile [128][128] hi/lo
    for (int u = tid; u < 2048; u += 256) {
        const int r = u >> 4, c = (u & 15) * 8;
        const size_t g = (size_t)(b * T_SZ + q0 + r) * C_DIM + h * HD + c;
        *(uint4*)(sbuf + (r * ASTR + c) * 2)        = *(const uint4*)&g_qh[g];
        *(uint4*)(sbuf + AQ_B + (r * ASTR + c) * 2) = *(const uint4*)&g_ql[g];
    }

    const int qq = lane >> 3, r8 = lane & 7;
    const int arow = (qq & 1) * 8 + r8, acolq = (qq >> 1) * 8;
    const int b4row = (lane >> 4) * 8 + (lane & 7);
    const int b4colq = ((lane >> 3) & 1) * 8;
    const int er = lane >> 2, ec = (lane & 3) * 2;

    float m0 = -1e30f, m1 = -1e30f;
    float La[4] = {0.f, 0.f, 0.f, 0.f};
    float O[16][4];
#pragma unroll
    for (int t = 0; t < 16; t++)
#pragma unroll
        for (int r = 0; r < 4; r++) O[t][r] = 0.f;

    const u32 ones2 = 0x3C003C00u;
    const u32 onesfrag[2] = {ones2, ones2};

    const int ktmax = 2 * qt + 1;

    // cp.async stage loader: 3072 16B chunks, 12 per thread
    auto issue_kv = [&](int kt, int s) {
#pragma unroll
        for (int v = 0; v < 12; v++) {
            const int u = tid + v * 256;
            const int arr = u >> 10;              // 0=Kh,1=Kl,2=Vh
            const int idx = u & 1023;
            const int r = idx >> 4, c = (idx & 15) * 8;
            const size_t g = (size_t)(b * T_SZ + kt * 64 + r) * HD + c;
            const void* gp = (arr == 0) ? (const void*)&g_kh[g]
                           : (arr == 1) ? (const void*)&g_kl[g]
                                        : (const void*)&g_vh[g];
            CP16(stage0 + s * ASTG_B + arr * AST_B + (r * ASTR + c) * 2, gp);
        }
        CP_COMMIT();
    };

    issue_kv(0, 0);

    for (int kt = 0; kt <= ktmax; kt++) {
        const int s = kt & 1;
        if (kt < ktmax) { issue_kv(kt + 1, s ^ 1); CP_WAIT1(); }
        else            { CP_WAIT0(); }
        __syncthreads();

        const u32 sKh = stage0 + s * ASTG_B;
        const u32 sKl = sKh + AST_B;
        const u32 sVh = sKl + AST_B;

        // ---- S = Q @ K^T (pre-scaled), bf16 hi/lo 3-pass ----
        float S[8][4];
#pragma unroll
        for (int t = 0; t < 8; t++)
#pragma unroll
            for (int r = 0; r < 4; r++) S[t][r] = 0.f;

#pragma unroll
        for (int ks = 0; ks < 8; ks++) {
            u32 qh[4], ql[4];
            const u32 qoff = ((wm + arow) * ASTR + ks * 16 + acolq) * 2;
            LDSM_X4(qh[0], qh[1], qh[2], qh[3], sQh + qoff);
            LDSM_X4(ql[0], ql[1], ql[2], ql[3], sQl + qoff);
#pragma unroll
            for (int nt2 = 0; nt2 < 4; nt2++) {
                u32 kh[4], kl[4];
                const u32 koff = ((nt2 * 16 + b4row) * ASTR + ks * 16 + b4colq) * 2;
                LDSM_X4(kh[0], kh[1], kh[2], kh[3], sKh + koff);
                LDSM_X4(kl[0], kl[1], kl[2], kl[3], sKl + koff);
                MMA16816(S[2*nt2],   qh, kh);     MMA16816(S[2*nt2],   qh, kl);
                MMA16816(S[2*nt2],   ql, kh);
                MMA16816(S[2*nt2+1], qh, kh + 2); MMA16816(S[2*nt2+1], qh, kl + 2);
                MMA16816(S[2*nt2+1], ql, kh + 2);
            }
        }

        // ---- causal mask (only when tile can cross this warp's diagonal) ----
        if (kt * 64 + 63 > q0 + wm) {
            const int rg0 = q0 + wm + er;
#pragma unroll
            for (int t = 0; t < 8; t++)
#pragma unroll
                for (int j = 0; j < 2; j++) {
                    const int col = kt * 64 + t * 8 + ec + j;
                    if (col > rg0)     S[t][j]     = -1e30f;
                    if (col > rg0 + 8) S[t][2 + j] = -1e30f;
                }
        }

        // ---- online softmax ----
        float mt0 = -1e30f, mt1 = -1e30f;
#pragma unroll
        for (int t = 0; t < 8; t++) {
            mt0 = fmaxf(mt0, fmaxf(S[t][0], S[t][1]));
            mt1 = fmaxf(mt1, fmaxf(S[t][2], S[t][3]));
        }
        mt0 = fmaxf(mt0, __shfl_xor_sync(0xffffffffu, mt0, 1));
        mt0 = fmaxf(mt0, __shfl_xor_sync(0xffffffffu, mt0, 2));
        mt1 = fmaxf(mt1, __shfl_xor_sync(0xffffffffu, mt1, 1));
        mt1 = fmaxf(mt1, __shfl_xor_sync(0xffffffffu, mt1, 2));
        const float mn0 = fmaxf(m0, mt0), mn1 = fmaxf(m1, mt1);
        const float a0 = __expf(m0 - mn0), a1 = __expf(m1 - mn1);
        m0 = mn0; m1 = mn1;
        La[0] *= a0; La[1] *= a0; La[2] *= a1; La[3] *= a1;
#pragma unroll
        for (int t = 0; t < 16; t++) {
            O[t][0] *= a0; O[t][1] *= a0;
            O[t][2] *= a1; O[t][3] *= a1;
        }

        const float mnl0 = mn0 * LOG2E, mnl1 = mn1 * LOG2E;
        u32 ph[8][2];
#pragma unroll
        for (int t = 0; t < 8; t++) {
            const float p0 = ex2f(fmaf(S[t][0], LOG2E, -mnl0));
            const float p1 = ex2f(fmaf(S[t][1], LOG2E, -mnl0));
            const float p2 = ex2f(fmaf(S[t][2], LOG2E, -mnl1));
            const float p3 = ex2f(fmaf(S[t][3], LOG2E, -mnl1));
            ph[t][0] = cvtf16x2(p0, p1);
            ph[t][1] = cvtf16x2(p2, p3);
        }

        // ---- O += P @ V (f16 single pass) + row sums via ones-MMA ----
#pragma unroll
        for (int ks2 = 0; ks2 < 4; ks2++) {
            const u32 ah[4] = {ph[2*ks2][0], ph[2*ks2][1], ph[2*ks2+1][0], ph[2*ks2+1][1]};
            MMA16816H(La, ah, onesfrag);
#pragma unroll
            for (int nt2 = 0; nt2 < 8; nt2++) {
                u32 vh[4];
                const u32 voff = ((ks2 * 16 + (lane & 15)) * ASTR
                                  + nt2 * 16 + (lane >> 4) * 8) * 2;
                LDSM_X4T(vh[0], vh[1], vh[2], vh[3], sVh + voff);
                MMA16816H(O[2*nt2],   ah, vh);
                MMA16816H(O[2*nt2+1], ah, vh + 2);
            }
        }
        __syncthreads();   // all warps done with stage s before it is refilled
    }

    const float inv0 = 1.0f / La[0], inv1 = 1.0f / La[2];
    const size_t row0 = (size_t)(b * T_SZ + q0 + wm + er);
#pragma unroll
    for (int t = 0; t < 16; t++) {
        const int col = h * HD + t * 8 + ec;
        *(float2*)&out[row0 * C_DIM + col]       = make_float2(O[t][0] * inv0, O[t][1] * inv0);
        *(float2*)&out[(row0 + 8) * C_DIM + col] = make_float2(O[t][2] * inv1, O[t][3] * inv1);
    }
}

// ---------------- launcher ----------------------------------------------------
extern "C" void kernel_launch(void* const* d_in, const int* in_sizes, int n_in,
                              void* d_out, int out_size)
{
    const float* x    = (const float*)d_in[0];
    const float* Wg   = (const float*)d_in[1];
    const float* Wqkv = (const float*)d_in[2];
    float* out = (float*)d_out;

    cudaFuncSetAttribute(attn_mma_kernel, cudaFuncAttributeMaxDynamicSharedMemorySize, ATTN_SMEM);
    cudaFuncSetAttribute(qproj_mma_kernel, cudaFuncAttributeMaxDynamicSharedMemorySize, QP_SMEM);

    __nv_bfloat16 *wh, *wl;
    cudaGetSymbolAddress((void**)&wh, g_wh);
    cudaGetSymbolAddress((void**)&wl, g_wl);

    zero_kernel<<<512, 256>>>();
    cvt_kernel<<<(C_DIM * C_DIM / 4 + 255) / 256, 256>>>(Wqkv, wh, wl, C_DIM * C_DIM / 4);
    xcvt_gate_kernel<<<BT / GT, 256>>>(x, Wg);
    qproj_mma_kernel<<<dim3(C_DIM / 128, BT / 128), 256, QP_SMEM>>>();
    kvproj_kernel<<<dim3(128, N_HEADS, 2 * KV_SPLITS), 256>>>(x, Wqkv);
    kvcvt_kernel<<<(BT * HD / 4 + 255) / 256, 256>>>();
    attn_mma_kernel<<<dim3(16, N_HEADS, B_SZ), 256, ATTN_SMEM>>>(out);
}

// round 13
// speedup vs baseline: 6.2564x; 1.0395x over previous
#include <cuda_runtime.h>
#include <cuda_bf16.h>
#include <cuda_fp16.h>
#include <math.h>

#define C_DIM   2048
#define N_HEADS 16
#define HD      128
#define B_SZ    2
#define T_SZ    2048
#define BT      (B_SZ * T_SZ)

typedef unsigned long long u64;
typedef unsigned int u32;

#define LOG2E 1.4426950408889634f

// ---------------- packed f32x2 helpers (SASS FFMA2) -------------------------
__device__ __forceinline__ u64 pk2(float lo, float hi) {
    u64 r; asm("mov.b64 %0, {%1, %2};" : "=l"(r) : "f"(lo), "f"(hi)); return r;
}
__device__ __forceinline__ void fma2(u64& d, u64 a, u64 b) {
    asm("fma.rn.f32x2 %0, %1, %2, %0;" : "+l"(d) : "l"(a), "l"(b));
}
__device__ __forceinline__ float2 upk2(u64 v) {
    float2 f; asm("mov.b64 {%0, %1}, %2;" : "=f"(f.x), "=f"(f.y) : "l"(v)); return f;
}

// ---------------- mma.sync / ldmatrix / cp.async helpers --------------------
__device__ __forceinline__ u32 smem_u32(const void* p) {
    u32 a; asm("{ .reg .u64 t; cvta.to.shared.u64 t, %1; cvt.u32.u64 %0, t; }"
               : "=r"(a) : "l"(p));
    return a;
}
#define LDSM_X4(r0, r1, r2, r3, addr) \
    asm volatile("ldmatrix.sync.aligned.m8n8.x4.shared.b16 {%0,%1,%2,%3}, [%4];" \
        : "=r"(r0), "=r"(r1), "=r"(r2), "=r"(r3) : "r"(addr))
#define LDSM_X4T(r0, r1, r2, r3, addr) \
    asm volatile("ldmatrix.sync.aligned.m8n8.x4.trans.shared.b16 {%0,%1,%2,%3}, [%4];" \
        : "=r"(r0), "=r"(r1), "=r"(r2), "=r"(r3) : "r"(addr))
#define LDSM_X2(r0, r1, addr) \
    asm volatile("ldmatrix.sync.aligned.m8n8.x2.shared.b16 {%0,%1}, [%2];" \
        : "=r"(r0), "=r"(r1) : "r"(addr))
#define MMA16816(d, a, b) \
    asm volatile("mma.sync.aligned.m16n8k16.row.col.f32.bf16.bf16.f32 " \
        "{%0,%1,%2,%3}, {%4,%5,%6,%7}, {%8,%9}, {%0,%1,%2,%3};" \
        : "+f"((d)[0]), "+f"((d)[1]), "+f"((d)[2]), "+f"((d)[3]) \
        : "r"((a)[0]), "r"((a)[1]), "r"((a)[2]), "r"((a)[3]), "r"((b)[0]), "r"((b)[1]))
#define MMA16816H(d, a, b) \
    asm volatile("mma.sync.aligned.m16n8k16.row.col.f32.f16.f16.f32 " \
        "{%0,%1,%2,%3}, {%4,%5,%6,%7}, {%8,%9}, {%0,%1,%2,%3};" \
        : "+f"((d)[0]), "+f"((d)[1]), "+f"((d)[2]), "+f"((d)[3]) \
        : "r"((a)[0]), "r"((a)[1]), "r"((a)[2]), "r"((a)[3]), "r"((b)[0]), "r"((b)[1]))
#define CP16(daddr, gsrc) \
    asm volatile("cp.async.cg.shared.global [%0], [%1], 16;" \
        :: "r"(daddr), "l"(gsrc) : "memory")
#define CP_COMMIT() asm volatile("cp.async.commit_group;" ::: "memory")
#define CP_WAIT0()  asm volatile("cp.async.wait_group 0;" ::: "memory")
#define CP_WAIT1()  asm volatile("cp.async.wait_group 1;" ::: "memory")

__device__ __forceinline__ u32 pack_bf2(__nv_bfloat16 a, __nv_bfloat16 b) {
    __nv_bfloat162 t = __halves2bfloat162(a, b);
    return *(u32*)&t;
}
__device__ __forceinline__ float ex2f(float x) {
    float r; asm("ex2.approx.f32 %0, %1;" : "=f"(r) : "f"(x)); return r;
}
__device__ __forceinline__ u32 cvtf16x2(float lo, float hi) {
    u32 r; asm("cvt.rn.f16x2.f32 %0, %1, %2;" : "=r"(r) : "f"(hi), "f"(lo)); return r;
}

// ---------------- scratch ----------------------------------------------------
__device__ __align__(16) float g_ks[BT * HD];
__device__ __align__(16) float g_vs[BT * HD];
__device__ float g_gv [BT];
__device__ int   g_cnt[N_HEADS];
__device__ int   g_list[N_HEADS * BT];
__device__ __align__(16) __nv_bfloat16 g_xh[BT * C_DIM];
__device__ __align__(16) __nv_bfloat16 g_xl[BT * C_DIM];
__device__ __align__(16) __nv_bfloat16 g_wh[C_DIM * C_DIM];
__device__ __align__(16) __nv_bfloat16 g_wl[C_DIM * C_DIM];
__device__ __align__(16) __nv_bfloat16 g_qh[BT * C_DIM];   // scaled Q hi
__device__ __align__(16) __nv_bfloat16 g_ql[BT * C_DIM];   // scaled Q lo
__device__ __align__(16) __nv_bfloat16 g_kh[BT * HD];
__device__ __align__(16) __nv_bfloat16 g_kl[BT * HD];
__device__ __align__(16) __half        g_vh[BT * HD];      // V f16

// ---------------- K0: zero counters + K/V accumulators -----------------------
__global__ __launch_bounds__(256) void zero_kernel() {
    const int i = blockIdx.x * 256 + threadIdx.x;
    const float4 z = make_float4(0.f, 0.f, 0.f, 0.f);
    if (i < BT * HD / 4) { ((float4*)g_ks)[i] = z; ((float4*)g_vs)[i] = z; }
    if (blockIdx.x == 0 && threadIdx.x < N_HEADS) g_cnt[threadIdx.x] = 0;
}

// ---------------- K1: split fp32 -> bf16 hi/lo (Q weights only) ---------------
__global__ __launch_bounds__(256) void cvt_kernel(
    const float* __restrict__ src, __nv_bfloat16* __restrict__ hi,
    __nv_bfloat16* __restrict__ lo, int n4)
{
    const int i = blockIdx.x * 256 + threadIdx.x;
    if (i >= n4) return;
    const float4 v = ((const float4*)src)[i];
    const float f[4] = {v.x, v.y, v.z, v.w};
    __nv_bfloat16 h[4], l[4];
#pragma unroll
    for (int j = 0; j < 4; j++) {
        h[j] = __float2bfloat16(f[j]);
        l[j] = __float2bfloat16(f[j] - __bfloat162float(h[j]));
    }
    u32* H = (u32*)hi; u32* L = (u32*)lo;
    H[2*i]   = pack_bf2(h[0], h[1]);
    H[2*i+1] = pack_bf2(h[2], h[3]);
    L[2*i]   = pack_bf2(l[0], l[1]);
    L[2*i+1] = pack_bf2(l[2], l[3]);
}

// ---------------- K2: fused x hi/lo conversion + gating -----------------------
#define GT   16
#define XSTR 144

__global__ __launch_bounds__(256) void xcvt_gate_kernel(
    const float* __restrict__ x, const float* __restrict__ Wg)
{
    __shared__ float Xs[GT * XSTR];
    __shared__ float Ws[16 * 128];
    const int tid = threadIdx.x;
    const int t0 = blockIdx.x * GT;

    float acc[N_HEADS];
#pragma unroll
    for (int h = 0; h < N_HEADS; h++) acc[h] = 0.0f;

    for (int kc = 0; kc < C_DIM / 128; kc++) {
        __syncthreads();
        for (int u = tid; u < 512; u += 256) {
            const int h = u >> 5, c4 = u & 31;
            *(float4*)&Ws[h * 128 + c4 * 4] =
                *(const float4*)&Wg[(size_t)h * C_DIM + kc * 128 + c4 * 4];
        }
        for (int u = tid; u < GT * 32; u += 256) {
            const int r = u >> 5, c4 = u & 31;
            const size_t g = (size_t)(t0 + r) * C_DIM + kc * 128 + c4 * 4;
            const float4 v = *(const float4*)&x[g];
            *(float4*)&Xs[r * XSTR + c4 * 4] = v;
            const float f[4] = {v.x, v.y, v.z, v.w};
            __nv_bfloat16 h_[4], l_[4];
#pragma unroll
            for (int j = 0; j < 4; j++) {
                h_[j] = __float2bfloat16(f[j]);
                l_[j] = __float2bfloat16(f[j] - __bfloat162float(h_[j]));
            }
            ((u32*)&g_xh[g])[0] = pack_bf2(h_[0], h_[1]);
            ((u32*)&g_xh[g])[1] = pack_bf2(h_[2], h_[3]);
            ((u32*)&g_xl[g])[0] = pack_bf2(l_[0], l_[1]);
            ((u32*)&g_xl[g])[1] = pack_bf2(l_[2], l_[3]);
        }
        __syncthreads();
        const int r = tid >> 4, i = tid & 15;
#pragma unroll
        for (int k = 0; k < 8; k++) {
            const float xv = Xs[r * XSTR + k * 16 + i];
#pragma unroll
            for (int h = 0; h < N_HEADS; h++)
                acc[h] += xv * Ws[h * 128 + k * 16 + i];
        }
    }
#pragma unroll
    for (int off = 1; off < 16; off <<= 1) {
#pragma unroll
        for (int h = 0; h < N_HEADS; h++)
            acc[h] += __shfl_xor_sync(0xffffffffu, acc[h], off);
    }
    if ((tid & 15) == 0) {
        const int t = t0 + (tid >> 4);
        float mx = acc[0]; int bi = 0;
#pragma unroll
        for (int h = 1; h < N_HEADS; h++)
            if (acc[h] > mx) { mx = acc[h]; bi = h; }
        float s = 0.0f;
#pragma unroll
        for (int h = 0; h < N_HEADS; h++) s += expf(acc[h] - mx);
        g_gv[t] = 1.0f / s;
        const int pos = atomicAdd(&g_cnt[bi], 1);
        g_list[bi * BT + pos] = t;
    }
}

// ---------------- K3: Q projection, mma.sync + cp.async double-buffer ---------
// Pass-major MMA ordering: 16 independent accs between each acc reuse.
#define QSTR 40
#define QP_SZ   (128 * QSTR)
#define QP_SZB  (QP_SZ * 2)
#define QP_STAGEB (4 * QP_SZB)
#define QP_SMEM (2 * QP_STAGEB)

__global__ __launch_bounds__(256, 2) void qproj_mma_kernel()
{
    extern __shared__ __nv_bfloat16 qsm[];
    const u32 sb = smem_u32(qsm);

    const int tid = threadIdx.x, lane = tid & 31, wid = tid >> 5;
    const int wm = (wid >> 2) * 64;
    const int wn = (wid & 3) * 32;
    const int m0 = blockIdx.y * 128, n0 = blockIdx.x * 128;

    float acc[4][4][4];
#pragma unroll
    for (int i = 0; i < 4; i++)
#pragma unroll
        for (int j = 0; j < 4; j++)
#pragma unroll
            for (int r = 0; r < 4; r++) acc[i][j][r] = 0.0f;

    const int q = lane >> 3, r8 = lane & 7;
    const int arow = (q & 1) * 8 + r8, acolq = (q >> 1) * 8;
    const int l2 = lane & 15;
    const int brow = l2 & 7, bcolq = (l2 >> 3) * 8;

    auto issue_stage = [&](int kt, int s) {
#pragma unroll
        for (int v = 0; v < 8; v++) {
            const int u = tid + v * 256;
            const int arr = u >> 9;
            const int rr = (u >> 2) & 127;
            const int cc = (u & 3) * 8;
            const __nv_bfloat16* gp;
            if (arr == 0)      gp = g_xh + (size_t)(m0 + rr) * C_DIM + kt + cc;
            else if (arr == 1) gp = g_xl + (size_t)(m0 + rr) * C_DIM + kt + cc;
            else if (arr == 2) gp = g_wh + (size_t)(n0 + rr) * C_DIM + kt + cc;
            else               gp = g_wl + (size_t)(n0 + rr) * C_DIM + kt + cc;
            const u32 da = sb + s * QP_STAGEB + arr * QP_SZB + (rr * QSTR + cc) * 2;
            CP16(da, gp);
        }
        CP_COMMIT();
    };

    issue_stage(0, 0);

    const int NIT = C_DIM / 32;
    for (int i = 0; i < NIT; i++) {
        const int s = i & 1;
        if (i + 1 < NIT) { issue_stage((i + 1) * 32, s ^ 1); CP_WAIT1(); }
        else             { CP_WAIT0(); }
        __syncthreads();

        const u32 sAh = sb + s * QP_STAGEB;
        const u32 sAl = sAh + QP_SZB;
        const u32 sBh = sAl + QP_SZB;
        const u32 sBl = sBh + QP_SZB;

#pragma unroll
        for (int ks = 0; ks < 2; ks++) {
            const int acol = ks * 16 + acolq;
            const int bcol = ks * 16 + bcolq;
            u32 a_hi[4][4], a_lo[4][4], b_hi[4][2], b_lo[4][2];
#pragma unroll
            for (int mt = 0; mt < 4; mt++) {
                const u32 off = ((wm + mt * 16 + arow) * QSTR + acol) * 2;
                LDSM_X4(a_hi[mt][0], a_hi[mt][1], a_hi[mt][2], a_hi[mt][3], sAh + off);
                LDSM_X4(a_lo[mt][0], a_lo[mt][1], a_lo[mt][2], a_lo[mt][3], sAl + off);
            }
#pragma unroll
            for (int nt = 0; nt < 4; nt++) {
                const u32 off = ((wn + nt * 8 + brow) * QSTR + bcol) * 2;
                LDSM_X2(b_hi[nt][0], b_hi[nt][1], sBh + off);
                LDSM_X2(b_lo[nt][0], b_lo[nt][1], sBl + off);
            }
            // pass-major: no accumulator RAW within a pass
#pragma unroll
            for (int mt = 0; mt < 4; mt++)
#pragma unroll
                for (int nt = 0; nt < 4; nt++)
                    MMA16816(acc[mt][nt], a_hi[mt], b_hi[nt]);
#pragma unroll
            for (int mt = 0; mt < 4; mt++)
#pragma unroll
                for (int nt = 0; nt < 4; nt++)
                    MMA16816(acc[mt][nt], a_hi[mt], b_lo[nt]);
#pragma unroll
            for (int mt = 0; mt < 4; mt++)
#pragma unroll
                for (int nt = 0; nt < 4; nt++)
                    MMA16816(acc[mt][nt], a_lo[mt], b_hi[nt]);
        }
        __syncthreads();
    }

    const float SC = 0.08838834764831845f;  // 1/sqrt(128)
    const int er = lane >> 2, ec = (lane & 3) * 2;
#pragma unroll
    for (int mt = 0; mt < 4; mt++) {
        const size_t row = (size_t)(m0 + wm + mt * 16 + er);
#pragma unroll
        for (int nt = 0; nt < 4; nt++) {
            const int col = n0 + wn + nt * 8 + ec;
#pragma unroll
            for (int half = 0; half < 2; half++) {
                const float v0 = acc[mt][nt][half * 2 + 0] * SC;
                const float v1 = acc[mt][nt][half * 2 + 1] * SC;
                const __nv_bfloat16 h0 = __float2bfloat16(v0);
                const __nv_bfloat16 h1 = __float2bfloat16(v1);
                const __nv_bfloat16 e0 = __float2bfloat16(v0 - __bfloat162float(h0));
                const __nv_bfloat16 e1 = __float2bfloat16(v1 - __bfloat162float(h1));
                const size_t o = (row + half * 8) * C_DIM + col;
                *(u32*)&g_qh[o] = pack_bf2(h0, h1);
                *(u32*)&g_ql[o] = pack_bf2(e0, e1);
            }
        }
    }
}

// ---------------- K4: grouped K/V projection, split-K=4 + atomics -------------
#define KV_SPLITS 4
#define KV_KCH (C_DIM / KV_SPLITS)

__global__ __launch_bounds__(256) void kvproj_kernel(
    const float* __restrict__ x, const float* __restrict__ Wqkv)
{
    const int h = blockIdx.y;
    const int kv = blockIdx.z & 1, sp = blockIdx.z >> 1;
    const int cnt = g_cnt[h];
    const int m0 = blockIdx.x * 32;
    if (m0 >= cnt) return;

    __shared__ float As[16][32];
    __shared__ float Bs[16][128];
    const int tid = threadIdx.x;
    const int blr = tid >> 2, blc = (tid & 3) << 2;
    const int tx = tid & 31, ty = tid >> 5;

    const int* lst = g_list + h * BT;
    int tokA = 0;
    if (tid < 128) tokA = lst[min(m0 + (tid >> 2), cnt - 1)];
    const float* Bp = Wqkv + (size_t)(C_DIM * (1 + kv) + h * HD) * C_DIM;

    u64 acc2[4][2];
#pragma unroll
    for (int i = 0; i < 4; i++) { acc2[i][0] = 0ULL; acc2[i][1] = 0ULL; }

    const int k0 = sp * KV_KCH;
    for (int kt = k0; kt < k0 + KV_KCH; kt += 16) {
        float4 a0 = make_float4(0.f, 0.f, 0.f, 0.f);
        if (tid < 128)
            a0 = *(const float4*)(x + (size_t)tokA * C_DIM + kt + blc);
        const float4 b0 = *(const float4*)(Bp + (size_t)blr        * C_DIM + kt + blc);
        const float4 b1 = *(const float4*)(Bp + (size_t)(blr + 64) * C_DIM + kt + blc);
        __syncthreads();
        if (tid < 128) {
            const int ar = tid >> 2;
            As[blc+0][ar] = a0.x; As[blc+1][ar] = a0.y;
            As[blc+2][ar] = a0.z; As[blc+3][ar] = a0.w;
        }
        Bs[blc+0][blr] = b0.x; Bs[blc+1][blr] = b0.y; Bs[blc+2][blr] = b0.z; Bs[blc+3][blr] = b0.w;
        Bs[blc+0][blr+64] = b1.x; Bs[blc+1][blr+64] = b1.y; Bs[blc+2][blr+64] = b1.z; Bs[blc+3][blr+64] = b1.w;
        __syncthreads();
#pragma unroll
        for (int k = 0; k < 16; k++) {
            const float4 av = *(const float4*)&As[k][ty * 4];
            const float4 bv = *(const float4*)&Bs[k][tx * 4];
            const u64 b20 = pk2(bv.x, bv.y), b21 = pk2(bv.z, bv.w);
            const float aa[4] = {av.x, av.y, av.z, av.w};
#pragma unroll
            for (int i = 0; i < 4; i++) {
                const u64 a2 = pk2(aa[i], aa[i]);
                fma2(acc2[i][0], a2, b20);
                fma2(acc2[i][1], a2, b21);
            }
        }
    }
    float* dst = kv ? g_vs : g_ks;
#pragma unroll
    for (int i = 0; i < 4; i++) {
        const int m = m0 + ty * 4 + i;
        if (m < cnt) {
            const int tok = lst[m];
            const float sc = kv ? g_gv[tok] : 1.0f;
            const float2 c0 = upk2(acc2[i][0]), c1 = upk2(acc2[i][1]);
            float* d = dst + (size_t)tok * HD + tx * 4;
            atomicAdd(d + 0, c0.x * sc);
            atomicAdd(d + 1, c0.y * sc);
            atomicAdd(d + 2, c1.x * sc);
            atomicAdd(d + 3, c1.y * sc);
        }
    }
}

// ---------------- K4b: K fp32 -> bf16 hi/lo ; V fp32 -> f16 -------------------
__global__ __launch_bounds__(256) void kvcvt_kernel() {
    const int i = blockIdx.x * 256 + threadIdx.x;
    if (i >= BT * HD / 4) return;
    {
        const float4 v = ((const float4*)g_ks)[i];
        const float f[4] = {v.x, v.y, v.z, v.w};
        __nv_bfloat16 h[4], l[4];
#pragma unroll
        for (int j = 0; j < 4; j++) {
            h[j] = __float2bfloat16(f[j]);
            l[j] = __float2bfloat16(f[j] - __bfloat162float(h[j]));
        }
        ((u32*)g_kh)[2*i]   = pack_bf2(h[0], h[1]);
        ((u32*)g_kh)[2*i+1] = pack_bf2(h[2], h[3]);
        ((u32*)g_kl)[2*i]   = pack_bf2(l[0], l[1]);
        ((u32*)g_kl)[2*i+1] = pack_bf2(l[2], l[3]);
    }
    {
        const float4 v = ((const float4*)g_vs)[i];
        ((u32*)g_vh)[2*i]   = cvtf16x2(v.x, v.y);
        ((u32*)g_vh)[2*i+1] = cvtf16x2(v.z, v.w);
    }
}

// ---------------- K5: tensor-core causal flash MQA attention ------------------
#define ASTR 136
#define AQ_B   (128 * ASTR * 2)
#define AST_B  (64 * ASTR * 2)
#define ASTG_B (3 * AST_B)
#define ATTN_SMEM (2 * AQ_B + 2 * ASTG_B)

__global__ __launch_bounds__(256, 1) void attn_mma_kernel(float* __restrict__ out)
{
    extern __shared__ char sbuf[];
    const u32 sb = smem_u32(sbuf);
    const u32 sQh = sb, sQl = sb + AQ_B;
    const u32 stage0 = sb + 2 * AQ_B;

    const int b  = blockIdx.z, h = blockIdx.y;
    const int qt = gridDim.x - 1 - blockIdx.x;
    const int q0 = qt * 128;
    const int tid = threadIdx.x, lane = tid & 31, wid = tid >> 5;
    const int wm = wid * 16;

    for (int u = tid; u < 2048; u += 256) {
        const int r = u >> 4, c = (u & 15) * 8;
        const size_t g = (size_t)(b * T_SZ + q0 + r) * C_DIM + h * HD + c;
        *(uint4*)(sbuf + (r * ASTR + c) * 2)        = *(const uint4*)&g_qh[g];
        *(uint4*)(sbuf + AQ_B + (r * ASTR + c) * 2) = *(const uint4*)&g_ql[g];
    }

    const int qq = lane >> 3, r8 = lane & 7;
    const int arow = (qq & 1) * 8 + r8, acolq = (qq >> 1) * 8;
    const int b4row = (lane >> 4) * 8 + (lane & 7);
    const int b4colq = ((lane >> 3) & 1) * 8;
    const int er = lane >> 2, ec = (lane & 3) * 2;

    float m0 = -1e30f, m1 = -1e30f;
    float La[4] = {0.f, 0.f, 0.f, 0.f};
    float O[16][4];
#pragma unroll
    for (int t = 0; t < 16; t++)
#pragma unroll
        for (int r = 0; r < 4; r++) O[t][r] = 0.f;

    const u32 ones2 = 0x3C003C00u;
    const u32 onesfrag[2] = {ones2, ones2};

    const int ktmax = 2 * qt + 1;

    auto issue_kv = [&](int kt, int s) {
#pragma unroll
        for (int v = 0; v < 12; v++) {
            const int u = tid + v * 256;
            const int arr = u >> 10;
            const int idx = u & 1023;
            const int r = idx >> 4, c = (idx & 15) * 8;
            const size_t g = (size_t)(b * T_SZ + kt * 64 + r) * HD + c;
            const void* gp = (arr == 0) ? (const void*)&g_kh[g]
                           : (arr == 1) ? (const void*)&g_kl[g]
                                        : (const void*)&g_vh[g];
            CP16(stage0 + s * ASTG_B + arr * AST_B + (r * ASTR + c) * 2, gp);
        }
        CP_COMMIT();
    };

    issue_kv(0, 0);

    for (int kt = 0; kt <= ktmax; kt++) {
        const int s = kt & 1;
        if (kt < ktmax) { issue_kv(kt + 1, s ^ 1); CP_WAIT1(); }
        else            { CP_WAIT0(); }
        __syncthreads();

        const u32 sKh = stage0 + s * ASTG_B;
        const u32 sKl = sKh + AST_B;
        const u32 sVh = sKl + AST_B;

        float S[8][4];
#pragma unroll
        for (int t = 0; t < 8; t++)
#pragma unroll
            for (int r = 0; r < 4; r++) S[t][r] = 0.f;

#pragma unroll
        for (int ks = 0; ks < 8; ks++) {
            u32 qh[4], ql[4];
            const u32 qoff = ((wm + arow) * ASTR + ks * 16 + acolq) * 2;
            LDSM_X4(qh[0], qh[1], qh[2], qh[3], sQh + qoff);
            LDSM_X4(ql[0], ql[1], ql[2], ql[3], sQl + qoff);
#pragma unroll
            for (int nt2 = 0; nt2 < 4; nt2++) {
                u32 kh[4], kl[4];
                const u32 koff = ((nt2 * 16 + b4row) * ASTR + ks * 16 + b4colq) * 2;
                LDSM_X4(kh[0], kh[1], kh[2], kh[3], sKh + koff);
                LDSM_X4(kl[0], kl[1], kl[2], kl[3], sKl + koff);
                MMA16816(S[2*nt2],   qh, kh);     MMA16816(S[2*nt2+1], qh, kh + 2);
                MMA16816(S[2*nt2],   qh, kl);     MMA16816(S[2*nt2+1], qh, kl + 2);
                MMA16816(S[2*nt2],   ql, kh);     MMA16816(S[2*nt2+1], ql, kh + 2);
            }
        }

        if (kt * 64 + 63 > q0 + wm) {
            const int rg0 = q0 + wm + er;
#pragma unroll
            for (int t = 0; t < 8; t++)
#pragma unroll
                for (int j = 0; j < 2; j++) {
                    const int col = kt * 64 + t * 8 + ec + j;
                    if (col > rg0)     S[t][j]     = -1e30f;
                    if (col > rg0 + 8) S[t][2 + j] = -1e30f;
                }
        }

        float mt0 = -1e30f, mt1 = -1e30f;
#pragma unroll
        for (int t = 0; t < 8; t++) {
            mt0 = fmaxf(mt0, fmaxf(S[t][0], S[t][1]));
            mt1 = fmaxf(mt1, fmaxf(S[t][2], S[t][3]));
        }
        mt0 = fmaxf(mt0, __shfl_xor_sync(0xffffffffu, mt0, 1));
        mt0 = fmaxf(mt0, __shfl_xor_sync(0xffffffffu, mt0, 2));
        mt1 = fmaxf(mt1, __shfl_xor_sync(0xffffffffu, mt1, 1));
        mt1 = fmaxf(mt1, __shfl_xor_sync(0xffffffffu, mt1, 2));
        const float mn0 = fmaxf(m0, mt0), mn1 = fmaxf(m1, mt1);
        const float a0 = __expf(m0 - mn0), a1 = __expf(m1 - mn1);
        m0 = mn0; m1 = mn1;
        La[0] *= a0; La[1] *= a0; La[2] *= a1; La[3] *= a1;
#pragma unroll
        for (int t = 0; t < 16; t++) {
            O[t][0] *= a0; O[t][1] *= a0;
            O[t][2] *= a1; O[t][3] *= a1;
        }

        const float mnl0 = mn0 * LOG2E, mnl1 = mn1 * LOG2E;
        u32 ph[8][2];
#pragma unroll
        for (int t = 0; t < 8; t++) {
            const float p0 = ex2f(fmaf(S[t][0], LOG2E, -mnl0));
            const float p1 = ex2f(fmaf(S[t][1], LOG2E, -mnl0));
            const float p2 = ex2f(fmaf(S[t][2], LOG2E, -mnl1));
            const float p3 = ex2f(fmaf(S[t][3], LOG2E, -mnl1));
            ph[t][0] = cvtf16x2(p0, p1);
            ph[t][1] = cvtf16x2(p2, p3);
        }

#pragma unroll
        for (int ks2 = 0; ks2 < 4; ks2++) {
            const u32 ah[4] = {ph[2*ks2][0], ph[2*ks2][1], ph[2*ks2+1][0], ph[2*ks2+1][1]};
            MMA16816H(La, ah, onesfrag);
#pragma unroll
            for (int nt2 = 0; nt2 < 8; nt2++) {
                u32 vh[4];
                const u32 voff = ((ks2 * 16 + (lane & 15)) * ASTR
                                  + nt2 * 16 + (lane >> 4) * 8) * 2;
                LDSM_X4T(vh[0], vh[1], vh[2], vh[3], sVh + voff);
                MMA16816H(O[2*nt2],   ah, vh);
                MMA16816H(O[2*nt2+1], ah, vh + 2);
            }
        }
        __syncthreads();
    }

    const float inv0 = 1.0f / La[0], inv1 = 1.0f / La[2];
    const size_t row0 = (size_t)(b * T_SZ + q0 + wm + er);
#pragma unroll
    for (int t = 0; t < 16; t++) {
        const int col = h * HD + t * 8 + ec;
        *(float2*)&out[row0 * C_DIM + col]       = make_float2(O[t][0] * inv0, O[t][1] * inv0);
        *(float2*)&out[(row0 + 8) * C_DIM + col] = make_float2(O[t][2] * inv1, O[t][3] * inv1);
    }
}

// ---------------- launcher: two-stream overlap (qproj || kvproj) --------------
extern "C" void kernel_launch(void* const* d_in, const int* in_sizes, int n_in,
                              void* d_out, int out_size)
{
    const float* x    = (const float*)d_in[0];
    const float* Wg   = (const float*)d_in[1];
    const float* Wqkv = (const float*)d_in[2];
    float* out = (float*)d_out;

    // Host-side handles, created once on the first (uncaptured) call.
    // Subsequent (captured) calls execute only capturable ops on them.
    static cudaStream_t s2 = nullptr;
    static cudaEvent_t evF = nullptr, evX = nullptr, evQ = nullptr;
    if (s2 == nullptr) {
        cudaStreamCreateWithFlags(&s2, cudaStreamNonBlocking);
        cudaEventCreateWithFlags(&evF, cudaEventDisableTiming);
        cudaEventCreateWithFlags(&evX, cudaEventDisableTiming);
        cudaEventCreateWithFlags(&evQ, cudaEventDisableTiming);
    }

    cudaFuncSetAttribute(attn_mma_kernel, cudaFuncAttributeMaxDynamicSharedMemorySize, ATTN_SMEM);
    cudaFuncSetAttribute(qproj_mma_kernel, cudaFuncAttributeMaxDynamicSharedMemorySize, QP_SMEM);

    __nv_bfloat16 *wh, *wl;
    cudaGetSymbolAddress((void**)&wh, g_wh);
    cudaGetSymbolAddress((void**)&wl, g_wl);

    // fork s2 from the main stream
    cudaEventRecord(evF, 0);
    cudaStreamWaitEvent(s2, evF, 0);

    // s2: weight hi/lo conversion (independent of x-side work)
    cvt_kernel<<<(C_DIM * C_DIM / 4 + 255) / 256, 256, 0, s2>>>(Wqkv, wh, wl, C_DIM * C_DIM / 4);

    // main: zero + fused x-convert/gating
    zero_kernel<<<512, 256>>>();
    xcvt_gate_kernel<<<BT / GT, 256>>>(x, Wg);
    cudaEventRecord(evX, 0);

    // s2: qproj (needs cvt(W) [s2-ordered] + xcvt_gate [evX])
    cudaStreamWaitEvent(s2, evX, 0);
    qproj_mma_kernel<<<dim3(C_DIM / 128, BT / 128), 256, QP_SMEM, s2>>>();
    cudaEventRecord(evQ, s2);

    // main: kvproj + kvcvt, concurrent with qproj
    kvproj_kernel<<<dim3(128, N_HEADS, 2 * KV_SPLITS), 256>>>(x, Wqkv);
    kvcvt_kernel<<<(BT * HD / 4 + 255) / 256, 256>>>();

    // join and run attention
    cudaStreamWaitEvent(0, evQ, 0);
    attn_mma_kernel<<<dim3(16, N_HEADS, B_SZ), 256, ATTN_SMEM>>>(out);
}